// round 1
// baseline (speedup 1.0000x reference)
#include <cuda_runtime.h>
#include <math.h>

// Problem constants (fixed shapes for this problem)
#define NN 50000
#define EE 800000
#define F_IN 58
#define H1 300
#define H2 100

// ---------------------------------------------------------------------------
// Scratch: single device-global struct (no runtime allocation allowed).
// All member offsets are multiples of 16 bytes (rowptr padded to NN+4).
// ---------------------------------------------------------------------------
struct alignas(16) Scratch {
    int   deg[NN];          // out-degree histogram over src
    int   cnt[NN];          // in-degree histogram over dst (for CSR)
    int   rowptr[NN + 4];   // CSR row pointers (padded for 16B alignment)
    int   cursor[NN];       // CSR fill cursors
    int   eidx[EE];         // CSR edge id list
    float dis[NN];          // deg^-1/2
    float norm[EE];         // -(dis[src]*dis[dst])
    float tx1[NN * F_IN];   // stage-1 aggregation output [N,58]
    float h[NN * H1];       // relu(cheb1) [N,300]
    float hW21[NN * H2];    // h @ W2_1 [N,100]
    float agg2[NN * H2];    // Agg(hW21) [N,100]
    float x1[NN * H2];      // relu(cheb2) [N,100]
    float xm[NN * H2];
    float z[NN * H2];
    float s0[NN];           // xm @ W3_0
    float s1[NN];           // xm @ W3_1
    float agg3[NN];         // Agg(s1)
    float accum[2];         // pos/neg log-sum accumulators
};
__device__ Scratch g_s;

// ---------------------------------------------------------------------------
// Small utility kernels
// ---------------------------------------------------------------------------
__global__ void zero_kernel(int* deg, int* cnt, float* accum, int n) {
    int i = blockIdx.x * blockDim.x + threadIdx.x;
    if (i < n) { deg[i] = 0; cnt[i] = 0; }
    if (i < 2) accum[i] = 0.f;
}

__global__ void hist_kernel(const int* __restrict__ src, const int* __restrict__ dst,
                            int* deg, int* cnt, int e) {
    int i = blockIdx.x * blockDim.x + threadIdx.x;
    if (i < e) {
        atomicAdd(&deg[src[i]], 1);
        atomicAdd(&cnt[dst[i]], 1);
    }
}

__global__ void dis_kernel(const int* __restrict__ deg, float* __restrict__ dis, int n) {
    int i = blockIdx.x * blockDim.x + threadIdx.x;
    if (i < n) {
        int d = deg[i];
        dis[i] = (d > 0) ? (1.0f / sqrtf((float)d)) : 0.0f;
    }
}

__global__ void norm_kernel(const int* __restrict__ src, const int* __restrict__ dst,
                            const float* __restrict__ dis, float* __restrict__ norm, int e) {
    int i = blockIdx.x * blockDim.x + threadIdx.x;
    if (i < e) norm[i] = -(dis[src[i]] * dis[dst[i]]);
}

// Single-block exclusive scan of cnt[0..n) -> rowptr (also copies into cursor).
__global__ void scan_kernel(const int* __restrict__ cnt, int* __restrict__ rowptr,
                            int* __restrict__ cursor, int n) {
    __shared__ int warp_sums[32];
    __shared__ int s_base;
    int tid = threadIdx.x;  // 1024 threads
    if (tid == 0) s_base = 0;
    __syncthreads();
    for (int t0 = 0; t0 < n; t0 += 1024) {
        int i = t0 + tid;
        int v = (i < n) ? cnt[i] : 0;
        int x = v;
        #pragma unroll
        for (int d = 1; d < 32; d <<= 1) {
            int y = __shfl_up_sync(0xFFFFFFFFu, x, d);
            if ((tid & 31) >= d) x += y;
        }
        if ((tid & 31) == 31) warp_sums[tid >> 5] = x;
        __syncthreads();
        if (tid < 32) {
            int y = warp_sums[tid];
            int zz = y;
            #pragma unroll
            for (int d = 1; d < 32; d <<= 1) {
                int w = __shfl_up_sync(0xFFFFFFFFu, zz, d);
                if (tid >= d) zz += w;
            }
            warp_sums[tid] = zz - y;  // exclusive warp offset
        }
        __syncthreads();
        int incl = x + warp_sums[tid >> 5];
        int excl = s_base + incl - v;
        if (i < n) { rowptr[i] = excl; cursor[i] = excl; }
        __syncthreads();
        if (tid == 1023) s_base += incl;  // tile total (padded lanes contribute 0)
        __syncthreads();
    }
    if (tid == 0) rowptr[n] = s_base;
}

__global__ void fill_kernel(const int* __restrict__ dst, int* __restrict__ cursor,
                            int* __restrict__ eidx, int e) {
    int i = blockIdx.x * blockDim.x + threadIdx.x;
    if (i < e) {
        int p = atomicAdd(&cursor[dst[i]], 1);
        eidx[p] = i;
    }
}

// ---------------------------------------------------------------------------
// CSR aggregation: out[i,:] = sum_{e in edges(dst==i)} val[src[e],:] * norm[e]
// Warp per node; F features strided by lane.
// ---------------------------------------------------------------------------
template <int F>
__global__ void agg_kernel(const float* __restrict__ val, const int* __restrict__ eidx,
                           const int* __restrict__ rowptr, const int* __restrict__ src,
                           const float* __restrict__ norm, float* __restrict__ out, int n) {
    int warp = (blockIdx.x * blockDim.x + threadIdx.x) >> 5;
    int lane = threadIdx.x & 31;
    if (warp >= n) return;
    int beg = rowptr[warp], end = rowptr[warp + 1];
    constexpr int R = (F + 31) / 32;
    float acc[R];
    #pragma unroll
    for (int r = 0; r < R; r++) acc[r] = 0.f;
    for (int j = beg; j < end; j++) {
        int e = eidx[j];
        int s = src[e];
        float w = norm[e];
        const float* vrow = val + (long)s * F;
        #pragma unroll
        for (int r = 0; r < R; r++) {
            int f = lane + r * 32;
            if (f < F) acc[r] += vrow[f] * w;
        }
    }
    float* orow = out + (long)warp * F;
    #pragma unroll
    for (int r = 0; r < R; r++) {
        int f = lane + r * 32;
        if (f < F) orow[f] = acc[r];
    }
}

__global__ void agg1_kernel(const float* __restrict__ val, const int* __restrict__ eidx,
                            const int* __restrict__ rowptr, const int* __restrict__ src,
                            const float* __restrict__ norm, float* __restrict__ out, int n) {
    int i = blockIdx.x * blockDim.x + threadIdx.x;
    if (i >= n) return;
    float a = 0.f;
    int end = rowptr[i + 1];
    for (int j = rowptr[i]; j < end; j++) {
        int e = eidx[j];
        a += val[src[e]] * norm[e];
    }
    out[i] = a;
}

// ---------------------------------------------------------------------------
// Register-blocked fp32 GEMM: C = epilogue(A1@B1 [+ A2@B2])
// MODE 0: C = acc
// MODE 1: C = relu(acc + bias)
// MODE 2: C = relu(acc + add + bias)
// MODE 3: C = add + relu(acc + bias)
// TRANSB: B is stored [M,K] (read B[n,k]) instead of [K,M].
// ---------------------------------------------------------------------------
template <int MODE, bool DUAL, bool TRANSB>
__global__ __launch_bounds__(256)
void gemm_kernel(const float* __restrict__ A1, const float* __restrict__ B1,
                 const float* __restrict__ A2, const float* __restrict__ B2,
                 const float* __restrict__ addm, const float* __restrict__ bias,
                 float* __restrict__ C, int Nr, int K, int M) {
    constexpr int BM = 64, BN = 64, BK = 16;
    __shared__ float As[BK][BM + 1];
    __shared__ float Bs[BK][BN];
    int bm = blockIdx.y * BM, bn = blockIdx.x * BN;
    int tid = threadIdx.x;
    int tr = tid / 16, tc = tid % 16;
    float acc[4][4];
    #pragma unroll
    for (int i = 0; i < 4; i++)
        #pragma unroll
        for (int j = 0; j < 4; j++) acc[i][j] = 0.f;

    int npass = DUAL ? 2 : 1;
    for (int pass = 0; pass < npass; pass++) {
        const float* A = pass ? A2 : A1;
        const float* B = pass ? B2 : B1;
        for (int k0 = 0; k0 < K; k0 += BK) {
            #pragma unroll
            for (int i = 0; i < 4; i++) {
                int idx = tid + i * 256;
                int m = idx / BK, k = idx % BK;
                int gr = bm + m, gk = k0 + k;
                As[k][m] = (gr < Nr && gk < K) ? A[(long)gr * K + gk] : 0.f;
            }
            #pragma unroll
            for (int i = 0; i < 4; i++) {
                int idx = tid + i * 256;
                int k = idx / BN, nn = idx % BN;
                int gk = k0 + k, gn = bn + nn;
                float v = 0.f;
                if (gk < K && gn < M)
                    v = TRANSB ? B[(long)gn * K + gk] : B[(long)gk * M + gn];
                Bs[k][nn] = v;
            }
            __syncthreads();
            #pragma unroll
            for (int k = 0; k < BK; k++) {
                float a[4], b[4];
                #pragma unroll
                for (int i = 0; i < 4; i++) a[i] = As[k][tr * 4 + i];
                #pragma unroll
                for (int j = 0; j < 4; j++) b[j] = Bs[k][tc * 4 + j];
                #pragma unroll
                for (int i = 0; i < 4; i++)
                    #pragma unroll
                    for (int j = 0; j < 4; j++) acc[i][j] += a[i] * b[j];
            }
            __syncthreads();
        }
    }

    #pragma unroll
    for (int i = 0; i < 4; i++) {
        int r = bm + tr * 4 + i;
        if (r >= Nr) continue;
        #pragma unroll
        for (int j = 0; j < 4; j++) {
            int c = bn + tc * 4 + j;
            if (c >= M) continue;
            float v = acc[i][j];
            if (MODE >= 1) v += bias[c];
            if (MODE == 2) v += addm[(long)r * M + c];
            if (MODE >= 1) v = fmaxf(v, 0.f);
            if (MODE == 3) v += addm[(long)r * M + c];
            C[(long)r * M + c] = v;
        }
    }
}

// ---------------------------------------------------------------------------
// Stage-3 dual GEMV: s0 = xm@W3_0, s1 = xm@W3_1  (K=100)
// ---------------------------------------------------------------------------
__global__ void gemv3_kernel(const float* __restrict__ xm, const float* __restrict__ w0,
                             const float* __restrict__ w1, float* __restrict__ s0,
                             float* __restrict__ s1, int n) {
    int warp = (blockIdx.x * blockDim.x + threadIdx.x) >> 5;
    int lane = threadIdx.x & 31;
    if (warp >= n) return;
    float a0 = 0.f, a1 = 0.f;
    const float* row = xm + (long)warp * H2;
    for (int f = lane; f < H2; f += 32) {
        float v = row[f];
        a0 += v * w0[f];
        a1 += v * w1[f];
    }
    #pragma unroll
    for (int d = 16; d; d >>= 1) {
        a0 += __shfl_down_sync(0xFFFFFFFFu, a0, d);
        a1 += __shfl_down_sync(0xFFFFFFFFu, a1, d);
    }
    if (lane == 0) { s0[warp] = a0; s1[warp] = a1; }
}

// ---------------------------------------------------------------------------
// Edge score loss: warp per edge, float4 dot over z[,:100], hierarchical reduce.
// which==0: sum log(sigmoid(s)+1e-15); which==1: sum log(1-sigmoid(s)+1e-15)
// ---------------------------------------------------------------------------
__global__ void score_kernel(const float* __restrict__ z, const int* __restrict__ ei,
                             int E_, float* __restrict__ accum, int which) {
    const int* s = ei;
    const int* d = ei + E_;
    int lane = threadIdx.x & 31;
    int warp_global = (blockIdx.x * blockDim.x + threadIdx.x) >> 5;
    int nwarps = (gridDim.x * blockDim.x) >> 5;
    float lsum = 0.f;
    for (int e = warp_global; e < E_; e += nwarps) {
        int a = s[e], b = d[e];
        const float4* za = (const float4*)(z + (long)a * H2);
        const float4* zb = (const float4*)(z + (long)b * H2);
        float dot = 0.f;
        if (lane < 25) {
            float4 u = za[lane];
            float4 v = zb[lane];
            dot = u.x * v.x + u.y * v.y + u.z * v.z + u.w * v.w;
        }
        #pragma unroll
        for (int dd = 16; dd; dd >>= 1) dot += __shfl_down_sync(0xFFFFFFFFu, dot, dd);
        if (lane == 0) {
            float sig = 1.f / (1.f + expf(-dot));
            float t = which ? logf(1.f - sig + 1e-15f) : logf(sig + 1e-15f);
            lsum += t;
        }
    }
    __shared__ float red[32];
    float w = lsum;
    #pragma unroll
    for (int dd = 16; dd; dd >>= 1) w += __shfl_down_sync(0xFFFFFFFFu, w, dd);
    if (lane == 0) red[threadIdx.x >> 5] = w;
    __syncthreads();
    if (threadIdx.x < 32) {
        float v2 = (threadIdx.x < (blockDim.x >> 5)) ? red[threadIdx.x] : 0.f;
        #pragma unroll
        for (int dd = 16; dd; dd >>= 1) v2 += __shfl_down_sync(0xFFFFFFFFu, v2, dd);
        if (threadIdx.x == 0) atomicAdd(&accum[which], v2);
    }
}

// ---------------------------------------------------------------------------
// Final output: out[i] = s0[i] + agg3[i] + b3; out[n]=r_loss; out[n+1]=c1; out[n+2]=c2
// ---------------------------------------------------------------------------
__global__ void final_kernel(const float* __restrict__ s0, const float* __restrict__ agg3,
                             const float* __restrict__ b3, const float* __restrict__ accum,
                             const float* __restrict__ c1, const float* __restrict__ c2,
                             float* __restrict__ out, int n, float invE) {
    int i = blockIdx.x * blockDim.x + threadIdx.x;
    if (i < n) out[i] = s0[i] + agg3[i] + b3[0];
    if (i == 0) {
        out[n] = -(accum[0] + accum[1]) * invE;
        out[n + 1] = c1[0];
        out[n + 2] = c2[0];
    }
}

// ---------------------------------------------------------------------------
// Launch
// ---------------------------------------------------------------------------
extern "C" void kernel_launch(void* const* d_in, const int* in_sizes, int n_in,
                              void* d_out, int out_size) {
    const float* x      = (const float*)d_in[0];
    const int*   ei     = (const int*)d_in[1];
    const int*   nei    = (const int*)d_in[2];
    const float* W1_0   = (const float*)d_in[3];
    const float* W1_1   = (const float*)d_in[4];
    const float* b1     = (const float*)d_in[5];
    const float* W2_0   = (const float*)d_in[6];
    const float* W2_1   = (const float*)d_in[7];
    const float* b2     = (const float*)d_in[8];
    const float* W3_0   = (const float*)d_in[9];
    const float* W3_1   = (const float*)d_in[10];
    const float* b3     = (const float*)d_in[11];
    const float* lin1_W = (const float*)d_in[12];
    const float* lin1_b = (const float*)d_in[13];
    const float* lin2_W = (const float*)d_in[14];
    const float* lin2_b = (const float*)d_in[15];
    const float* c1     = (const float*)d_in[16];
    const float* c2     = (const float*)d_in[17];
    float* out = (float*)d_out;

    int n = in_sizes[0] / F_IN;   // 50000
    int e = in_sizes[1] / 2;      // 800000

    Scratch* sp = nullptr;
    cudaGetSymbolAddress((void**)&sp, g_s);
    int*   deg    = sp->deg;
    int*   cnt    = sp->cnt;
    int*   rowptr = sp->rowptr;
    int*   cursor = sp->cursor;
    int*   eidx   = sp->eidx;
    float* dis    = sp->dis;
    float* norm   = sp->norm;
    float* tx1    = sp->tx1;
    float* h      = sp->h;
    float* hW21   = sp->hW21;
    float* agg2   = sp->agg2;
    float* x1     = sp->x1;
    float* xm     = sp->xm;
    float* z      = sp->z;
    float* s0     = sp->s0;
    float* s1     = sp->s1;
    float* agg3   = sp->agg3;
    float* accum  = sp->accum;

    const int* src = ei;
    const int* dst = ei + e;

    int nb_n = (n + 255) / 256;
    int nb_e = (e + 255) / 256;

    // 1-6: degree, norm, CSR build
    zero_kernel<<<nb_n, 256>>>(deg, cnt, accum, n);
    hist_kernel<<<nb_e, 256>>>(src, dst, deg, cnt, e);
    dis_kernel<<<nb_n, 256>>>(deg, dis, n);
    norm_kernel<<<nb_e, 256>>>(src, dst, dis, norm, e);
    scan_kernel<<<1, 1024>>>(cnt, rowptr, cursor, n);
    fill_kernel<<<nb_e, 256>>>(dst, cursor, eidx, e);

    // 7: stage-1 aggregation at F=58
    int agg_blocks = (n * 32 + 255) / 256;
    agg_kernel<F_IN><<<agg_blocks, 256>>>(x, eidx, rowptr, src, norm, tx1, n);

    // 8: h = relu(x@W1_0 + tx1@W1_1 + b1)   [K=58, M=300]
    gemm_kernel<1, true, false><<<dim3((H1 + 63) / 64, (n + 63) / 64), 256>>>(
        x, W1_0, tx1, W1_1, nullptr, b1, h, n, F_IN, H1);

    // 9: hW21 = h@W2_1   [K=300, M=100]
    gemm_kernel<0, false, false><<<dim3((H2 + 63) / 64, (n + 63) / 64), 256>>>(
        h, W2_1, nullptr, nullptr, nullptr, nullptr, hW21, n, H1, H2);

    // 10: agg2 = Agg(hW21) at F=100
    agg_kernel<H2><<<agg_blocks, 256>>>(hW21, eidx, rowptr, src, norm, agg2, n);

    // 11: x1 = relu(h@W2_0 + agg2 + b2)
    gemm_kernel<2, false, false><<<dim3((H2 + 63) / 64, (n + 63) / 64), 256>>>(
        h, W2_0, nullptr, nullptr, agg2, b2, x1, n, H1, H2);

    // 12-13: xm = x1 + relu(x@lin1_W^T + lin1_b); z = x1 + relu(x@lin2_W^T + lin2_b)
    gemm_kernel<3, false, true><<<dim3((H2 + 63) / 64, (n + 63) / 64), 256>>>(
        x, lin1_W, nullptr, nullptr, x1, lin1_b, xm, n, F_IN, H2);
    gemm_kernel<3, false, true><<<dim3((H2 + 63) / 64, (n + 63) / 64), 256>>>(
        x, lin2_W, nullptr, nullptr, x1, lin2_b, z, n, F_IN, H2);

    // 14: s0 = xm@W3_0, s1 = xm@W3_1
    gemv3_kernel<<<agg_blocks, 256>>>(xm, W3_0, W3_1, s0, s1, n);

    // 15: agg3 = Agg(s1) at F=1
    agg1_kernel<<<nb_n, 256>>>(s1, eidx, rowptr, src, norm, agg3, n);

    // 16-17: edge score losses
    score_kernel<<<1184, 256>>>(z, ei, e, accum, 0);
    score_kernel<<<1184, 256>>>(z, nei, e, accum, 1);

    // 18: final assembly
    final_kernel<<<nb_n, 256>>>(s0, agg3, b3, accum, c1, c2, out, n, 1.0f / (float)e);
}

// round 2
// speedup vs baseline: 1.0998x; 1.0998x over previous
#include <cuda_runtime.h>
#include <math.h>

#define NN 50000
#define EE 800000
#define F_IN 58
#define FP 64      // padded feature dim for x / tx1
#define H1 300
#define H2 100

// ---------------------------------------------------------------------------
// Scratch (device-global, no runtime allocation).
// ---------------------------------------------------------------------------
struct alignas(16) Scratch {
    int   deg[NN];
    int   cnt[NN];
    int   rowptr[NN + 4];
    int   cursor[NN];
    int   csr_src[EE];       // src node per edge, CSR(dst) order
    float csr_norm[EE];      // norm per edge, CSR(dst) order
    float dis[NN];
    float xp[NN * FP];       // x padded to 64 cols (zeros in 58..63)
    float tx1[NN * FP];      // stage-1 aggregation, padded to 64
    float h[NN * H1];
    float hW21[NN * H2];
    float agg2[NN * H2];
    float x1[NN * H2];
    float xm[NN * H2];
    float z[NN * H2];
    float s0[NN];
    float s1[NN];
    float agg3[NN];
    float accum[2];
};
__device__ Scratch g_s;

// ---------------------------------------------------------------------------
// Setup kernels
// ---------------------------------------------------------------------------
__global__ void zero_kernel(int* deg, int* cnt, float* accum, int n) {
    int i = blockIdx.x * blockDim.x + threadIdx.x;
    if (i < n) { deg[i] = 0; cnt[i] = 0; }
    if (i < 2) accum[i] = 0.f;
}

__global__ void pad_x_kernel(const float* __restrict__ x, float* __restrict__ xp, int n) {
    int i = blockIdx.x * blockDim.x + threadIdx.x;
    if (i >= n * FP) return;
    int r = i / FP, f = i % FP;
    xp[i] = (f < F_IN) ? x[(long)r * F_IN + f] : 0.f;
}

__global__ void hist_kernel(const int* __restrict__ src, const int* __restrict__ dst,
                            int* deg, int* cnt, int e) {
    int i = blockIdx.x * blockDim.x + threadIdx.x;
    if (i < e) {
        atomicAdd(&deg[src[i]], 1);
        atomicAdd(&cnt[dst[i]], 1);
    }
}

__global__ void dis_kernel(const int* __restrict__ deg, float* __restrict__ dis, int n) {
    int i = blockIdx.x * blockDim.x + threadIdx.x;
    if (i < n) {
        int d = deg[i];
        dis[i] = (d > 0) ? (1.0f / sqrtf((float)d)) : 0.0f;
    }
}

// Single-block exclusive scan of cnt -> rowptr (copy into cursor).
__global__ void scan_kernel(const int* __restrict__ cnt, int* __restrict__ rowptr,
                            int* __restrict__ cursor, int n) {
    __shared__ int warp_sums[32];
    __shared__ int s_base;
    int tid = threadIdx.x;  // 1024
    if (tid == 0) s_base = 0;
    __syncthreads();
    for (int t0 = 0; t0 < n; t0 += 1024) {
        int i = t0 + tid;
        int v = (i < n) ? cnt[i] : 0;
        int x = v;
        #pragma unroll
        for (int d = 1; d < 32; d <<= 1) {
            int y = __shfl_up_sync(0xFFFFFFFFu, x, d);
            if ((tid & 31) >= d) x += y;
        }
        if ((tid & 31) == 31) warp_sums[tid >> 5] = x;
        __syncthreads();
        if (tid < 32) {
            int y = warp_sums[tid];
            int zz = y;
            #pragma unroll
            for (int d = 1; d < 32; d <<= 1) {
                int w = __shfl_up_sync(0xFFFFFFFFu, zz, d);
                if (tid >= d) zz += w;
            }
            warp_sums[tid] = zz - y;
        }
        __syncthreads();
        int incl = x + warp_sums[tid >> 5];
        int excl = s_base + incl - v;
        if (i < n) { rowptr[i] = excl; cursor[i] = excl; }
        __syncthreads();
        if (tid == 1023) s_base += incl;
        __syncthreads();
    }
    if (tid == 0) rowptr[n] = s_base;
}

// CSR fill: permute (src, norm) into dst-CSR order. Kills separate norm array.
__global__ void fill_kernel(const int* __restrict__ src, const int* __restrict__ dst,
                            const float* __restrict__ dis, int* __restrict__ cursor,
                            int* __restrict__ csr_src, float* __restrict__ csr_norm, int e) {
    int i = blockIdx.x * blockDim.x + threadIdx.x;
    if (i < e) {
        int s = src[i], d = dst[i];
        int p = atomicAdd(&cursor[d], 1);
        csr_src[p] = s;
        csr_norm[p] = -(dis[s] * dis[d]);
    }
}

// ---------------------------------------------------------------------------
// CSR aggregation: warp per node, F features strided by lane, row stride S.
// Zeros written for f in [F,S).
// ---------------------------------------------------------------------------
template <int F, int S>
__global__ void agg_kernel(const float* __restrict__ val, const int* __restrict__ csr_src,
                           const float* __restrict__ csr_norm, const int* __restrict__ rowptr,
                           float* __restrict__ out, int n) {
    int node = (blockIdx.x * blockDim.x + threadIdx.x) >> 5;
    int lane = threadIdx.x & 31;
    if (node >= n) return;
    int beg = rowptr[node], end = rowptr[node + 1];
    constexpr int R = (S + 31) / 32;
    float acc[R];
    #pragma unroll
    for (int r = 0; r < R; r++) acc[r] = 0.f;
    for (int j = beg; j < end; j++) {
        int s = csr_src[j];
        float w = csr_norm[j];
        const float* vrow = val + (long)s * S;
        #pragma unroll
        for (int r = 0; r < R; r++) {
            int f = lane + r * 32;
            if (f < F) acc[r] += vrow[f] * w;
        }
    }
    float* orow = out + (long)node * S;
    #pragma unroll
    for (int r = 0; r < R; r++) {
        int f = lane + r * 32;
        if (f < S) orow[f] = acc[r];
    }
}

__global__ void agg1_kernel(const float* __restrict__ val, const int* __restrict__ csr_src,
                            const float* __restrict__ csr_norm, const int* __restrict__ rowptr,
                            float* __restrict__ out, int n) {
    int i = blockIdx.x * blockDim.x + threadIdx.x;
    if (i >= n) return;
    float a = 0.f;
    int end = rowptr[i + 1];
    for (int j = rowptr[i]; j < end; j++)
        a += val[csr_src[j]] * csr_norm[j];
    out[i] = a;
}

// ---------------------------------------------------------------------------
// Vectorized register-blocked fp32 GEMM. 64x64 tile, BK=16, 256 thr, 4x4/thread.
// MODE 0: C = acc
// MODE 1: C = relu(acc + bias)
// MODE 2: C = relu(acc + addm + bias)
// MODE 3: C = addm + relu(acc + bias)
// DUAL:    acc += A2@B2 (second pass, same acc)          [stage 1]
// DUALOUT: second B/bias/output with shared A tile       [lin1+lin2]
// TRANSB:  B stored [M,KB] (read B[n,k])
// K: A row stride & k-loop bound (multiple of 4). KB: true inner dim for B guard.
// ---------------------------------------------------------------------------
template <int MODE, bool DUAL, bool TRANSB, bool DUALOUT>
__global__ __launch_bounds__(256)
void gemm_kernel(const float* __restrict__ A1, const float* __restrict__ B1,
                 const float* __restrict__ A2, const float* __restrict__ B2,
                 const float* __restrict__ addm, const float* __restrict__ bias,
                 const float* __restrict__ bias2,
                 float* __restrict__ C, float* __restrict__ C2,
                 int Nr, int K, int KB, int M) {
    constexpr int BM = 64, BN = 64, BK = 16;
    __shared__ alignas(16) float As[BK][BM + 4];
    __shared__ alignas(16) float Bs1[BK][BN];
    __shared__ alignas(16) float Bs2[DUALOUT ? BK : 1][BN];

    int bm = blockIdx.y * BM, bn = blockIdx.x * BN;
    int tid = threadIdx.x;
    int tr = tid / 16, tc = tid % 16;

    float acc1[4][4];
    float acc2[DUALOUT ? 4 : 1][4];
    #pragma unroll
    for (int i = 0; i < 4; i++)
        #pragma unroll
        for (int j = 0; j < 4; j++) acc1[i][j] = 0.f;
    if (DUALOUT) {
        #pragma unroll
        for (int i = 0; i < 4; i++)
            #pragma unroll
            for (int j = 0; j < 4; j++) acc2[i][j] = 0.f;
    }

    // A loader indices: 64 rows x 4 float4-groups
    int lm = tid >> 2;             // 0..63
    int lkq = (tid & 3) * 4;       // 0,4,8,12
    // B loader (!TRANSB): 16 k x 16 float4-groups
    int lk = tid >> 4;             // 0..15
    int lng = (tid & 15) * 4;      // 0..60

    int npass = DUAL ? 2 : 1;
    for (int pass = 0; pass < npass; pass++) {
        const float* A = pass ? A2 : A1;
        const float* B = pass ? B2 : B1;
        for (int k0 = 0; k0 < K; k0 += BK) {
            // load A tile (transposed into As[k][m]) via float4
            {
                int gr = bm + lm, gk = k0 + lkq;
                float4 v = make_float4(0.f, 0.f, 0.f, 0.f);
                if (gr < Nr && gk + 4 <= K)
                    v = *reinterpret_cast<const float4*>(A + (long)gr * K + gk);
                As[lkq + 0][lm] = v.x;
                As[lkq + 1][lm] = v.y;
                As[lkq + 2][lm] = v.z;
                As[lkq + 3][lm] = v.w;
            }
            // load B tile(s)
            if (!TRANSB) {
                int gk = k0 + lk, gn = bn + lng;
                float4 v = make_float4(0.f, 0.f, 0.f, 0.f);
                if (gk < KB && gn < M)  // M%4==0 -> group fully in-bounds
                    v = *reinterpret_cast<const float4*>(B + (long)gk * M + gn);
                *reinterpret_cast<float4*>(&Bs1[lk][lng]) = v;
                if (DUALOUT) {
                    float4 v2 = make_float4(0.f, 0.f, 0.f, 0.f);
                    if (gk < KB && gn < M)
                        v2 = *reinterpret_cast<const float4*>(B2 + (long)gk * M + gn);
                    *reinterpret_cast<float4*>(&Bs2[lk][lng]) = v2;
                }
            } else {
                #pragma unroll
                for (int i = 0; i < 4; i++) {
                    int idx = tid + i * 256;
                    int k = idx / BN, nn = idx % BN;
                    int gk = k0 + k, gn = bn + nn;
                    Bs1[k][nn] = (gk < KB && gn < M) ? B[(long)gn * KB + gk] : 0.f;
                    if (DUALOUT)
                        Bs2[k][nn] = (gk < KB && gn < M) ? B2[(long)gn * KB + gk] : 0.f;
                }
            }
            __syncthreads();
            #pragma unroll
            for (int k = 0; k < BK; k++) {
                float4 a = *reinterpret_cast<const float4*>(&As[k][tr * 4]);
                float4 b = *reinterpret_cast<const float4*>(&Bs1[k][tc * 4]);
                float av[4] = {a.x, a.y, a.z, a.w};
                float bv[4] = {b.x, b.y, b.z, b.w};
                #pragma unroll
                for (int i = 0; i < 4; i++)
                    #pragma unroll
                    for (int j = 0; j < 4; j++) acc1[i][j] += av[i] * bv[j];
                if (DUALOUT) {
                    float4 b2 = *reinterpret_cast<const float4*>(&Bs2[k][tc * 4]);
                    float b2v[4] = {b2.x, b2.y, b2.z, b2.w};
                    #pragma unroll
                    for (int i = 0; i < 4; i++)
                        #pragma unroll
                        for (int j = 0; j < 4; j++) acc2[i][j] += av[i] * b2v[j];
                }
            }
            __syncthreads();
        }
    }

    // Epilogue (M%4==0, c0 multiple of 4 -> group fully valid iff c0 < M)
    int c0 = bn + tc * 4;
    if (c0 >= M) return;
    float4 bi = make_float4(0.f, 0.f, 0.f, 0.f), bi2 = bi;
    if (MODE >= 1) bi = *reinterpret_cast<const float4*>(bias + c0);
    if (DUALOUT) bi2 = *reinterpret_cast<const float4*>(bias2 + c0);
    #pragma unroll
    for (int i = 0; i < 4; i++) {
        int r = bm + tr * 4 + i;
        if (r >= Nr) continue;
        long base = (long)r * M + c0;
        float ad[4] = {0.f, 0.f, 0.f, 0.f};
        if (MODE == 2 || MODE == 3) {
            float4 a4 = *reinterpret_cast<const float4*>(addm + base);
            ad[0] = a4.x; ad[1] = a4.y; ad[2] = a4.z; ad[3] = a4.w;
        }
        float bv[4] = {bi.x, bi.y, bi.z, bi.w};
        float out1[4];
        #pragma unroll
        for (int j = 0; j < 4; j++) {
            float v = acc1[i][j];
            if (MODE >= 1) v += bv[j];
            if (MODE == 2) v += ad[j];
            if (MODE >= 1) v = fmaxf(v, 0.f);
            if (MODE == 3) v += ad[j];
            out1[j] = v;
        }
        *reinterpret_cast<float4*>(C + base) =
            make_float4(out1[0], out1[1], out1[2], out1[3]);
        if (DUALOUT) {
            float b2v[4] = {bi2.x, bi2.y, bi2.z, bi2.w};
            float out2[4];
            #pragma unroll
            for (int j = 0; j < 4; j++) {
                float v = acc2[i][j] + b2v[j];
                v = fmaxf(v, 0.f);
                out2[j] = v + ad[j];
            }
            *reinterpret_cast<float4*>(C2 + base) =
                make_float4(out2[0], out2[1], out2[2], out2[3]);
        }
    }
}

// ---------------------------------------------------------------------------
// Stage-3 dual GEMV: s0 = xm@W3_0, s1 = xm@W3_1  (K=100)
// ---------------------------------------------------------------------------
__global__ void gemv3_kernel(const float* __restrict__ xm, const float* __restrict__ w0,
                             const float* __restrict__ w1, float* __restrict__ s0,
                             float* __restrict__ s1, int n) {
    int warp = (blockIdx.x * blockDim.x + threadIdx.x) >> 5;
    int lane = threadIdx.x & 31;
    if (warp >= n) return;
    float a0 = 0.f, a1 = 0.f;
    const float* row = xm + (long)warp * H2;
    for (int f = lane; f < H2; f += 32) {
        float v = row[f];
        a0 += v * w0[f];
        a1 += v * w1[f];
    }
    #pragma unroll
    for (int d = 16; d; d >>= 1) {
        a0 += __shfl_down_sync(0xFFFFFFFFu, a0, d);
        a1 += __shfl_down_sync(0xFFFFFFFFu, a1, d);
    }
    if (lane == 0) { s0[warp] = a0; s1[warp] = a1; }
}

// ---------------------------------------------------------------------------
// Merged pos+neg edge score loss: warp per edge over [0, 2E).
// ---------------------------------------------------------------------------
__global__ void score_kernel(const float* __restrict__ z, const int* __restrict__ ei,
                             const int* __restrict__ nei, int E_, float* __restrict__ accum) {
    int lane = threadIdx.x & 31;
    int warp_global = (blockIdx.x * blockDim.x + threadIdx.x) >> 5;
    int nwarps = (gridDim.x * blockDim.x) >> 5;
    float psum = 0.f, nsum = 0.f;
    for (int t = warp_global; t < 2 * E_; t += nwarps) {
        int which = (t >= E_);
        const int* p = which ? nei : ei;
        int e = which ? t - E_ : t;
        int a = p[e], b = p[e + E_];
        const float4* za = (const float4*)(z + (long)a * H2);
        const float4* zb = (const float4*)(z + (long)b * H2);
        float dot = 0.f;
        if (lane < 25) {
            float4 u = za[lane];
            float4 v = zb[lane];
            dot = u.x * v.x + u.y * v.y + u.z * v.z + u.w * v.w;
        }
        #pragma unroll
        for (int dd = 16; dd; dd >>= 1) dot += __shfl_down_sync(0xFFFFFFFFu, dot, dd);
        if (lane == 0) {
            float sig = 1.f / (1.f + expf(-dot));
            if (which) nsum += logf(1.f - sig + 1e-15f);
            else       psum += logf(sig + 1e-15f);
        }
    }
    __shared__ float redp[32], redn[32];
    #pragma unroll
    for (int dd = 16; dd; dd >>= 1) {
        psum += __shfl_down_sync(0xFFFFFFFFu, psum, dd);
        nsum += __shfl_down_sync(0xFFFFFFFFu, nsum, dd);
    }
    if (lane == 0) { redp[threadIdx.x >> 5] = psum; redn[threadIdx.x >> 5] = nsum; }
    __syncthreads();
    if (threadIdx.x < 32) {
        int nw = blockDim.x >> 5;
        float vp = (threadIdx.x < nw) ? redp[threadIdx.x] : 0.f;
        float vn = (threadIdx.x < nw) ? redn[threadIdx.x] : 0.f;
        #pragma unroll
        for (int dd = 16; dd; dd >>= 1) {
            vp += __shfl_down_sync(0xFFFFFFFFu, vp, dd);
            vn += __shfl_down_sync(0xFFFFFFFFu, vn, dd);
        }
        if (threadIdx.x == 0) {
            atomicAdd(&accum[0], vp);
            atomicAdd(&accum[1], vn);
        }
    }
}

__global__ void final_kernel(const float* __restrict__ s0, const float* __restrict__ agg3,
                             const float* __restrict__ b3, const float* __restrict__ accum,
                             const float* __restrict__ c1, const float* __restrict__ c2,
                             float* __restrict__ out, int n, float invE) {
    int i = blockIdx.x * blockDim.x + threadIdx.x;
    if (i < n) out[i] = s0[i] + agg3[i] + b3[0];
    if (i == 0) {
        out[n] = -(accum[0] + accum[1]) * invE;
        out[n + 1] = c1[0];
        out[n + 2] = c2[0];
    }
}

// ---------------------------------------------------------------------------
// Launch
// ---------------------------------------------------------------------------
extern "C" void kernel_launch(void* const* d_in, const int* in_sizes, int n_in,
                              void* d_out, int out_size) {
    const float* x      = (const float*)d_in[0];
    const int*   ei     = (const int*)d_in[1];
    const int*   nei    = (const int*)d_in[2];
    const float* W1_0   = (const float*)d_in[3];
    const float* W1_1   = (const float*)d_in[4];
    const float* b1     = (const float*)d_in[5];
    const float* W2_0   = (const float*)d_in[6];
    const float* W2_1   = (const float*)d_in[7];
    const float* b2     = (const float*)d_in[8];
    const float* W3_0   = (const float*)d_in[9];
    const float* W3_1   = (const float*)d_in[10];
    const float* b3     = (const float*)d_in[11];
    const float* lin1_W = (const float*)d_in[12];
    const float* lin1_b = (const float*)d_in[13];
    const float* lin2_W = (const float*)d_in[14];
    const float* lin2_b = (const float*)d_in[15];
    const float* c1     = (const float*)d_in[16];
    const float* c2     = (const float*)d_in[17];
    float* out = (float*)d_out;

    int n = in_sizes[0] / F_IN;   // 50000
    int e = in_sizes[1] / 2;      // 800000

    Scratch* sp = nullptr;
    cudaGetSymbolAddress((void**)&sp, g_s);

    const int* src = ei;
    const int* dst = ei + e;

    int nb_n = (n + 255) / 256;
    int nb_e = (e + 255) / 256;
    int agg_blocks = (n * 32 + 255) / 256;

    // Setup + CSR
    zero_kernel<<<nb_n, 256>>>(sp->deg, sp->cnt, sp->accum, n);
    pad_x_kernel<<<(n * FP + 255) / 256, 256>>>(x, sp->xp, n);
    hist_kernel<<<nb_e, 256>>>(src, dst, sp->deg, sp->cnt, e);
    dis_kernel<<<nb_n, 256>>>(sp->deg, sp->dis, n);
    scan_kernel<<<1, 1024>>>(sp->cnt, sp->rowptr, sp->cursor, n);
    fill_kernel<<<nb_e, 256>>>(src, dst, sp->dis, sp->cursor, sp->csr_src, sp->csr_norm, e);

    // Stage 1: tx1 = Agg(xp) at F=58 (padded to 64)
    agg_kernel<F_IN, FP><<<agg_blocks, 256>>>(sp->xp, sp->csr_src, sp->csr_norm,
                                              sp->rowptr, sp->tx1, n);
    // h = relu(xp@W1_0 + tx1@W1_1 + b1)   [K=64 padded, KB=58, M=300]
    gemm_kernel<1, true, false, false><<<dim3((H1 + 63) / 64, (n + 63) / 64), 256>>>(
        sp->xp, W1_0, sp->tx1, W1_1, nullptr, b1, nullptr, sp->h, nullptr, n, FP, F_IN, H1);

    // Stage 2: hW21 = h@W2_1   [K=300, M=100]
    gemm_kernel<0, false, false, false><<<dim3((H2 + 63) / 64, (n + 63) / 64), 256>>>(
        sp->h, W2_1, nullptr, nullptr, nullptr, nullptr, nullptr, sp->hW21, nullptr,
        n, H1, H1, H2);
    agg_kernel<H2, H2><<<agg_blocks, 256>>>(sp->hW21, sp->csr_src, sp->csr_norm,
                                            sp->rowptr, sp->agg2, n);
    // x1 = relu(h@W2_0 + agg2 + b2)
    gemm_kernel<2, false, false, false><<<dim3((H2 + 63) / 64, (n + 63) / 64), 256>>>(
        sp->h, W2_0, nullptr, nullptr, sp->agg2, b2, nullptr, sp->x1, nullptr,
        n, H1, H1, H2);

    // xm = x1 + relu(xp@lin1_W^T + lin1_b); z = x1 + relu(xp@lin2_W^T + lin2_b)
    gemm_kernel<3, false, true, true><<<dim3((H2 + 63) / 64, (n + 63) / 64), 256>>>(
        sp->xp, lin1_W, nullptr, lin2_W, sp->x1, lin1_b, lin2_b, sp->xm, sp->z,
        n, FP, F_IN, H2);

    // Stage 3
    gemv3_kernel<<<agg_blocks, 256>>>(sp->xm, W3_0, W3_1, sp->s0, sp->s1, n);
    agg1_kernel<<<nb_n, 256>>>(sp->s1, sp->csr_src, sp->csr_norm, sp->rowptr, sp->agg3, n);

    // Edge losses (merged pos+neg)
    score_kernel<<<2048, 256>>>(sp->z, ei, nei, e, sp->accum);

    // Final assembly
    final_kernel<<<nb_n, 256>>>(sp->s0, sp->agg3, b3, sp->accum, c1, c2, out, n,
                                1.0f / (float)e);
}

// round 4
// speedup vs baseline: 1.2380x; 1.1257x over previous
#include <cuda_runtime.h>
#include <cuda_bf16.h>
#include <cstdint>
#include <math.h>

#define NN 50000
#define EE 800000
#define F_IN 58
#define FP 64
#define H1 300
#define H2 100
#define H1P 320   // padded H1
#define H2P 128   // padded H2
#define KA1 128   // K for GEMM1: [xp|tx1]
#define KH 320    // padded K for GEMM2/3 (h)

// ---------------------------------------------------------------------------
// Scratch (device-global, no runtime allocation).
// ---------------------------------------------------------------------------
struct alignas(16) Scratch {
    int   deg[NN];
    int   cnt[NN];
    int   rowptr[NN + 4];
    int   cursor[NN];
    int   csr_src[EE];
    float csr_norm[EE];
    int   bsum[64];
    int   boff[64];
    float dis[NN];
    float xp[NN * FP];
    float tx1[NN * FP];
    __nv_bfloat16 xpA_hi[NN * KA1], xpA_lo[NN * KA1];   // [xp|tx1] bf16 split
    __nv_bfloat16 h_hi[NN * KH],   h_lo[NN * KH];       // h bf16 split, [N,320]
    float hW21[NN * H2P];
    float agg2[NN * H2P];
    float x1[NN * H2P];
    float xm[NN * H2P];
    float z[NN * H2P];
    __nv_bfloat16 W1c_hi[KA1 * H1P], W1c_lo[KA1 * H1P]; // [128,320]
    __nv_bfloat16 W20_hi[KH * H2P],  W20_lo[KH * H2P];  // [320,128]
    __nv_bfloat16 W21_hi[KH * H2P],  W21_lo[KH * H2P];
    __nv_bfloat16 L1_hi[FP * H2P],   L1_lo[FP * H2P];   // [64,128] lin W^T
    __nv_bfloat16 L2_hi[FP * H2P],   L2_lo[FP * H2P];
    float b1p[H1P], b2p[H2P], l1bp[H2P], l2bp[H2P];
    float s0[NN], s1[NN], agg3[NN];
    float accum[2];
};
__device__ Scratch g_s;

// ---------------------------------------------------------------------------
// PTX helpers
// ---------------------------------------------------------------------------
__device__ __forceinline__ uint32_t smem_u32(const void* p) {
    return (uint32_t)__cvta_generic_to_shared(p);
}
__device__ __forceinline__ void ldm_x4(uint32_t* r, uint32_t addr) {
    asm volatile("ldmatrix.sync.aligned.m8n8.x4.shared.b16 {%0,%1,%2,%3}, [%4];"
                 : "=r"(r[0]), "=r"(r[1]), "=r"(r[2]), "=r"(r[3]) : "r"(addr));
}
__device__ __forceinline__ void ldm_x4_t(uint32_t* r, uint32_t addr) {
    asm volatile("ldmatrix.sync.aligned.m8n8.x4.trans.shared.b16 {%0,%1,%2,%3}, [%4];"
                 : "=r"(r[0]), "=r"(r[1]), "=r"(r[2]), "=r"(r[3]) : "r"(addr));
}
__device__ __forceinline__ void mma_bf16(float* c, const uint32_t* a, const uint32_t* b) {
    asm volatile("mma.sync.aligned.m16n8k16.row.col.f32.bf16.bf16.f32 "
                 "{%0,%1,%2,%3}, {%4,%5,%6,%7}, {%8,%9}, {%0,%1,%2,%3};"
                 : "+f"(c[0]), "+f"(c[1]), "+f"(c[2]), "+f"(c[3])
                 : "r"(a[0]), "r"(a[1]), "r"(a[2]), "r"(a[3]), "r"(b[0]), "r"(b[1]));
}
__device__ __forceinline__ void bf16_split(float v, __nv_bfloat16& hi, __nv_bfloat16& lo) {
    hi = __float2bfloat16(v);
    lo = __float2bfloat16(v - __bfloat162float(hi));
}

// ---------------------------------------------------------------------------
// Setup kernels
// ---------------------------------------------------------------------------
__global__ void zero_kernel(int* deg, int* cnt, float* accum, int n) {
    int i = blockIdx.x * blockDim.x + threadIdx.x;
    if (i < n) { deg[i] = 0; cnt[i] = 0; }
    if (i < 2) accum[i] = 0.f;
}

__global__ void pad_x_kernel(const float* __restrict__ x, float* __restrict__ xp, int n) {
    int i = blockIdx.x * blockDim.x + threadIdx.x;
    if (i >= n * FP) return;
    int r = i / FP, f = i % FP;
    xp[i] = (f < F_IN) ? x[(long)r * F_IN + f] : 0.f;
}

__global__ void hist_kernel(const int* __restrict__ src, const int* __restrict__ dst,
                            int* deg, int* cnt, int e) {
    int i = blockIdx.x * blockDim.x + threadIdx.x;
    if (i < e) {
        atomicAdd(&deg[src[i]], 1);
        atomicAdd(&cnt[dst[i]], 1);
    }
}

__global__ void dis_kernel(const int* __restrict__ deg, float* __restrict__ dis, int n) {
    int i = blockIdx.x * blockDim.x + threadIdx.x;
    if (i < n) {
        int d = deg[i];
        dis[i] = (d > 0) ? (1.0f / sqrtf((float)d)) : 0.0f;
    }
}

// Parallel scan stage 1: per-block (1024) exclusive scan + block totals.
__global__ void scan1_kernel(const int* __restrict__ cnt, int* __restrict__ rowptr,
                             int* __restrict__ bsum, int n) {
    __shared__ int warp_sums[32];
    int tid = threadIdx.x;
    int i = blockIdx.x * 1024 + tid;
    int v = (i < n) ? cnt[i] : 0;
    int x = v;
    #pragma unroll
    for (int d = 1; d < 32; d <<= 1) {
        int y = __shfl_up_sync(0xFFFFFFFFu, x, d);
        if ((tid & 31) >= d) x += y;
    }
    if ((tid & 31) == 31) warp_sums[tid >> 5] = x;
    __syncthreads();
    if (tid < 32) {
        int y = warp_sums[tid];
        int zz = y;
        #pragma unroll
        for (int d = 1; d < 32; d <<= 1) {
            int w = __shfl_up_sync(0xFFFFFFFFu, zz, d);
            if (tid >= d) zz += w;
        }
        warp_sums[tid] = zz - y;
    }
    __syncthreads();
    int incl = x + warp_sums[tid >> 5];
    if (i < n) rowptr[i] = incl - v;
    if (tid == 1023) bsum[blockIdx.x] = incl;
}

__global__ void scan2_kernel(const int* __restrict__ bsum, int* __restrict__ boff,
                             int* __restrict__ rowptr, int nb, int n) {
    if (threadIdx.x == 0 && blockIdx.x == 0) {
        int run = 0;
        for (int b = 0; b < nb; b++) { boff[b] = run; run += bsum[b]; }
        rowptr[n] = run;
    }
}

__global__ void scan3_kernel(int* __restrict__ rowptr, int* __restrict__ cursor,
                             const int* __restrict__ boff, int n) {
    int i = blockIdx.x * 1024 + threadIdx.x;
    if (i < n) {
        int v = rowptr[i] + boff[blockIdx.x];
        rowptr[i] = v;
        cursor[i] = v;
    }
}

__global__ void fill_kernel(const int* __restrict__ src, const int* __restrict__ dst,
                            const float* __restrict__ dis, int* __restrict__ cursor,
                            int* __restrict__ csr_src, float* __restrict__ csr_norm, int e) {
    int i = blockIdx.x * blockDim.x + threadIdx.x;
    if (i < e) {
        int s = src[i], d = dst[i];
        int p = atomicAdd(&cursor[d], 1);
        csr_src[p] = s;
        csr_norm[p] = -(dis[s] * dis[d]);
    }
}

// ---------------------------------------------------------------------------
// Converters (fp32 -> bf16 hi/lo split)
// ---------------------------------------------------------------------------
__global__ void convA_kernel(const float* __restrict__ xp, const float* __restrict__ tx1,
                             __nv_bfloat16* __restrict__ hi, __nv_bfloat16* __restrict__ lo,
                             int n) {
    int i = blockIdx.x * blockDim.x + threadIdx.x;
    if (i >= n * KA1) return;
    int r = i >> 7, c = i & 127;
    float v = (c < FP) ? xp[(long)r * FP + c] : tx1[(long)r * FP + (c - FP)];
    __nv_bfloat16 h16, l16;
    bf16_split(v, h16, l16);
    hi[i] = h16; lo[i] = l16;
}

__global__ void convW1_kernel(const float* __restrict__ W10, const float* __restrict__ W11,
                              __nv_bfloat16* __restrict__ hi, __nv_bfloat16* __restrict__ lo) {
    int i = blockIdx.x * blockDim.x + threadIdx.x;
    if (i >= KA1 * H1P) return;
    int k = i / H1P, m = i % H1P;
    float v = 0.f;
    if (m < H1) {
        if (k < F_IN) v = W10[k * H1 + m];
        else if (k >= FP && k < FP + F_IN) v = W11[(k - FP) * H1 + m];
    }
    __nv_bfloat16 h16, l16;
    bf16_split(v, h16, l16);
    hi[i] = h16; lo[i] = l16;
}

__global__ void convW2_kernel(const float* __restrict__ W,
                              __nv_bfloat16* __restrict__ hi, __nv_bfloat16* __restrict__ lo) {
    int i = blockIdx.x * blockDim.x + threadIdx.x;
    if (i >= KH * H2P) return;
    int k = i >> 7, m = i & 127;
    float v = (k < H1 && m < H2) ? W[k * H2 + m] : 0.f;
    __nv_bfloat16 h16, l16;
    bf16_split(v, h16, l16);
    hi[i] = h16; lo[i] = l16;
}

__global__ void convWT_kernel(const float* __restrict__ W /* [100,58] */,
                              __nv_bfloat16* __restrict__ hi, __nv_bfloat16* __restrict__ lo) {
    int i = blockIdx.x * blockDim.x + threadIdx.x;
    if (i >= FP * H2P) return;
    int k = i >> 7, m = i & 127;
    float v = (k < F_IN && m < H2) ? W[m * F_IN + k] : 0.f;
    __nv_bfloat16 h16, l16;
    bf16_split(v, h16, l16);
    hi[i] = h16; lo[i] = l16;
}

__global__ void padb_kernel(const float* b1, const float* b2, const float* l1b,
                            const float* l2b, float* b1p, float* b2p, float* l1bp,
                            float* l2bp) {
    int i = threadIdx.x;  // 320 threads
    if (i < H1P) b1p[i] = (i < H1) ? b1[i] : 0.f;
    if (i < H2P) {
        b2p[i]  = (i < H2) ? b2[i] : 0.f;
        l1bp[i] = (i < H2) ? l1b[i] : 0.f;
        l2bp[i] = (i < H2) ? l2b[i] : 0.f;
    }
}

// ---------------------------------------------------------------------------
// CSR aggregation: warp per node. F = valid cols, S = row stride.
// ---------------------------------------------------------------------------
template <int F, int S>
__global__ void agg_kernel(const float* __restrict__ val, const int* __restrict__ csr_src,
                           const float* __restrict__ csr_norm, const int* __restrict__ rowptr,
                           float* __restrict__ out, int n) {
    int node = (blockIdx.x * blockDim.x + threadIdx.x) >> 5;
    int lane = threadIdx.x & 31;
    if (node >= n) return;
    int beg = rowptr[node], end = rowptr[node + 1];
    constexpr int R = (S + 31) / 32;
    float acc[R];
    #pragma unroll
    for (int r = 0; r < R; r++) acc[r] = 0.f;
    for (int j = beg; j < end; j++) {
        int s = csr_src[j];
        float w = csr_norm[j];
        const float* vrow = val + (long)s * S;
        #pragma unroll
        for (int r = 0; r < R; r++) {
            int f = lane + r * 32;
            if (f < F) acc[r] += vrow[f] * w;
        }
    }
    float* orow = out + (long)node * S;
    #pragma unroll
    for (int r = 0; r < R; r++) {
        int f = lane + r * 32;
        if (f < S) orow[f] = acc[r];
    }
}

__global__ void agg1_kernel(const float* __restrict__ val, const int* __restrict__ csr_src,
                            const float* __restrict__ csr_norm, const int* __restrict__ rowptr,
                            float* __restrict__ out, int n) {
    int i = blockIdx.x * blockDim.x + threadIdx.x;
    if (i >= n) return;
    float a = 0.f;
    int end = rowptr[i + 1];
    for (int j = rowptr[i]; j < end; j++)
        a += val[csr_src[j]] * csr_norm[j];
    out[i] = a;
}

// ---------------------------------------------------------------------------
// Split-bf16 tensor-core GEMM.
// C[fp32] = epilogue( A_hi@B_hi + A_hi@B_lo + A_lo@B_hi )
// Tile: BM=128, BN=64, BK=32. 256 threads = 8 warps (4x2), 32x32 per warp.
// MODE 0: C=acc | 1: relu(acc+bias) | 2: relu(acc+addm+bias) | 3: addm+relu(acc+bias)
// DUALOUT: second B/bias/output (shared A). OUTBF16: write hi/lo bf16 split.
// Requirements: K%32==0, M%64==0, grid.x=M/64, all operands padded (no col guards).
// ---------------------------------------------------------------------------
template <int MODE, bool DUALOUT, bool OUTBF16>
__global__ __launch_bounds__(256)
void bgemm_kernel(const __nv_bfloat16* __restrict__ Ahi, const __nv_bfloat16* __restrict__ Alo,
                  int lda, int K,
                  const __nv_bfloat16* __restrict__ B1hi, const __nv_bfloat16* __restrict__ B1lo,
                  const __nv_bfloat16* __restrict__ B2hi, const __nv_bfloat16* __restrict__ B2lo,
                  const float* __restrict__ addm, const float* __restrict__ bias1,
                  const float* __restrict__ bias2,
                  float* __restrict__ C1, float* __restrict__ C2,
                  __nv_bfloat16* __restrict__ Cbhi, __nv_bfloat16* __restrict__ Cblo,
                  int Nr, int M) {
    __shared__ __align__(16) __nv_bfloat16 As_hi[128][40];
    __shared__ __align__(16) __nv_bfloat16 As_lo[128][40];
    __shared__ __align__(16) __nv_bfloat16 Bs_hi[32][72];
    __shared__ __align__(16) __nv_bfloat16 Bs_lo[32][72];
    __shared__ __align__(16) __nv_bfloat16 Bs2_hi[32][72];
    __shared__ __align__(16) __nv_bfloat16 Bs2_lo[32][72];

    int tid = threadIdx.x;
    int bm = blockIdx.y * 128, bn = blockIdx.x * 64;
    int lane = tid & 31, wid = tid >> 5;
    int wm = (wid >> 1) * 32, wn = (wid & 1) * 32;

    float acc[2][4][4];
    float acc2[2][4][4];
    #pragma unroll
    for (int mf = 0; mf < 2; mf++)
        #pragma unroll
        for (int nf = 0; nf < 4; nf++)
            #pragma unroll
            for (int q = 0; q < 4; q++) { acc[mf][nf][q] = 0.f; acc2[mf][nf][q] = 0.f; }

    for (int k0 = 0; k0 < K; k0 += 32) {
        // --- load A tile (hi+lo): 128 rows x 32 halves, uint4 chunks
        #pragma unroll
        for (int i = 0; i < 2; i++) {
            int c = tid * 2 + i;
            int row = c >> 2, seg = c & 3;
            int gr = bm + row;
            uint4 vh = make_uint4(0, 0, 0, 0), vl = vh;
            if (gr < Nr) {
                long off = (long)gr * lda + k0 + seg * 8;
                vh = *reinterpret_cast<const uint4*>(Ahi + off);
                vl = *reinterpret_cast<const uint4*>(Alo + off);
            }
            *reinterpret_cast<uint4*>(&As_hi[row][seg * 8]) = vh;
            *reinterpret_cast<uint4*>(&As_lo[row][seg * 8]) = vl;
        }
        // --- load B tile(s): 32 rows x 64 halves
        {
            int row = tid >> 3, seg = tid & 7;
            long off = (long)(k0 + row) * M + bn + seg * 8;
            *reinterpret_cast<uint4*>(&Bs_hi[row][seg * 8]) =
                *reinterpret_cast<const uint4*>(B1hi + off);
            *reinterpret_cast<uint4*>(&Bs_lo[row][seg * 8]) =
                *reinterpret_cast<const uint4*>(B1lo + off);
            if constexpr (DUALOUT) {
                *reinterpret_cast<uint4*>(&Bs2_hi[row][seg * 8]) =
                    *reinterpret_cast<const uint4*>(B2hi + off);
                *reinterpret_cast<uint4*>(&Bs2_lo[row][seg * 8]) =
                    *reinterpret_cast<const uint4*>(B2lo + off);
            }
        }
        __syncthreads();

        #pragma unroll
        for (int s = 0; s < 32; s += 16) {
            uint32_t a_hi[2][4], a_lo[2][4];
            #pragma unroll
            for (int mf = 0; mf < 2; mf++) {
                int row = wm + mf * 16 + (lane & 15);
                int col = s + ((lane >> 4) << 3);
                ldm_x4(a_hi[mf], smem_u32(&As_hi[row][col]));
                ldm_x4(a_lo[mf], smem_u32(&As_lo[row][col]));
            }
            int kr = s + (lane & 7) + (lane & 8);
            int nshift = (lane >> 4) << 3;
            uint32_t b_hi[4][2], b_lo[4][2];
            #pragma unroll
            for (int g = 0; g < 2; g++) {
                int nc = wn + g * 16 + nshift;
                uint32_t r[4];
                ldm_x4_t(r, smem_u32(&Bs_hi[kr][nc]));
                b_hi[g * 2][0] = r[0]; b_hi[g * 2][1] = r[1];
                b_hi[g * 2 + 1][0] = r[2]; b_hi[g * 2 + 1][1] = r[3];
                ldm_x4_t(r, smem_u32(&Bs_lo[kr][nc]));
                b_lo[g * 2][0] = r[0]; b_lo[g * 2][1] = r[1];
                b_lo[g * 2 + 1][0] = r[2]; b_lo[g * 2 + 1][1] = r[3];
            }
            #pragma unroll
            for (int mf = 0; mf < 2; mf++)
                #pragma unroll
                for (int nf = 0; nf < 4; nf++) {
                    mma_bf16(acc[mf][nf], a_hi[mf], b_hi[nf]);
                    mma_bf16(acc[mf][nf], a_hi[mf], b_lo[nf]);
                    mma_bf16(acc[mf][nf], a_lo[mf], b_hi[nf]);
                }
            if constexpr (DUALOUT) {
                uint32_t b2_hi[4][2], b2_lo[4][2];
                #pragma unroll
                for (int g = 0; g < 2; g++) {
                    int nc = wn + g * 16 + nshift;
                    uint32_t r[4];
                    ldm_x4_t(r, smem_u32(&Bs2_hi[kr][nc]));
                    b2_hi[g * 2][0] = r[0]; b2_hi[g * 2][1] = r[1];
                    b2_hi[g * 2 + 1][0] = r[2]; b2_hi[g * 2 + 1][1] = r[3];
                    ldm_x4_t(r, smem_u32(&Bs2_lo[kr][nc]));
                    b2_lo[g * 2][0] = r[0]; b2_lo[g * 2][1] = r[1];
                    b2_lo[g * 2 + 1][0] = r[2]; b2_lo[g * 2 + 1][1] = r[3];
                }
                #pragma unroll
                for (int mf = 0; mf < 2; mf++)
                    #pragma unroll
                    for (int nf = 0; nf < 4; nf++) {
                        mma_bf16(acc2[mf][nf], a_hi[mf], b2_hi[nf]);
                        mma_bf16(acc2[mf][nf], a_hi[mf], b2_lo[nf]);
                        mma_bf16(acc2[mf][nf], a_lo[mf], b2_hi[nf]);
                    }
            }
        }
        __syncthreads();
    }

    // --- epilogue
    int gid = lane >> 2, tig = lane & 3;
    #pragma unroll
    for (int mf = 0; mf < 2; mf++) {
        #pragma unroll
        for (int nf = 0; nf < 4; nf++) {
            int c = bn + wn + nf * 8 + tig * 2;
            float bv0 = 0.f, bv1 = 0.f, b2v0 = 0.f, b2v1 = 0.f;
            if constexpr (MODE >= 1) { bv0 = bias1[c]; bv1 = bias1[c + 1]; }
            if constexpr (DUALOUT) { b2v0 = bias2[c]; b2v1 = bias2[c + 1]; }
            #pragma unroll
            for (int half = 0; half < 2; half++) {
                int r = bm + wm + mf * 16 + gid + half * 8;
                if (r >= Nr) continue;
                long base = (long)r * M + c;
                float v0 = acc[mf][nf][half * 2 + 0];
                float v1 = acc[mf][nf][half * 2 + 1];
                float ad0 = 0.f, ad1 = 0.f;
                if constexpr (MODE == 2 || MODE == 3) {
                    ad0 = addm[base]; ad1 = addm[base + 1];
                }
                if constexpr (MODE >= 1) { v0 += bv0; v1 += bv1; }
                if constexpr (MODE == 2) { v0 += ad0; v1 += ad1; }
                if constexpr (MODE >= 1) { v0 = fmaxf(v0, 0.f); v1 = fmaxf(v1, 0.f); }
                if constexpr (MODE == 3) { v0 += ad0; v1 += ad1; }
                if constexpr (OUTBF16) {
                    __nv_bfloat16 h16, l16;
                    bf16_split(v0, h16, l16); Cbhi[base] = h16; Cblo[base] = l16;
                    bf16_split(v1, h16, l16); Cbhi[base + 1] = h16; Cblo[base + 1] = l16;
                } else {
                    C1[base] = v0; C1[base + 1] = v1;
                }
                if constexpr (DUALOUT) {
                    float w0 = fmaxf(acc2[mf][nf][half * 2 + 0] + b2v0, 0.f) + ad0;
                    float w1 = fmaxf(acc2[mf][nf][half * 2 + 1] + b2v1, 0.f) + ad1;
                    C2[base] = w0; C2[base + 1] = w1;
                }
            }
        }
    }
}

// ---------------------------------------------------------------------------
// Stage-3 dual GEMV (xm stride H2P): s0 = xm@W3_0, s1 = xm@W3_1
// ---------------------------------------------------------------------------
__global__ void gemv3_kernel(const float* __restrict__ xm, const float* __restrict__ w0,
                             const float* __restrict__ w1, float* __restrict__ s0,
                             float* __restrict__ s1, int n) {
    int warp = (blockIdx.x * blockDim.x + threadIdx.x) >> 5;
    int lane = threadIdx.x & 31;
    if (warp >= n) return;
    float a0 = 0.f, a1 = 0.f;
    const float* row = xm + (long)warp * H2P;
    for (int f = lane; f < H2; f += 32) {
        float v = row[f];
        a0 += v * w0[f];
        a1 += v * w1[f];
    }
    #pragma unroll
    for (int d = 16; d; d >>= 1) {
        a0 += __shfl_down_sync(0xFFFFFFFFu, a0, d);
        a1 += __shfl_down_sync(0xFFFFFFFFu, a1, d);
    }
    if (lane == 0) { s0[warp] = a0; s1[warp] = a1; }
}

// ---------------------------------------------------------------------------
// Merged pos+neg edge score loss (z stride H2P).
// ---------------------------------------------------------------------------
__global__ void score_kernel(const float* __restrict__ z, const int* __restrict__ ei,
                             const int* __restrict__ nei, int E_, float* __restrict__ accum) {
    int lane = threadIdx.x & 31;
    int warp_global = (blockIdx.x * blockDim.x + threadIdx.x) >> 5;
    int nwarps = (gridDim.x * blockDim.x) >> 5;
    float psum = 0.f, nsum = 0.f;
    for (int t = warp_global; t < 2 * E_; t += nwarps) {
        int which = (t >= E_);
        const int* p = which ? nei : ei;
        int e = which ? t - E_ : t;
        int a = p[e], b = p[e + E_];
        const float4* za = (const float4*)(z + (long)a * H2P);
        const float4* zb = (const float4*)(z + (long)b * H2P);
        float dot = 0.f;
        if (lane < 25) {
            float4 u = za[lane];
            float4 v = zb[lane];
            dot = u.x * v.x + u.y * v.y + u.z * v.z + u.w * v.w;
        }
        #pragma unroll
        for (int dd = 16; dd; dd >>= 1) dot += __shfl_down_sync(0xFFFFFFFFu, dot, dd);
        if (lane == 0) {
            float sig = 1.f / (1.f + expf(-dot));
            if (which) nsum += logf(1.f - sig + 1e-15f);
            else       psum += logf(sig + 1e-15f);
        }
    }
    __shared__ float redp[32], redn[32];
    #pragma unroll
    for (int dd = 16; dd; dd >>= 1) {
        psum += __shfl_down_sync(0xFFFFFFFFu, psum, dd);
        nsum += __shfl_down_sync(0xFFFFFFFFu, nsum, dd);
    }
    if (lane == 0) { redp[threadIdx.x >> 5] = psum; redn[threadIdx.x >> 5] = nsum; }
    __syncthreads();
    if (threadIdx.x < 32) {
        int nw = blockDim.x >> 5;
        float vp = (threadIdx.x < nw) ? redp[threadIdx.x] : 0.f;
        float vn = (threadIdx.x < nw) ? redn[threadIdx.x] : 0.f;
        #pragma unroll
        for (int dd = 16; dd; dd >>= 1) {
            vp += __shfl_down_sync(0xFFFFFFFFu, vp, dd);
            vn += __shfl_down_sync(0xFFFFFFFFu, vn, dd);
        }
        if (threadIdx.x == 0) {
            atomicAdd(&accum[0], vp);
            atomicAdd(&accum[1], vn);
        }
    }
}

__global__ void final_kernel(const float* __restrict__ s0, const float* __restrict__ agg3,
                             const float* __restrict__ b3, const float* __restrict__ accum,
                             const float* __restrict__ c1, const float* __restrict__ c2,
                             float* __restrict__ out, int n, float invE) {
    int i = blockIdx.x * blockDim.x + threadIdx.x;
    if (i < n) out[i] = s0[i] + agg3[i] + b3[0];
    if (i == 0) {
        out[n] = -(accum[0] + accum[1]) * invE;
        out[n + 1] = c1[0];
        out[n + 2] = c2[0];
    }
}

// ---------------------------------------------------------------------------
// Launch
// ---------------------------------------------------------------------------
extern "C" void kernel_launch(void* const* d_in, const int* in_sizes, int n_in,
                              void* d_out, int out_size) {
    const float* x      = (const float*)d_in[0];
    const int*   ei     = (const int*)d_in[1];
    const int*   nei    = (const int*)d_in[2];
    const float* W1_0   = (const float*)d_in[3];
    const float* W1_1   = (const float*)d_in[4];
    const float* b1     = (const float*)d_in[5];
    const float* W2_0   = (const float*)d_in[6];
    const float* W2_1   = (const float*)d_in[7];
    const float* b2     = (const float*)d_in[8];
    const float* W3_0   = (const float*)d_in[9];
    const float* W3_1   = (const float*)d_in[10];
    const float* b3     = (const float*)d_in[11];
    const float* lin1_W = (const float*)d_in[12];
    const float* lin1_b = (const float*)d_in[13];
    const float* lin2_W = (const float*)d_in[14];
    const float* lin2_b = (const float*)d_in[15];
    const float* c1     = (const float*)d_in[16];
    const float* c2     = (const float*)d_in[17];
    float* out = (float*)d_out;

    int n = in_sizes[0] / F_IN;   // 50000
    int e = in_sizes[1] / 2;      // 800000

    Scratch* sp = nullptr;
    cudaGetSymbolAddress((void**)&sp, g_s);

    const int* src = ei;
    const int* dst = ei + e;

    int nb_n = (n + 255) / 256;
    int nb_e = (e + 255) / 256;
    int agg_blocks = (n * 32 + 255) / 256;
    int nb_scan = (n + 1023) / 1024;
    int gy = (n + 127) / 128;

    // Setup + CSR
    zero_kernel<<<nb_n, 256>>>(sp->deg, sp->cnt, sp->accum, n);
    pad_x_kernel<<<(n * FP + 255) / 256, 256>>>(x, sp->xp, n);
    hist_kernel<<<nb_e, 256>>>(src, dst, sp->deg, sp->cnt, e);
    dis_kernel<<<nb_n, 256>>>(sp->deg, sp->dis, n);
    scan1_kernel<<<nb_scan, 1024>>>(sp->cnt, sp->rowptr, sp->bsum, n);
    scan2_kernel<<<1, 32>>>(sp->bsum, sp->boff, sp->rowptr, nb_scan, n);
    scan3_kernel<<<nb_scan, 1024>>>(sp->rowptr, sp->cursor, sp->boff, n);
    fill_kernel<<<nb_e, 256>>>(src, dst, sp->dis, sp->cursor, sp->csr_src, sp->csr_norm, e);

    // Weight/bias conversion (independent, tiny)
    convW1_kernel<<<(KA1 * H1P + 255) / 256, 256>>>(W1_0, W1_1, sp->W1c_hi, sp->W1c_lo);
    convW2_kernel<<<(KH * H2P + 255) / 256, 256>>>(W2_1, sp->W21_hi, sp->W21_lo);
    convW2_kernel<<<(KH * H2P + 255) / 256, 256>>>(W2_0, sp->W20_hi, sp->W20_lo);
    convWT_kernel<<<(FP * H2P + 255) / 256, 256>>>(lin1_W, sp->L1_hi, sp->L1_lo);
    convWT_kernel<<<(FP * H2P + 255) / 256, 256>>>(lin2_W, sp->L2_hi, sp->L2_lo);
    padb_kernel<<<1, H1P>>>(b1, b2, lin1_b, lin2_b, sp->b1p, sp->b2p, sp->l1bp, sp->l2bp);

    // Stage 1: tx1 = Agg(xp) at F=58
    agg_kernel<F_IN, FP><<<agg_blocks, 256>>>(sp->xp, sp->csr_src, sp->csr_norm,
                                              sp->rowptr, sp->tx1, n);
    convA_kernel<<<(n * KA1 + 255) / 256, 256>>>(sp->xp, sp->tx1, sp->xpA_hi, sp->xpA_lo, n);

    // G1: h(bf16 split) = relu([xp|tx1] @ W1cat + b1)   K=128, M=320
    bgemm_kernel<1, false, true><<<dim3(H1P / 64, gy), 256>>>(
        sp->xpA_hi, sp->xpA_lo, KA1, KA1, sp->W1c_hi, sp->W1c_lo, nullptr, nullptr,
        nullptr, sp->b1p, nullptr, nullptr, nullptr, sp->h_hi, sp->h_lo, n, H1P);

    // G2: hW21 = h @ W2_1   K=320, M=128
    bgemm_kernel<0, false, false><<<dim3(H2P / 64, gy), 256>>>(
        sp->h_hi, sp->h_lo, KH, KH, sp->W21_hi, sp->W21_lo, nullptr, nullptr,
        nullptr, nullptr, nullptr, sp->hW21, nullptr, nullptr, nullptr, n, H2P);

    // agg2 = Agg(hW21) at F=100 (stride 128)
    agg_kernel<H2, H2P><<<agg_blocks, 256>>>(sp->hW21, sp->csr_src, sp->csr_norm,
                                             sp->rowptr, sp->agg2, n);

    // G3: x1 = relu(h @ W2_0 + agg2 + b2)
    bgemm_kernel<2, false, false><<<dim3(H2P / 64, gy), 256>>>(
        sp->h_hi, sp->h_lo, KH, KH, sp->W20_hi, sp->W20_lo, nullptr, nullptr,
        sp->agg2, sp->b2p, nullptr, sp->x1, nullptr, nullptr, nullptr, n, H2P);

    // G4: xm = x1 + relu(xp@lin1^T + b); z = x1 + relu(xp@lin2^T + b)   K=64
    bgemm_kernel<3, true, false><<<dim3(H2P / 64, gy), 256>>>(
        sp->xpA_hi, sp->xpA_lo, KA1, FP, sp->L1_hi, sp->L1_lo, sp->L2_hi, sp->L2_lo,
        sp->x1, sp->l1bp, sp->l2bp, sp->xm, sp->z, nullptr, nullptr, n, H2P);

    // Stage 3
    gemv3_kernel<<<agg_blocks, 256>>>(sp->xm, W3_0, W3_1, sp->s0, sp->s1, n);
    agg1_kernel<<<nb_n, 256>>>(sp->s1, sp->csr_src, sp->csr_norm, sp->rowptr, sp->agg3, n);

    // Edge losses
    score_kernel<<<2048, 256>>>(sp->z, ei, nei, e, sp->accum);

    // Final
    final_kernel<<<nb_n, 256>>>(sp->s0, sp->agg3, b3, sp->accum, c1, c2, out, n,
                                1.0f / (float)e);
}

// round 5
// speedup vs baseline: 1.2814x; 1.0350x over previous
#include <cuda_runtime.h>
#include <cuda_bf16.h>
#include <cstdint>
#include <math.h>

#define NN 50000
#define EE 800000
#define F_IN 58
#define FP 64
#define H1 300
#define H2 100
#define H1P 320
#define H2P 128
#define KA1 128   // GEMM1 K: [xp|tx1]
#define KH 320    // padded K for fused stage-2 GEMM
#define M2B 256   // fused stage-2 GEMM N: [W2_1|W2_0]

// ---------------------------------------------------------------------------
// Scratch (device-global, no runtime allocation).
// ---------------------------------------------------------------------------
struct alignas(16) Scratch {
    int   deg[NN];
    int   cnt[NN];
    int   rowptr[NN + 4];
    int   cursor[NN];
    int   csr_src[EE];
    float csr_norm[EE];
    int   bsum[64];
    int   boff[64];
    float dis[NN];
    float xp[NN * FP];
    __nv_bfloat16 xpA_hi[NN * KA1], xpA_lo[NN * KA1]; // [xp|Agg(xp)] split
    __nv_bfloat16 h_hi[NN * KH],   h_lo[NN * KH];
    float hW2b[NN * M2B];     // h @ [W2_1 | W2_0]
    float agg2[NN * H2P];
    float xm[NN * H2P];
    __nv_bfloat16 z_bf[NN * H2P];
    __nv_bfloat16 W1c_hi[KA1 * H1P], W1c_lo[KA1 * H1P];
    __nv_bfloat16 W2c_hi[KH * M2B],  W2c_lo[KH * M2B];
    __nv_bfloat16 L1_hi[FP * H2P],   L1_lo[FP * H2P];
    __nv_bfloat16 L2_hi[FP * H2P],   L2_lo[FP * H2P];
    float b1p[H1P], b2p[H2P], l1bp[H2P], l2bp[H2P];
    float s0[NN], s1[NN];
    float accum[2];
};
__device__ Scratch g_s;

// ---------------------------------------------------------------------------
// PTX helpers
// ---------------------------------------------------------------------------
__device__ __forceinline__ uint32_t smem_u32(const void* p) {
    return (uint32_t)__cvta_generic_to_shared(p);
}
__device__ __forceinline__ void ldm_x4(uint32_t* r, uint32_t addr) {
    asm volatile("ldmatrix.sync.aligned.m8n8.x4.shared.b16 {%0,%1,%2,%3}, [%4];"
                 : "=r"(r[0]), "=r"(r[1]), "=r"(r[2]), "=r"(r[3]) : "r"(addr));
}
__device__ __forceinline__ void ldm_x4_t(uint32_t* r, uint32_t addr) {
    asm volatile("ldmatrix.sync.aligned.m8n8.x4.trans.shared.b16 {%0,%1,%2,%3}, [%4];"
                 : "=r"(r[0]), "=r"(r[1]), "=r"(r[2]), "=r"(r[3]) : "r"(addr));
}
__device__ __forceinline__ void mma_bf16(float* c, const uint32_t* a, const uint32_t* b) {
    asm volatile("mma.sync.aligned.m16n8k16.row.col.f32.bf16.bf16.f32 "
                 "{%0,%1,%2,%3}, {%4,%5,%6,%7}, {%8,%9}, {%0,%1,%2,%3};"
                 : "+f"(c[0]), "+f"(c[1]), "+f"(c[2]), "+f"(c[3])
                 : "r"(a[0]), "r"(a[1]), "r"(a[2]), "r"(a[3]), "r"(b[0]), "r"(b[1]));
}
__device__ __forceinline__ void bf16_split(float v, __nv_bfloat16& hi, __nv_bfloat16& lo) {
    hi = __float2bfloat16(v);
    lo = __float2bfloat16(v - __bfloat162float(hi));
}

// ---------------------------------------------------------------------------
// pad_xc: zero deg/cnt/accum; write xp fp32 + xpA cols [0,64) bf16 split.
// ---------------------------------------------------------------------------
__global__ void pad_xc_kernel(const float* __restrict__ x, int n) {
    int i = blockIdx.x * blockDim.x + threadIdx.x;
    if (i < n) { g_s.deg[i] = 0; g_s.cnt[i] = 0; }
    if (i < 2) g_s.accum[i] = 0.f;
    if (i >= n * FP) return;
    int r = i >> 6, f = i & 63;
    float v = (f < F_IN) ? x[(long)r * F_IN + f] : 0.f;
    g_s.xp[i] = v;
    __nv_bfloat16 h16, l16;
    bf16_split(v, h16, l16);
    long o = (long)r * KA1 + f;
    g_s.xpA_hi[o] = h16;
    g_s.xpA_lo[o] = l16;
}

__global__ void hist_kernel(const int* __restrict__ src, const int* __restrict__ dst,
                            int* deg, int* cnt, int e) {
    int i = blockIdx.x * blockDim.x + threadIdx.x;
    if (i < e) {
        atomicAdd(&deg[src[i]], 1);
        atomicAdd(&cnt[dst[i]], 1);
    }
}

// scan stage 1 (+ dis computation folded in)
__global__ void scan1dis_kernel(const int* __restrict__ cnt, const int* __restrict__ deg,
                                int* __restrict__ rowptr, int* __restrict__ bsum,
                                float* __restrict__ dis, int n) {
    __shared__ int warp_sums[32];
    int tid = threadIdx.x;
    int i = blockIdx.x * 1024 + tid;
    if (i < n) {
        int d = deg[i];
        dis[i] = (d > 0) ? (1.0f / sqrtf((float)d)) : 0.0f;
    }
    int v = (i < n) ? cnt[i] : 0;
    int x = v;
    #pragma unroll
    for (int d = 1; d < 32; d <<= 1) {
        int y = __shfl_up_sync(0xFFFFFFFFu, x, d);
        if ((tid & 31) >= d) x += y;
    }
    if ((tid & 31) == 31) warp_sums[tid >> 5] = x;
    __syncthreads();
    if (tid < 32) {
        int y = warp_sums[tid];
        int zz = y;
        #pragma unroll
        for (int d = 1; d < 32; d <<= 1) {
            int w = __shfl_up_sync(0xFFFFFFFFu, zz, d);
            if (tid >= d) zz += w;
        }
        warp_sums[tid] = zz - y;
    }
    __syncthreads();
    int incl = x + warp_sums[tid >> 5];
    if (i < n) rowptr[i] = incl - v;
    if (tid == 1023) bsum[blockIdx.x] = incl;
}

__global__ void scan2_kernel(const int* __restrict__ bsum, int* __restrict__ boff,
                             int* __restrict__ rowptr, int nb, int n) {
    if (threadIdx.x == 0 && blockIdx.x == 0) {
        int run = 0;
        for (int b = 0; b < nb; b++) { boff[b] = run; run += bsum[b]; }
        rowptr[n] = run;
    }
}

__global__ void scan3_kernel(int* __restrict__ rowptr, int* __restrict__ cursor,
                             const int* __restrict__ boff, int n) {
    int i = blockIdx.x * 1024 + threadIdx.x;
    if (i < n) {
        int v = rowptr[i] + boff[blockIdx.x];
        rowptr[i] = v;
        cursor[i] = v;
    }
}

__global__ void fill_kernel(const int* __restrict__ src, const int* __restrict__ dst,
                            const float* __restrict__ dis, int* __restrict__ cursor,
                            int* __restrict__ csr_src, float* __restrict__ csr_norm, int e) {
    int i = blockIdx.x * blockDim.x + threadIdx.x;
    if (i < e) {
        int s = src[i], d = dst[i];
        int p = atomicAdd(&cursor[d], 1);
        csr_src[p] = s;
        csr_norm[p] = -(dis[s] * dis[d]);
    }
}

// ---------------------------------------------------------------------------
// All weight/bias conversions in ONE kernel.
// ---------------------------------------------------------------------------
#define CN1 (KA1 * H1P)
#define CN2 (KH * M2B)
#define CN3 (FP * H2P)
#define CTOT (CN1 + CN2 + 2 * CN3 + H1P + 3 * H2P)
__global__ void convall_kernel(const float* __restrict__ W10, const float* __restrict__ W11,
                               const float* __restrict__ W20, const float* __restrict__ W21,
                               const float* __restrict__ l1W, const float* __restrict__ l2W,
                               const float* __restrict__ b1, const float* __restrict__ b2,
                               const float* __restrict__ l1b, const float* __restrict__ l2b) {
    int i = blockIdx.x * blockDim.x + threadIdx.x;
    if (i < CN1) {
        int k = i / H1P, m = i % H1P;
        float v = 0.f;
        if (m < H1) {
            if (k < F_IN) v = W10[k * H1 + m];
            else if (k >= FP && k < FP + F_IN) v = W11[(k - FP) * H1 + m];
        }
        __nv_bfloat16 h16, l16; bf16_split(v, h16, l16);
        g_s.W1c_hi[i] = h16; g_s.W1c_lo[i] = l16;
        return;
    }
    i -= CN1;
    if (i < CN2) {
        int k = i / M2B, m = i % M2B;
        float v = 0.f;
        if (k < H1) {
            if (m < H2P) { if (m < H2) v = W21[k * H2 + m]; }
            else { int mm = m - H2P; if (mm < H2) v = W20[k * H2 + mm]; }
        }
        __nv_bfloat16 h16, l16; bf16_split(v, h16, l16);
        g_s.W2c_hi[i] = h16; g_s.W2c_lo[i] = l16;
        return;
    }
    i -= CN2;
    if (i < CN3) {
        int k = i >> 7, m = i & 127;
        float v = (k < F_IN && m < H2) ? l1W[m * F_IN + k] : 0.f;
        __nv_bfloat16 h16, l16; bf16_split(v, h16, l16);
        g_s.L1_hi[i] = h16; g_s.L1_lo[i] = l16;
        return;
    }
    i -= CN3;
    if (i < CN3) {
        int k = i >> 7, m = i & 127;
        float v = (k < F_IN && m < H2) ? l2W[m * F_IN + k] : 0.f;
        __nv_bfloat16 h16, l16; bf16_split(v, h16, l16);
        g_s.L2_hi[i] = h16; g_s.L2_lo[i] = l16;
        return;
    }
    i -= CN3;
    if (i < H1P) { g_s.b1p[i] = (i < H1) ? b1[i] : 0.f; return; }
    i -= H1P;
    if (i < H2P) { g_s.b2p[i] = (i < H2) ? b2[i] : 0.f; return; }
    i -= H2P;
    if (i < H2P) { g_s.l1bp[i] = (i < H2) ? l1b[i] : 0.f; return; }
    i -= H2P;
    if (i < H2P) { g_s.l2bp[i] = (i < H2) ? l2b[i] : 0.f; return; }
}

// ---------------------------------------------------------------------------
// Stage-1 aggregation writing bf16 split directly into xpA cols [64,128).
// ---------------------------------------------------------------------------
__global__ void aggx_kernel(const float* __restrict__ val, const int* __restrict__ csr_src,
                            const float* __restrict__ csr_norm, const int* __restrict__ rowptr,
                            __nv_bfloat16* __restrict__ hi, __nv_bfloat16* __restrict__ lo,
                            int n) {
    int node = (blockIdx.x * blockDim.x + threadIdx.x) >> 5;
    int lane = threadIdx.x & 31;
    if (node >= n) return;
    int beg = rowptr[node], end = rowptr[node + 1];
    float acc0 = 0.f, acc1 = 0.f;
    for (int j = beg; j < end; j++) {
        int s = csr_src[j];
        float w = csr_norm[j];
        const float* vrow = val + (long)s * FP;
        acc0 += vrow[lane] * w;
        if (lane + 32 < F_IN) acc1 += vrow[lane + 32] * w;
    }
    long o = (long)node * KA1 + FP + lane;
    __nv_bfloat16 h16, l16;
    bf16_split(acc0, h16, l16); hi[o] = h16; lo[o] = l16;
    bf16_split(acc1, h16, l16); hi[o + 32] = h16; lo[o + 32] = l16;
}

// ---------------------------------------------------------------------------
// Aggregation: warp per node; F valid cols; SV = val row stride; SO = out stride.
// ---------------------------------------------------------------------------
template <int F, int SV, int SO>
__global__ void agg_kernel(const float* __restrict__ val, const int* __restrict__ csr_src,
                           const float* __restrict__ csr_norm, const int* __restrict__ rowptr,
                           float* __restrict__ out, int n) {
    int node = (blockIdx.x * blockDim.x + threadIdx.x) >> 5;
    int lane = threadIdx.x & 31;
    if (node >= n) return;
    int beg = rowptr[node], end = rowptr[node + 1];
    constexpr int R = (SO + 31) / 32;
    float acc[R];
    #pragma unroll
    for (int r = 0; r < R; r++) acc[r] = 0.f;
    for (int j = beg; j < end; j++) {
        int s = csr_src[j];
        float w = csr_norm[j];
        const float* vrow = val + (long)s * SV;
        #pragma unroll
        for (int r = 0; r < R; r++) {
            int f = lane + r * 32;
            if (f < F) acc[r] += vrow[f] * w;
        }
    }
    float* orow = out + (long)node * SO;
    #pragma unroll
    for (int r = 0; r < R; r++) {
        int f = lane + r * 32;
        if (f < SO) orow[f] = acc[r];
    }
}

// ---------------------------------------------------------------------------
// Split-bf16 tensor-core GEMM. BM=128, BN=64, BK=32, 256 thr, 8 warps 32x32.
// MODE 0: C1 = acc
// MODE 1: C1 = relu(acc + bias1)                       (OUTBF16 writes hi/lo)
// MODE 4: x1 = relu(addm[r*256+128+c] + addm2 + bias3)
//         C1 = x1 + relu(acc1 + bias1)  [xm fp32]
//         Cbhi = bf16(x1 + relu(acc2 + bias2))  [z]    (requires DUALOUT)
// ---------------------------------------------------------------------------
template <int MODE, bool DUALOUT, bool OUTBF16>
__global__ __launch_bounds__(256)
void bgemm_kernel(const __nv_bfloat16* __restrict__ Ahi, const __nv_bfloat16* __restrict__ Alo,
                  int lda, int K,
                  const __nv_bfloat16* __restrict__ B1hi, const __nv_bfloat16* __restrict__ B1lo,
                  const __nv_bfloat16* __restrict__ B2hi, const __nv_bfloat16* __restrict__ B2lo,
                  const float* __restrict__ addm, const float* __restrict__ addm2,
                  const float* __restrict__ bias1, const float* __restrict__ bias2,
                  const float* __restrict__ bias3,
                  float* __restrict__ C1,
                  __nv_bfloat16* __restrict__ Cbhi, __nv_bfloat16* __restrict__ Cblo,
                  int Nr, int M) {
    __shared__ __align__(16) __nv_bfloat16 As_hi[128][40];
    __shared__ __align__(16) __nv_bfloat16 As_lo[128][40];
    __shared__ __align__(16) __nv_bfloat16 Bs_hi[32][72];
    __shared__ __align__(16) __nv_bfloat16 Bs_lo[32][72];
    __shared__ __align__(16) __nv_bfloat16 Bs2_hi[32][72];
    __shared__ __align__(16) __nv_bfloat16 Bs2_lo[32][72];

    int tid = threadIdx.x;
    int bm = blockIdx.y * 128, bn = blockIdx.x * 64;
    int lane = tid & 31, wid = tid >> 5;
    int wm = (wid >> 1) * 32, wn = (wid & 1) * 32;

    float acc[2][4][4];
    float acc2[2][4][4];
    #pragma unroll
    for (int mf = 0; mf < 2; mf++)
        #pragma unroll
        for (int nf = 0; nf < 4; nf++)
            #pragma unroll
            for (int q = 0; q < 4; q++) { acc[mf][nf][q] = 0.f; acc2[mf][nf][q] = 0.f; }

    for (int k0 = 0; k0 < K; k0 += 32) {
        #pragma unroll
        for (int i = 0; i < 2; i++) {
            int c = tid * 2 + i;
            int row = c >> 2, seg = c & 3;
            int gr = bm + row;
            uint4 vh = make_uint4(0, 0, 0, 0), vl = vh;
            if (gr < Nr) {
                long off = (long)gr * lda + k0 + seg * 8;
                vh = *reinterpret_cast<const uint4*>(Ahi + off);
                vl = *reinterpret_cast<const uint4*>(Alo + off);
            }
            *reinterpret_cast<uint4*>(&As_hi[row][seg * 8]) = vh;
            *reinterpret_cast<uint4*>(&As_lo[row][seg * 8]) = vl;
        }
        {
            int row = tid >> 3, seg = tid & 7;
            long off = (long)(k0 + row) * M + bn + seg * 8;
            *reinterpret_cast<uint4*>(&Bs_hi[row][seg * 8]) =
                *reinterpret_cast<const uint4*>(B1hi + off);
            *reinterpret_cast<uint4*>(&Bs_lo[row][seg * 8]) =
                *reinterpret_cast<const uint4*>(B1lo + off);
            if constexpr (DUALOUT) {
                *reinterpret_cast<uint4*>(&Bs2_hi[row][seg * 8]) =
                    *reinterpret_cast<const uint4*>(B2hi + off);
                *reinterpret_cast<uint4*>(&Bs2_lo[row][seg * 8]) =
                    *reinterpret_cast<const uint4*>(B2lo + off);
            }
        }
        __syncthreads();

        #pragma unroll
        for (int s = 0; s < 32; s += 16) {
            uint32_t a_hi[2][4], a_lo[2][4];
            #pragma unroll
            for (int mf = 0; mf < 2; mf++) {
                int row = wm + mf * 16 + (lane & 15);
                int col = s + ((lane >> 4) << 3);
                ldm_x4(a_hi[mf], smem_u32(&As_hi[row][col]));
                ldm_x4(a_lo[mf], smem_u32(&As_lo[row][col]));
            }
            int kr = s + (lane & 7) + (lane & 8);
            int nshift = (lane >> 4) << 3;
            uint32_t b_hi[4][2], b_lo[4][2];
            #pragma unroll
            for (int g = 0; g < 2; g++) {
                int nc = wn + g * 16 + nshift;
                uint32_t r[4];
                ldm_x4_t(r, smem_u32(&Bs_hi[kr][nc]));
                b_hi[g * 2][0] = r[0]; b_hi[g * 2][1] = r[1];
                b_hi[g * 2 + 1][0] = r[2]; b_hi[g * 2 + 1][1] = r[3];
                ldm_x4_t(r, smem_u32(&Bs_lo[kr][nc]));
                b_lo[g * 2][0] = r[0]; b_lo[g * 2][1] = r[1];
                b_lo[g * 2 + 1][0] = r[2]; b_lo[g * 2 + 1][1] = r[3];
            }
            #pragma unroll
            for (int mf = 0; mf < 2; mf++)
                #pragma unroll
                for (int nf = 0; nf < 4; nf++) {
                    mma_bf16(acc[mf][nf], a_hi[mf], b_hi[nf]);
                    mma_bf16(acc[mf][nf], a_hi[mf], b_lo[nf]);
                    mma_bf16(acc[mf][nf], a_lo[mf], b_hi[nf]);
                }
            if constexpr (DUALOUT) {
                uint32_t b2_hi[4][2], b2_lo[4][2];
                #pragma unroll
                for (int g = 0; g < 2; g++) {
                    int nc = wn + g * 16 + nshift;
                    uint32_t r[4];
                    ldm_x4_t(r, smem_u32(&Bs2_hi[kr][nc]));
                    b2_hi[g * 2][0] = r[0]; b2_hi[g * 2][1] = r[1];
                    b2_hi[g * 2 + 1][0] = r[2]; b2_hi[g * 2 + 1][1] = r[3];
                    ldm_x4_t(r, smem_u32(&Bs2_lo[kr][nc]));
                    b2_lo[g * 2][0] = r[0]; b2_lo[g * 2][1] = r[1];
                    b2_lo[g * 2 + 1][0] = r[2]; b2_lo[g * 2 + 1][1] = r[3];
                }
                #pragma unroll
                for (int mf = 0; mf < 2; mf++)
                    #pragma unroll
                    for (int nf = 0; nf < 4; nf++) {
                        mma_bf16(acc2[mf][nf], a_hi[mf], b2_hi[nf]);
                        mma_bf16(acc2[mf][nf], a_hi[mf], b2_lo[nf]);
                        mma_bf16(acc2[mf][nf], a_lo[mf], b2_hi[nf]);
                    }
            }
        }
        __syncthreads();
    }

    // --- epilogue
    int gid = lane >> 2, tig = lane & 3;
    #pragma unroll
    for (int mf = 0; mf < 2; mf++) {
        #pragma unroll
        for (int nf = 0; nf < 4; nf++) {
            int c = bn + wn + nf * 8 + tig * 2;
            float bv0 = 0.f, bv1 = 0.f, b2v0 = 0.f, b2v1 = 0.f;
            if constexpr (MODE >= 1) { bv0 = bias1[c]; bv1 = bias1[c + 1]; }
            if constexpr (DUALOUT) { b2v0 = bias2[c]; b2v1 = bias2[c + 1]; }
            #pragma unroll
            for (int half = 0; half < 2; half++) {
                int r = bm + wm + mf * 16 + gid + half * 8;
                if (r >= Nr) continue;
                long base = (long)r * M + c;
                float v0 = acc[mf][nf][half * 2 + 0];
                float v1 = acc[mf][nf][half * 2 + 1];
                if constexpr (MODE == 4) {
                    long pbase = (long)r * M2B + H2P + c;
                    float x10 = fmaxf(addm[pbase]     + addm2[base]     + bias3[c],     0.f);
                    float x11 = fmaxf(addm[pbase + 1] + addm2[base + 1] + bias3[c + 1], 0.f);
                    C1[base]     = x10 + fmaxf(v0 + bv0, 0.f);
                    C1[base + 1] = x11 + fmaxf(v1 + bv1, 0.f);
                    float z0 = x10 + fmaxf(acc2[mf][nf][half * 2 + 0] + b2v0, 0.f);
                    float z1 = x11 + fmaxf(acc2[mf][nf][half * 2 + 1] + b2v1, 0.f);
                    Cbhi[base]     = __float2bfloat16(z0);
                    Cbhi[base + 1] = __float2bfloat16(z1);
                } else {
                    if constexpr (MODE >= 1) {
                        v0 = fmaxf(v0 + bv0, 0.f);
                        v1 = fmaxf(v1 + bv1, 0.f);
                    }
                    if constexpr (OUTBF16) {
                        __nv_bfloat16 h16, l16;
                        bf16_split(v0, h16, l16); Cbhi[base] = h16; Cblo[base] = l16;
                        bf16_split(v1, h16, l16); Cbhi[base + 1] = h16; Cblo[base + 1] = l16;
                    } else {
                        C1[base] = v0; C1[base + 1] = v1;
                    }
                }
            }
        }
    }
}

// ---------------------------------------------------------------------------
// Stage-3 dual GEMV: s0 = xm@W3_0, s1 = xm@W3_1
// ---------------------------------------------------------------------------
__global__ void gemv3_kernel(const float* __restrict__ xm, const float* __restrict__ w0,
                             const float* __restrict__ w1, float* __restrict__ s0,
                             float* __restrict__ s1, int n) {
    int warp = (blockIdx.x * blockDim.x + threadIdx.x) >> 5;
    int lane = threadIdx.x & 31;
    if (warp >= n) return;
    float a0 = 0.f, a1 = 0.f;
    const float* row = xm + (long)warp * H2P;
    for (int f = lane; f < H2; f += 32) {
        float v = row[f];
        a0 += v * w0[f];
        a1 += v * w1[f];
    }
    #pragma unroll
    for (int d = 16; d; d >>= 1) {
        a0 += __shfl_down_sync(0xFFFFFFFFu, a0, d);
        a1 += __shfl_down_sync(0xFFFFFFFFu, a1, d);
    }
    if (lane == 0) { s0[warp] = a0; s1[warp] = a1; }
}

// ---------------------------------------------------------------------------
// Merged pos+neg edge score loss over bf16 z (stride H2P).
// ---------------------------------------------------------------------------
__global__ void score_kernel(const __nv_bfloat16* __restrict__ zb, const int* __restrict__ ei,
                             const int* __restrict__ nei, int E_, float* __restrict__ accum) {
    int lane = threadIdx.x & 31;
    int warp_global = (blockIdx.x * blockDim.x + threadIdx.x) >> 5;
    int nwarps = (gridDim.x * blockDim.x) >> 5;
    float psum = 0.f, nsum = 0.f;
    for (int t = warp_global; t < 2 * E_; t += nwarps) {
        int which = (t >= E_);
        const int* p = which ? nei : ei;
        int e = which ? t - E_ : t;
        int a = p[e], b = p[e + E_];
        float dot = 0.f;
        if (lane < 25) {
            uint2 ua = reinterpret_cast<const uint2*>(zb + (long)a * H2P)[lane];
            uint2 ub = reinterpret_cast<const uint2*>(zb + (long)b * H2P)[lane];
            float2 a0 = __bfloat1622float2(*reinterpret_cast<__nv_bfloat162*>(&ua.x));
            float2 a1 = __bfloat1622float2(*reinterpret_cast<__nv_bfloat162*>(&ua.y));
            float2 b0 = __bfloat1622float2(*reinterpret_cast<__nv_bfloat162*>(&ub.x));
            float2 b1 = __bfloat1622float2(*reinterpret_cast<__nv_bfloat162*>(&ub.y));
            dot = a0.x * b0.x + a0.y * b0.y + a1.x * b1.x + a1.y * b1.y;
        }
        #pragma unroll
        for (int dd = 16; dd; dd >>= 1) dot += __shfl_down_sync(0xFFFFFFFFu, dot, dd);
        if (lane == 0) {
            float sig = 1.f / (1.f + expf(-dot));
            if (which) nsum += logf(1.f - sig + 1e-15f);
            else       psum += logf(sig + 1e-15f);
        }
    }
    __shared__ float redp[32], redn[32];
    #pragma unroll
    for (int dd = 16; dd; dd >>= 1) {
        psum += __shfl_down_sync(0xFFFFFFFFu, psum, dd);
        nsum += __shfl_down_sync(0xFFFFFFFFu, nsum, dd);
    }
    if (lane == 0) { redp[threadIdx.x >> 5] = psum; redn[threadIdx.x >> 5] = nsum; }
    __syncthreads();
    if (threadIdx.x < 32) {
        int nw = blockDim.x >> 5;
        float vp = (threadIdx.x < nw) ? redp[threadIdx.x] : 0.f;
        float vn = (threadIdx.x < nw) ? redn[threadIdx.x] : 0.f;
        #pragma unroll
        for (int dd = 16; dd; dd >>= 1) {
            vp += __shfl_down_sync(0xFFFFFFFFu, vp, dd);
            vn += __shfl_down_sync(0xFFFFFFFFu, vn, dd);
        }
        if (threadIdx.x == 0) {
            atomicAdd(&accum[0], vp);
            atomicAdd(&accum[1], vn);
        }
    }
}

// ---------------------------------------------------------------------------
// Final: out[i] = s0[i] + Agg(s1)[i] + b3 (stage-3 F=1 aggregation fused in).
// ---------------------------------------------------------------------------
__global__ void agg1final_kernel(const float* __restrict__ s0, const float* __restrict__ s1,
                                 const int* __restrict__ csr_src, const float* __restrict__ csr_norm,
                                 const int* __restrict__ rowptr, const float* __restrict__ b3,
                                 const float* __restrict__ accum, const float* __restrict__ c1,
                                 const float* __restrict__ c2, float* __restrict__ out,
                                 int n, float invE) {
    int i = blockIdx.x * blockDim.x + threadIdx.x;
    if (i < n) {
        float a = 0.f;
        int end = rowptr[i + 1];
        for (int j = rowptr[i]; j < end; j++)
            a += s1[csr_src[j]] * csr_norm[j];
        out[i] = s0[i] + a + b3[0];
    }
    if (i == 0) {
        out[n] = -(accum[0] + accum[1]) * invE;
        out[n + 1] = c1[0];
        out[n + 2] = c2[0];
    }
}

// ---------------------------------------------------------------------------
// Launch
// ---------------------------------------------------------------------------
extern "C" void kernel_launch(void* const* d_in, const int* in_sizes, int n_in,
                              void* d_out, int out_size) {
    const float* x      = (const float*)d_in[0];
    const int*   ei     = (const int*)d_in[1];
    const int*   nei    = (const int*)d_in[2];
    const float* W1_0   = (const float*)d_in[3];
    const float* W1_1   = (const float*)d_in[4];
    const float* b1     = (const float*)d_in[5];
    const float* W2_0   = (const float*)d_in[6];
    const float* W2_1   = (const float*)d_in[7];
    const float* b2     = (const float*)d_in[8];
    const float* W3_0   = (const float*)d_in[9];
    const float* W3_1   = (const float*)d_in[10];
    const float* b3     = (const float*)d_in[11];
    const float* lin1_W = (const float*)d_in[12];
    const float* lin1_b = (const float*)d_in[13];
    const float* lin2_W = (const float*)d_in[14];
    const float* lin2_b = (const float*)d_in[15];
    const float* c1     = (const float*)d_in[16];
    const float* c2     = (const float*)d_in[17];
    float* out = (float*)d_out;

    int n = in_sizes[0] / F_IN;   // 50000
    int e = in_sizes[1] / 2;      // 800000

    Scratch* sp = nullptr;
    cudaGetSymbolAddress((void**)&sp, g_s);

    const int* src = ei;
    const int* dst = ei + e;

    int nb_n = (n + 255) / 256;
    int nb_e = (e + 255) / 256;
    int agg_blocks = (n * 32 + 255) / 256;
    int nb_scan = (n + 1023) / 1024;
    int gy = (n + 127) / 128;

    // Setup + CSR
    pad_xc_kernel<<<(n * FP + 255) / 256, 256>>>(x, n);
    hist_kernel<<<nb_e, 256>>>(src, dst, sp->deg, sp->cnt, e);
    scan1dis_kernel<<<nb_scan, 1024>>>(sp->cnt, sp->deg, sp->rowptr, sp->bsum, sp->dis, n);
    scan2_kernel<<<1, 32>>>(sp->bsum, sp->boff, sp->rowptr, nb_scan, n);
    scan3_kernel<<<nb_scan, 1024>>>(sp->rowptr, sp->cursor, sp->boff, n);
    fill_kernel<<<nb_e, 256>>>(src, dst, sp->dis, sp->cursor, sp->csr_src, sp->csr_norm, e);

    // Weight conversion (single kernel)
    convall_kernel<<<(CTOT + 255) / 256, 256>>>(W1_0, W1_1, W2_0, W2_1, lin1_W, lin2_W,
                                                b1, b2, lin1_b, lin2_b);

    // Stage 1 aggregation -> xpA cols [64,128)
    aggx_kernel<<<agg_blocks, 256>>>(sp->xp, sp->csr_src, sp->csr_norm, sp->rowptr,
                                     sp->xpA_hi, sp->xpA_lo, n);

    // G1: h(bf16 split) = relu([xp|tx1] @ W1cat + b1)   K=128, M=320
    bgemm_kernel<1, false, true><<<dim3(H1P / 64, gy), 256>>>(
        sp->xpA_hi, sp->xpA_lo, KA1, KA1, sp->W1c_hi, sp->W1c_lo, nullptr, nullptr,
        nullptr, nullptr, sp->b1p, nullptr, nullptr, nullptr, sp->h_hi, sp->h_lo, n, H1P);

    // G2': hW2b = h @ [W2_1 | W2_0]   K=320, M=256
    bgemm_kernel<0, false, false><<<dim3(M2B / 64, gy), 256>>>(
        sp->h_hi, sp->h_lo, KH, KH, sp->W2c_hi, sp->W2c_lo, nullptr, nullptr,
        nullptr, nullptr, nullptr, nullptr, nullptr, sp->hW2b, nullptr, nullptr, n, M2B);

    // agg2 = Agg(hW2b[:, 0:100])
    agg_kernel<H2, M2B, H2P><<<agg_blocks, 256>>>(sp->hW2b, sp->csr_src, sp->csr_norm,
                                                  sp->rowptr, sp->agg2, n);

    // G4 (MODE 4): xm = x1 + relu(xp@L1+b); z_bf = bf16(x1 + relu(xp@L2+b));
    //              x1 = relu(hW2b[:,128:] + agg2 + b2) computed in epilogue
    bgemm_kernel<4, true, false><<<dim3(H2P / 64, gy), 256>>>(
        sp->xpA_hi, sp->xpA_lo, KA1, FP, sp->L1_hi, sp->L1_lo, sp->L2_hi, sp->L2_lo,
        sp->hW2b, sp->agg2, sp->l1bp, sp->l2bp, sp->b2p, sp->xm, sp->z_bf, nullptr, n, H2P);

    // Stage 3 + losses
    gemv3_kernel<<<agg_blocks, 256>>>(sp->xm, W3_0, W3_1, sp->s0, sp->s1, n);
    score_kernel<<<2048, 256>>>(sp->z_bf, ei, nei, e, sp->accum);
    agg1final_kernel<<<nb_n, 256>>>(sp->s0, sp->s1, sp->csr_src, sp->csr_norm, sp->rowptr,
                                    b3, sp->accum, c1, c2, out, n, 1.0f / (float)e);
}

// round 7
// speedup vs baseline: 1.6332x; 1.2745x over previous
#include <cuda_runtime.h>
#include <cuda_fp16.h>
#include <cstdint>
#include <math.h>

#define NN 50000
#define EE 800000
#define F_IN 58
#define FP 64
#define H1 300
#define H2 100
#define H1P 320
#define H2P 128
#define KA1 128   // GEMM1 K: [xp|tx1]
#define KH 320    // padded K for fused stage-2 GEMM
#define M2B 256   // fused stage-2 GEMM N: [W2_1|W2_0]

// ---------------------------------------------------------------------------
// Scratch (device-global, no runtime allocation).
// ---------------------------------------------------------------------------
struct alignas(16) Scratch {
    int   deg[NN];
    int   cnt[NN];
    int   rowptr[NN + 4];
    int   cursor[NN];
    int   csr_src[EE];
    float csr_norm[EE];
    int   bsum[64];
    int   boff[64];
    float dis[NN];
    float xp[NN * FP];
    __half xpA[NN * KA1];   // [xp | Agg(xp)] fp16
    __half h_fp[NN * KH];   // relu(cheb1) fp16, [N,320]
    float hW2b[NN * M2B];   // h @ [W2_1 | W2_0]
    float agg2[NN * H2P];
    float xm[NN * H2P];
    __half z_fp[NN * H2P];
    __half W1c[KA1 * H1P];  // [128,320]
    __half W2c[KH * M2B];   // [320,256]
    __half L1[FP * H2P];    // [64,128]
    __half L2[FP * H2P];
    float b1p[H1P], b2p[H2P], l1bp[H2P], l2bp[H2P];
    float s0[NN], s1[NN];
    float accum[2];
};
__device__ Scratch g_s;

// ---------------------------------------------------------------------------
// PTX helpers
// ---------------------------------------------------------------------------
__device__ __forceinline__ uint32_t smem_u32(const void* p) {
    return (uint32_t)__cvta_generic_to_shared(p);
}
__device__ __forceinline__ void ldm_x4(uint32_t* r, uint32_t addr) {
    asm volatile("ldmatrix.sync.aligned.m8n8.x4.shared.b16 {%0,%1,%2,%3}, [%4];"
                 : "=r"(r[0]), "=r"(r[1]), "=r"(r[2]), "=r"(r[3]) : "r"(addr));
}
__device__ __forceinline__ void ldm_x4_t(uint32_t* r, uint32_t addr) {
    asm volatile("ldmatrix.sync.aligned.m8n8.x4.trans.shared.b16 {%0,%1,%2,%3}, [%4];"
                 : "=r"(r[0]), "=r"(r[1]), "=r"(r[2]), "=r"(r[3]) : "r"(addr));
}
__device__ __forceinline__ void mma_fp16(float* c, const uint32_t* a, const uint32_t* b) {
    asm volatile("mma.sync.aligned.m16n8k16.row.col.f32.f16.f16.f32 "
                 "{%0,%1,%2,%3}, {%4,%5,%6,%7}, {%8,%9}, {%0,%1,%2,%3};"
                 : "+f"(c[0]), "+f"(c[1]), "+f"(c[2]), "+f"(c[3])
                 : "r"(a[0]), "r"(a[1]), "r"(a[2]), "r"(a[3]), "r"(b[0]), "r"(b[1]));
}

// ---------------------------------------------------------------------------
// pad_xc: zero deg/cnt/accum; write xp fp32 + xpA cols [0,64) fp16.
// ---------------------------------------------------------------------------
__global__ void pad_xc_kernel(const float* __restrict__ x, int n) {
    int i = blockIdx.x * blockDim.x + threadIdx.x;
    if (i < n) { g_s.deg[i] = 0; g_s.cnt[i] = 0; }
    if (i < 2) g_s.accum[i] = 0.f;
    if (i >= n * FP) return;
    int r = i >> 6, f = i & 63;
    float v = (f < F_IN) ? x[(long)r * F_IN + f] : 0.f;
    g_s.xp[i] = v;
    g_s.xpA[(long)r * KA1 + f] = __float2half(v);
}

__global__ void hist_kernel(const int* __restrict__ src, const int* __restrict__ dst,
                            int* deg, int* cnt, int e) {
    int i = blockIdx.x * blockDim.x + threadIdx.x;
    if (i < e) {
        atomicAdd(&deg[src[i]], 1);
        atomicAdd(&cnt[dst[i]], 1);
    }
}

// scan stage 1 (+ dis folded in)
__global__ void scan1dis_kernel(const int* __restrict__ cnt, const int* __restrict__ deg,
                                int* __restrict__ rowptr, int* __restrict__ bsum,
                                float* __restrict__ dis, int n) {
    __shared__ int warp_sums[32];
    int tid = threadIdx.x;
    int i = blockIdx.x * 1024 + tid;
    if (i < n) {
        int d = deg[i];
        dis[i] = (d > 0) ? (1.0f / sqrtf((float)d)) : 0.0f;
    }
    int v = (i < n) ? cnt[i] : 0;
    int x = v;
    #pragma unroll
    for (int d = 1; d < 32; d <<= 1) {
        int y = __shfl_up_sync(0xFFFFFFFFu, x, d);
        if ((tid & 31) >= d) x += y;
    }
    if ((tid & 31) == 31) warp_sums[tid >> 5] = x;
    __syncthreads();
    if (tid < 32) {
        int y = warp_sums[tid];
        int zz = y;
        #pragma unroll
        for (int d = 1; d < 32; d <<= 1) {
            int w = __shfl_up_sync(0xFFFFFFFFu, zz, d);
            if (tid >= d) zz += w;
        }
        warp_sums[tid] = zz - y;
    }
    __syncthreads();
    int incl = x + warp_sums[tid >> 5];
    if (i < n) rowptr[i] = incl - v;
    if (tid == 1023) bsum[blockIdx.x] = incl;
}

__global__ void scan2_kernel(const int* __restrict__ bsum, int* __restrict__ boff,
                             int* __restrict__ rowptr, int nb, int n) {
    if (threadIdx.x == 0 && blockIdx.x == 0) {
        int run = 0;
        for (int b = 0; b < nb; b++) { boff[b] = run; run += bsum[b]; }
        rowptr[n] = run;
    }
}

__global__ void scan3_kernel(int* __restrict__ rowptr, int* __restrict__ cursor,
                             const int* __restrict__ boff, int n) {
    int i = blockIdx.x * 1024 + threadIdx.x;
    if (i < n) {
        int v = rowptr[i] + boff[blockIdx.x];
        rowptr[i] = v;
        cursor[i] = v;
    }
}

__global__ void fill_kernel(const int* __restrict__ src, const int* __restrict__ dst,
                            const float* __restrict__ dis, int* __restrict__ cursor,
                            int* __restrict__ csr_src, float* __restrict__ csr_norm, int e) {
    int i = blockIdx.x * blockDim.x + threadIdx.x;
    if (i < e) {
        int s = src[i], d = dst[i];
        int p = atomicAdd(&cursor[d], 1);
        csr_src[p] = s;
        csr_norm[p] = -(dis[s] * dis[d]);
    }
}

// ---------------------------------------------------------------------------
// All weight/bias conversions in ONE kernel (fp16).
// ---------------------------------------------------------------------------
#define CN1 (KA1 * H1P)
#define CN2 (KH * M2B)
#define CN3 (FP * H2P)
#define CTOT (CN1 + CN2 + 2 * CN3 + H1P + 3 * H2P)
__global__ void convall_kernel(const float* __restrict__ W10, const float* __restrict__ W11,
                               const float* __restrict__ W20, const float* __restrict__ W21,
                               const float* __restrict__ l1W, const float* __restrict__ l2W,
                               const float* __restrict__ b1, const float* __restrict__ b2,
                               const float* __restrict__ l1b, const float* __restrict__ l2b) {
    int i = blockIdx.x * blockDim.x + threadIdx.x;
    if (i < CN1) {
        int k = i / H1P, m = i % H1P;
        float v = 0.f;
        if (m < H1) {
            if (k < F_IN) v = W10[k * H1 + m];
            else if (k >= FP && k < FP + F_IN) v = W11[(k - FP) * H1 + m];
        }
        g_s.W1c[i] = __float2half(v);
        return;
    }
    i -= CN1;
    if (i < CN2) {
        int k = i / M2B, m = i % M2B;
        float v = 0.f;
        if (k < H1) {
            if (m < H2P) { if (m < H2) v = W21[k * H2 + m]; }
            else { int mm = m - H2P; if (mm < H2) v = W20[k * H2 + mm]; }
        }
        g_s.W2c[i] = __float2half(v);
        return;
    }
    i -= CN2;
    if (i < CN3) {
        int k = i >> 7, m = i & 127;
        float v = (k < F_IN && m < H2) ? l1W[m * F_IN + k] : 0.f;
        g_s.L1[i] = __float2half(v);
        return;
    }
    i -= CN3;
    if (i < CN3) {
        int k = i >> 7, m = i & 127;
        float v = (k < F_IN && m < H2) ? l2W[m * F_IN + k] : 0.f;
        g_s.L2[i] = __float2half(v);
        return;
    }
    i -= CN3;
    if (i < H1P) { g_s.b1p[i] = (i < H1) ? b1[i] : 0.f; return; }
    i -= H1P;
    if (i < H2P) { g_s.b2p[i] = (i < H2) ? b2[i] : 0.f; return; }
    i -= H2P;
    if (i < H2P) { g_s.l1bp[i] = (i < H2) ? l1b[i] : 0.f; return; }
    i -= H2P;
    if (i < H2P) { g_s.l2bp[i] = (i < H2) ? l2b[i] : 0.f; return; }
}

// ---------------------------------------------------------------------------
// Stage-1 aggregation writing fp16 directly into xpA cols [64,128).
// ---------------------------------------------------------------------------
__global__ void aggx_kernel(const float* __restrict__ val, const int* __restrict__ csr_src,
                            const float* __restrict__ csr_norm, const int* __restrict__ rowptr,
                            __half* __restrict__ xpA, int n) {
    int node = (blockIdx.x * blockDim.x + threadIdx.x) >> 5;
    int lane = threadIdx.x & 31;
    if (node >= n) return;
    int beg = rowptr[node], end = rowptr[node + 1];
    float acc0 = 0.f, acc1 = 0.f;
    for (int j = beg; j < end; j++) {
        int s = csr_src[j];
        float w = csr_norm[j];
        const float* vrow = val + (long)s * FP;
        acc0 += vrow[lane] * w;
        if (lane + 32 < F_IN) acc1 += vrow[lane + 32] * w;
    }
    long o = (long)node * KA1 + FP + lane;
    xpA[o]      = __float2half(acc0);
    xpA[o + 32] = __float2half(acc1);
}

// ---------------------------------------------------------------------------
// Aggregation: warp per node; F valid cols; SV val stride; SO out stride.
// ---------------------------------------------------------------------------
template <int F, int SV, int SO>
__global__ void agg_kernel(const float* __restrict__ val, const int* __restrict__ csr_src,
                           const float* __restrict__ csr_norm, const int* __restrict__ rowptr,
                           float* __restrict__ out, int n) {
    int node = (blockIdx.x * blockDim.x + threadIdx.x) >> 5;
    int lane = threadIdx.x & 31;
    if (node >= n) return;
    int beg = rowptr[node], end = rowptr[node + 1];
    constexpr int R = (SO + 31) / 32;
    float acc[R];
    #pragma unroll
    for (int r = 0; r < R; r++) acc[r] = 0.f;
    for (int j = beg; j < end; j++) {
        int s = csr_src[j];
        float w = csr_norm[j];
        const float* vrow = val + (long)s * SV;
        #pragma unroll
        for (int r = 0; r < R; r++) {
            int f = lane + r * 32;
            if (f < F) acc[r] += vrow[f] * w;
        }
    }
    float* orow = out + (long)node * SO;
    #pragma unroll
    for (int r = 0; r < R; r++) {
        int f = lane + r * 32;
        if (f < SO) orow[f] = acc[r];
    }
}

// ---------------------------------------------------------------------------
// Single-pass fp16 tensor-core GEMM. BM=128, BN=64, BK=32, 8 warps 32x32.
// MODE 0: C1 = acc
// MODE 1: C1 = relu(acc + bias1)               (OUTFP16 -> Cb fp16)
// MODE 4: x1 = relu(addm[r*M2B+H2P+c] + addm2 + bias3)
//         C1 = x1 + relu(acc1 + bias1)   [xm fp32]
//         Cb = fp16(x1 + relu(acc2 + bias2))  [z]   (requires DUALOUT)
// ---------------------------------------------------------------------------
template <int MODE, bool DUALOUT, bool OUTFP16>
__global__ __launch_bounds__(256)
void hgemm_kernel(const __half* __restrict__ A, int lda, int K,
                  const __half* __restrict__ B1, const __half* __restrict__ B2,
                  const float* __restrict__ addm, const float* __restrict__ addm2,
                  const float* __restrict__ bias1, const float* __restrict__ bias2,
                  const float* __restrict__ bias3,
                  float* __restrict__ C1, __half* __restrict__ Cb,
                  int Nr, int M) {
    __shared__ __align__(16) __half As[128][40];
    __shared__ __align__(16) __half Bs[32][72];
    __shared__ __align__(16) __half Bs2[32][72];

    int tid = threadIdx.x;
    int bm = blockIdx.y * 128, bn = blockIdx.x * 64;
    int lane = tid & 31, wid = tid >> 5;
    int wm = (wid >> 1) * 32, wn = (wid & 1) * 32;

    float acc[2][4][4];
    float acc2[2][4][4];
    #pragma unroll
    for (int mf = 0; mf < 2; mf++)
        #pragma unroll
        for (int nf = 0; nf < 4; nf++)
            #pragma unroll
            for (int q = 0; q < 4; q++) { acc[mf][nf][q] = 0.f; acc2[mf][nf][q] = 0.f; }

    for (int k0 = 0; k0 < K; k0 += 32) {
        // A tile: 128 rows x 32 halves = 512 uint4; 256 threads x 2
        #pragma unroll
        for (int i = 0; i < 2; i++) {
            int c = tid * 2 + i;
            int row = c >> 2, seg = c & 3;
            int gr = bm + row;
            uint4 vh = make_uint4(0, 0, 0, 0);
            if (gr < Nr)
                vh = *reinterpret_cast<const uint4*>(A + (long)gr * lda + k0 + seg * 8);
            *reinterpret_cast<uint4*>(&As[row][seg * 8]) = vh;
        }
        // B tile(s): 32 rows x 64 halves = 256 uint4
        {
            int row = tid >> 3, seg = tid & 7;
            long off = (long)(k0 + row) * M + bn + seg * 8;
            *reinterpret_cast<uint4*>(&Bs[row][seg * 8]) =
                *reinterpret_cast<const uint4*>(B1 + off);
            if constexpr (DUALOUT) {
                *reinterpret_cast<uint4*>(&Bs2[row][seg * 8]) =
                    *reinterpret_cast<const uint4*>(B2 + off);
            }
        }
        __syncthreads();

        #pragma unroll
        for (int s = 0; s < 32; s += 16) {
            uint32_t a[2][4];
            #pragma unroll
            for (int mf = 0; mf < 2; mf++) {
                int row = wm + mf * 16 + (lane & 15);
                int col = s + ((lane >> 4) << 3);
                ldm_x4(a[mf], smem_u32(&As[row][col]));
            }
            int kr = s + (lane & 7) + (lane & 8);
            int nshift = (lane >> 4) << 3;
            uint32_t b[4][2];
            #pragma unroll
            for (int g = 0; g < 2; g++) {
                int nc = wn + g * 16 + nshift;
                uint32_t r[4];
                ldm_x4_t(r, smem_u32(&Bs[kr][nc]));
                b[g * 2][0] = r[0]; b[g * 2][1] = r[1];
                b[g * 2 + 1][0] = r[2]; b[g * 2 + 1][1] = r[3];
            }
            #pragma unroll
            for (int mf = 0; mf < 2; mf++)
                #pragma unroll
                for (int nf = 0; nf < 4; nf++)
                    mma_fp16(acc[mf][nf], a[mf], b[nf]);
            if constexpr (DUALOUT) {
                uint32_t b2[4][2];
                #pragma unroll
                for (int g = 0; g < 2; g++) {
                    int nc = wn + g * 16 + nshift;
                    uint32_t r[4];
                    ldm_x4_t(r, smem_u32(&Bs2[kr][nc]));
                    b2[g * 2][0] = r[0]; b2[g * 2][1] = r[1];
                    b2[g * 2 + 1][0] = r[2]; b2[g * 2 + 1][1] = r[3];
                }
                #pragma unroll
                for (int mf = 0; mf < 2; mf++)
                    #pragma unroll
                    for (int nf = 0; nf < 4; nf++)
                        mma_fp16(acc2[mf][nf], a[mf], b2[nf]);
            }
        }
        __syncthreads();
    }

    // --- epilogue
    int gid = lane >> 2, tig = lane & 3;
    #pragma unroll
    for (int mf = 0; mf < 2; mf++) {
        #pragma unroll
        for (int nf = 0; nf < 4; nf++) {
            int c = bn + wn + nf * 8 + tig * 2;
            float bv0 = 0.f, bv1 = 0.f, b2v0 = 0.f, b2v1 = 0.f;
            if constexpr (MODE >= 1) { bv0 = bias1[c]; bv1 = bias1[c + 1]; }
            if constexpr (DUALOUT) { b2v0 = bias2[c]; b2v1 = bias2[c + 1]; }
            #pragma unroll
            for (int half_i = 0; half_i < 2; half_i++) {
                int r = bm + wm + mf * 16 + gid + half_i * 8;
                if (r >= Nr) continue;
                long base = (long)r * M + c;
                float v0 = acc[mf][nf][half_i * 2 + 0];
                float v1 = acc[mf][nf][half_i * 2 + 1];
                if constexpr (MODE == 4) {
                    long pbase = (long)r * M2B + H2P + c;
                    float x10 = fmaxf(addm[pbase]     + addm2[base]     + bias3[c],     0.f);
                    float x11 = fmaxf(addm[pbase + 1] + addm2[base + 1] + bias3[c + 1], 0.f);
                    C1[base]     = x10 + fmaxf(v0 + bv0, 0.f);
                    C1[base + 1] = x11 + fmaxf(v1 + bv1, 0.f);
                    float z0 = x10 + fmaxf(acc2[mf][nf][half_i * 2 + 0] + b2v0, 0.f);
                    float z1 = x11 + fmaxf(acc2[mf][nf][half_i * 2 + 1] + b2v1, 0.f);
                    Cb[base]     = __float2half(z0);
                    Cb[base + 1] = __float2half(z1);
                } else {
                    if constexpr (MODE >= 1) {
                        v0 = fmaxf(v0 + bv0, 0.f);
                        v1 = fmaxf(v1 + bv1, 0.f);
                    }
                    if constexpr (OUTFP16) {
                        Cb[base]     = __float2half(v0);
                        Cb[base + 1] = __float2half(v1);
                    } else {
                        C1[base] = v0; C1[base + 1] = v1;
                    }
                }
            }
        }
    }
}

// ---------------------------------------------------------------------------
// Stage-3 dual GEMV: s0 = xm@W3_0, s1 = xm@W3_1
// ---------------------------------------------------------------------------
__global__ void gemv3_kernel(const float* __restrict__ xm, const float* __restrict__ w0,
                             const float* __restrict__ w1, float* __restrict__ s0,
                             float* __restrict__ s1, int n) {
    int warp = (blockIdx.x * blockDim.x + threadIdx.x) >> 5;
    int lane = threadIdx.x & 31;
    if (warp >= n) return;
    float a0 = 0.f, a1 = 0.f;
    const float* row = xm + (long)warp * H2P;
    for (int f = lane; f < H2; f += 32) {
        float v = row[f];
        a0 += v * w0[f];
        a1 += v * w1[f];
    }
    #pragma unroll
    for (int d = 16; d; d >>= 1) {
        a0 += __shfl_down_sync(0xFFFFFFFFu, a0, d);
        a1 += __shfl_down_sync(0xFFFFFFFFu, a1, d);
    }
    if (lane == 0) { s0[warp] = a0; s1[warp] = a1; }
}

// ---------------------------------------------------------------------------
// Merged pos+neg edge score loss over fp16 z (stride H2P).
// ---------------------------------------------------------------------------
__global__ void score_kernel(const __half* __restrict__ zb, const int* __restrict__ ei,
                             const int* __restrict__ nei, int E_, float* __restrict__ accum) {
    int lane = threadIdx.x & 31;
    int warp_global = (blockIdx.x * blockDim.x + threadIdx.x) >> 5;
    int nwarps = (gridDim.x * blockDim.x) >> 5;
    float psum = 0.f, nsum = 0.f;
    for (int t = warp_global; t < 2 * E_; t += nwarps) {
        int which = (t >= E_);
        const int* p = which ? nei : ei;
        int e = which ? t - E_ : t;
        int a = p[e], b = p[e + E_];
        float dot = 0.f;
        if (lane < 25) {
            uint2 ua = reinterpret_cast<const uint2*>(zb + (long)a * H2P)[lane];
            uint2 ub = reinterpret_cast<const uint2*>(zb + (long)b * H2P)[lane];
            float2 a0 = __half22float2(*reinterpret_cast<__half2*>(&ua.x));
            float2 a1 = __half22float2(*reinterpret_cast<__half2*>(&ua.y));
            float2 b0 = __half22float2(*reinterpret_cast<__half2*>(&ub.x));
            float2 b1 = __half22float2(*reinterpret_cast<__half2*>(&ub.y));
            dot = a0.x * b0.x + a0.y * b0.y + a1.x * b1.x + a1.y * b1.y;
        }
        #pragma unroll
        for (int dd = 16; dd; dd >>= 1) dot += __shfl_down_sync(0xFFFFFFFFu, dot, dd);
        if (lane == 0) {
            float sig = 1.f / (1.f + expf(-dot));
            if (which) nsum += logf(1.f - sig + 1e-15f);
            else       psum += logf(sig + 1e-15f);
        }
    }
    __shared__ float redp[32], redn[32];
    #pragma unroll
    for (int dd = 16; dd; dd >>= 1) {
        psum += __shfl_down_sync(0xFFFFFFFFu, psum, dd);
        nsum += __shfl_down_sync(0xFFFFFFFFu, nsum, dd);
    }
    if (lane == 0) { redp[threadIdx.x >> 5] = psum; redn[threadIdx.x >> 5] = nsum; }
    __syncthreads();
    if (threadIdx.x < 32) {
        int nw = blockDim.x >> 5;
        float vp = (threadIdx.x < nw) ? redp[threadIdx.x] : 0.f;
        float vn = (threadIdx.x < nw) ? redn[threadIdx.x] : 0.f;
        #pragma unroll
        for (int dd = 16; dd; dd >>= 1) {
            vp += __shfl_down_sync(0xFFFFFFFFu, vp, dd);
            vn += __shfl_down_sync(0xFFFFFFFFu, vn, dd);
        }
        if (threadIdx.x == 0) {
            atomicAdd(&accum[0], vp);
            atomicAdd(&accum[1], vn);
        }
    }
}

// ---------------------------------------------------------------------------
// Final: out[i] = s0[i] + Agg(s1)[i] + b3 (F=1 aggregation fused).
// ---------------------------------------------------------------------------
__global__ void agg1final_kernel(const float* __restrict__ s0, const float* __restrict__ s1,
                                 const int* __restrict__ csr_src, const float* __restrict__ csr_norm,
                                 const int* __restrict__ rowptr, const float* __restrict__ b3,
                                 const float* __restrict__ accum, const float* __restrict__ c1,
                                 const float* __restrict__ c2, float* __restrict__ out,
                                 int n, float invE) {
    int i = blockIdx.x * blockDim.x + threadIdx.x;
    if (i < n) {
        float a = 0.f;
        int end = rowptr[i + 1];
        for (int j = rowptr[i]; j < end; j++)
            a += s1[csr_src[j]] * csr_norm[j];
        out[i] = s0[i] + a + b3[0];
    }
    if (i == 0) {
        out[n] = -(accum[0] + accum[1]) * invE;
        out[n + 1] = c1[0];
        out[n + 2] = c2[0];
    }
}

// ---------------------------------------------------------------------------
// Launch
// ---------------------------------------------------------------------------
extern "C" void kernel_launch(void* const* d_in, const int* in_sizes, int n_in,
                              void* d_out, int out_size) {
    const float* x      = (const float*)d_in[0];
    const int*   ei     = (const int*)d_in[1];
    const int*   nei    = (const int*)d_in[2];
    const float* W1_0   = (const float*)d_in[3];
    const float* W1_1   = (const float*)d_in[4];
    const float* b1     = (const float*)d_in[5];
    const float* W2_0   = (const float*)d_in[6];
    const float* W2_1   = (const float*)d_in[7];
    const float* b2     = (const float*)d_in[8];
    const float* W3_0   = (const float*)d_in[9];
    const float* W3_1   = (const float*)d_in[10];
    const float* b3     = (const float*)d_in[11];
    const float* lin1_W = (const float*)d_in[12];
    const float* lin1_b = (const float*)d_in[13];
    const float* lin2_W = (const float*)d_in[14];
    const float* lin2_b = (const float*)d_in[15];
    const float* c1     = (const float*)d_in[16];
    const float* c2     = (const float*)d_in[17];
    float* out = (float*)d_out;

    int n = in_sizes[0] / F_IN;   // 50000
    int e = in_sizes[1] / 2;      // 800000

    Scratch* sp = nullptr;
    cudaGetSymbolAddress((void**)&sp, g_s);

    const int* src = ei;
    const int* dst = ei + e;

    int nb_n = (n + 255) / 256;
    int nb_e = (e + 255) / 256;
    int agg_blocks = (n * 32 + 255) / 256;
    int nb_scan = (n + 1023) / 1024;
    int gy = (n + 127) / 128;

    // Setup + CSR
    pad_xc_kernel<<<(n * FP + 255) / 256, 256>>>(x, n);
    hist_kernel<<<nb_e, 256>>>(src, dst, sp->deg, sp->cnt, e);
    scan1dis_kernel<<<nb_scan, 1024>>>(sp->cnt, sp->deg, sp->rowptr, sp->bsum, sp->dis, n);
    scan2_kernel<<<1, 32>>>(sp->bsum, sp->boff, sp->rowptr, nb_scan, n);
    scan3_kernel<<<nb_scan, 1024>>>(sp->rowptr, sp->cursor, sp->boff, n);
    fill_kernel<<<nb_e, 256>>>(src, dst, sp->dis, sp->cursor, sp->csr_src, sp->csr_norm, e);

    // Weight conversion (single kernel)
    convall_kernel<<<(CTOT + 255) / 256, 256>>>(W1_0, W1_1, W2_0, W2_1, lin1_W, lin2_W,
                                                b1, b2, lin1_b, lin2_b);

    // Stage 1 aggregation -> xpA cols [64,128)
    aggx_kernel<<<agg_blocks, 256>>>(sp->xp, sp->csr_src, sp->csr_norm, sp->rowptr,
                                     sp->xpA, n);

    // G1: h(fp16) = relu([xp|tx1] @ W1cat + b1)   K=128, M=320
    hgemm_kernel<1, false, true><<<dim3(H1P / 64, gy), 256>>>(
        sp->xpA, KA1, KA1, sp->W1c, nullptr, nullptr, nullptr,
        sp->b1p, nullptr, nullptr, nullptr, sp->h_fp, n, H1P);

    // G2': hW2b = h @ [W2_1 | W2_0]   K=320, M=256
    hgemm_kernel<0, false, false><<<dim3(M2B / 64, gy), 256>>>(
        sp->h_fp, KH, KH, sp->W2c, nullptr, nullptr, nullptr,
        nullptr, nullptr, nullptr, sp->hW2b, nullptr, n, M2B);

    // agg2 = Agg(hW2b[:, 0:100])
    agg_kernel<H2, M2B, H2P><<<agg_blocks, 256>>>(sp->hW2b, sp->csr_src, sp->csr_norm,
                                                  sp->rowptr, sp->agg2, n);

    // G4 (MODE 4): xm = x1 + relu(xp@L1+b); z = fp16(x1 + relu(xp@L2+b));
    //              x1 = relu(hW2b[:,128:] + agg2 + b2) in epilogue
    hgemm_kernel<4, true, false><<<dim3(H2P / 64, gy), 256>>>(
        sp->xpA, KA1, FP, sp->L1, sp->L2, sp->hW2b, sp->agg2,
        sp->l1bp, sp->l2bp, sp->b2p, sp->xm, sp->z_fp, n, H2P);

    // Stage 3 + losses
    gemv3_kernel<<<agg_blocks, 256>>>(sp->xm, W3_0, W3_1, sp->s0, sp->s1, n);
    score_kernel<<<2048, 256>>>(sp->z_fp, ei, nei, e, sp->accum);
    agg1final_kernel<<<nb_n, 256>>>(sp->s0, sp->s1, sp->csr_src, sp->csr_norm, sp->rowptr,
                                    b3, sp->accum, c1, c2, out, n, 1.0f / (float)e);
}

// round 8
// speedup vs baseline: 2.0148x; 1.2336x over previous
#include <cuda_runtime.h>
#include <cuda_fp16.h>
#include <cstdint>
#include <math.h>

#define NN 50000
#define EE 800000
#define F_IN 58
#define FP 64
#define H1 300
#define H2 100
#define H1P 320
#define H2P 128
#define KA1 128   // GEMM1 K: [xp|tx1]
#define KH 320    // padded K for fused stage-2 GEMM
#define M2B 256   // fused stage-2 GEMM logical N: [W2_1|W2_0]
#define ZS 104    // compact z row stride (halves); cols 100..103 == 0

// ---------------------------------------------------------------------------
// Scratch (device-global, no runtime allocation).
// ---------------------------------------------------------------------------
struct alignas(16) Scratch {
    int   deg[NN];
    int   cnt[NN];
    int   rowptr[NN + 4];
    int   cursor[NN];
    int   csr_src[EE];
    float csr_norm[EE];
    int   bsum[64];
    int   boff[64];
    float dis[NN];
    float xp[NN * FP];
    __half xpA[NN * KA1];    // [xp | Agg(xp)] fp16
    __half h_fp[NN * KH];    // relu(cheb1) fp16, [N,320]
    __half hW21f[NN * H2P];  // h @ W2_1 (fp16, gathered by agg2)
    float hW20[NN * H2P];    // h @ W2_0 (fp32)
    float agg2[NN * H2P];
    float xm[NN * H2P];
    __half z_fp[NN * ZS];    // compact fp16 z
    __half W1c[KA1 * H1P];   // [128,320]
    __half W2c[KH * M2B];    // [320,256]
    __half L1[FP * H2P];     // [64,128]
    __half L2[FP * H2P];
    float b1p[H1P], b2p[H2P], l1bp[H2P], l2bp[H2P];
    float s0[NN], s1[NN];
    float accum[2];
};
__device__ Scratch g_s;

// ---------------------------------------------------------------------------
// PTX helpers
// ---------------------------------------------------------------------------
__device__ __forceinline__ uint32_t smem_u32(const void* p) {
    return (uint32_t)__cvta_generic_to_shared(p);
}
__device__ __forceinline__ void ldm_x4(uint32_t* r, uint32_t addr) {
    asm volatile("ldmatrix.sync.aligned.m8n8.x4.shared.b16 {%0,%1,%2,%3}, [%4];"
                 : "=r"(r[0]), "=r"(r[1]), "=r"(r[2]), "=r"(r[3]) : "r"(addr));
}
__device__ __forceinline__ void ldm_x4_t(uint32_t* r, uint32_t addr) {
    asm volatile("ldmatrix.sync.aligned.m8n8.x4.trans.shared.b16 {%0,%1,%2,%3}, [%4];"
                 : "=r"(r[0]), "=r"(r[1]), "=r"(r[2]), "=r"(r[3]) : "r"(addr));
}
__device__ __forceinline__ void mma_fp16(float* c, const uint32_t* a, const uint32_t* b) {
    asm volatile("mma.sync.aligned.m16n8k16.row.col.f32.f16.f16.f32 "
                 "{%0,%1,%2,%3}, {%4,%5,%6,%7}, {%8,%9}, {%0,%1,%2,%3};"
                 : "+f"(c[0]), "+f"(c[1]), "+f"(c[2]), "+f"(c[3])
                 : "r"(a[0]), "r"(a[1]), "r"(a[2]), "r"(a[3]), "r"(b[0]), "r"(b[1]));
}

// ---------------------------------------------------------------------------
// pad_xc: zero deg/cnt/accum; write xp fp32 + xpA cols [0,64) fp16.
// ---------------------------------------------------------------------------
__global__ void pad_xc_kernel(const float* __restrict__ x, int n) {
    int i = blockIdx.x * blockDim.x + threadIdx.x;
    if (i < n) { g_s.deg[i] = 0; g_s.cnt[i] = 0; }
    if (i < 2) g_s.accum[i] = 0.f;
    if (i >= n * FP) return;
    int r = i >> 6, f = i & 63;
    float v = (f < F_IN) ? x[(long)r * F_IN + f] : 0.f;
    g_s.xp[i] = v;
    g_s.xpA[(long)r * KA1 + f] = __float2half(v);
}

__global__ void hist_kernel(const int* __restrict__ src, const int* __restrict__ dst,
                            int* deg, int* cnt, int e) {
    int i = blockIdx.x * blockDim.x + threadIdx.x;
    if (i < e) {
        atomicAdd(&deg[src[i]], 1);
        atomicAdd(&cnt[dst[i]], 1);
    }
}

// scan stage 1 (+ dis folded in)
__global__ void scan1dis_kernel(const int* __restrict__ cnt, const int* __restrict__ deg,
                                int* __restrict__ rowptr, int* __restrict__ bsum,
                                float* __restrict__ dis, int n) {
    __shared__ int warp_sums[32];
    int tid = threadIdx.x;
    int i = blockIdx.x * 1024 + tid;
    if (i < n) {
        int d = deg[i];
        dis[i] = (d > 0) ? (1.0f / sqrtf((float)d)) : 0.0f;
    }
    int v = (i < n) ? cnt[i] : 0;
    int x = v;
    #pragma unroll
    for (int d = 1; d < 32; d <<= 1) {
        int y = __shfl_up_sync(0xFFFFFFFFu, x, d);
        if ((tid & 31) >= d) x += y;
    }
    if ((tid & 31) == 31) warp_sums[tid >> 5] = x;
    __syncthreads();
    if (tid < 32) {
        int y = warp_sums[tid];
        int zz = y;
        #pragma unroll
        for (int d = 1; d < 32; d <<= 1) {
            int w = __shfl_up_sync(0xFFFFFFFFu, zz, d);
            if (tid >= d) zz += w;
        }
        warp_sums[tid] = zz - y;
    }
    __syncthreads();
    int incl = x + warp_sums[tid >> 5];
    if (i < n) rowptr[i] = incl - v;
    if (tid == 1023) bsum[blockIdx.x] = incl;
}

__global__ void scan2_kernel(const int* __restrict__ bsum, int* __restrict__ boff,
                             int* __restrict__ rowptr, int nb, int n) {
    if (threadIdx.x == 0 && blockIdx.x == 0) {
        int run = 0;
        for (int b = 0; b < nb; b++) { boff[b] = run; run += bsum[b]; }
        rowptr[n] = run;
    }
}

__global__ void scan3_kernel(int* __restrict__ rowptr, int* __restrict__ cursor,
                             const int* __restrict__ boff, int n) {
    int i = blockIdx.x * 1024 + threadIdx.x;
    if (i < n) {
        int v = rowptr[i] + boff[blockIdx.x];
        rowptr[i] = v;
        cursor[i] = v;
    }
}

__global__ void fill_kernel(const int* __restrict__ src, const int* __restrict__ dst,
                            const float* __restrict__ dis, int* __restrict__ cursor,
                            int* __restrict__ csr_src, float* __restrict__ csr_norm, int e) {
    int i = blockIdx.x * blockDim.x + threadIdx.x;
    if (i < e) {
        int s = src[i], d = dst[i];
        int p = atomicAdd(&cursor[d], 1);
        csr_src[p] = s;
        csr_norm[p] = -(dis[s] * dis[d]);
    }
}

// ---------------------------------------------------------------------------
// All weight/bias conversions in ONE kernel (fp16).
// ---------------------------------------------------------------------------
#define CN1 (KA1 * H1P)
#define CN2 (KH * M2B)
#define CN3 (FP * H2P)
#define CTOT (CN1 + CN2 + 2 * CN3 + H1P + 3 * H2P)
__global__ void convall_kernel(const float* __restrict__ W10, const float* __restrict__ W11,
                               const float* __restrict__ W20, const float* __restrict__ W21,
                               const float* __restrict__ l1W, const float* __restrict__ l2W,
                               const float* __restrict__ b1, const float* __restrict__ b2,
                               const float* __restrict__ l1b, const float* __restrict__ l2b) {
    int i = blockIdx.x * blockDim.x + threadIdx.x;
    if (i < CN1) {
        int k = i / H1P, m = i % H1P;
        float v = 0.f;
        if (m < H1) {
            if (k < F_IN) v = W10[k * H1 + m];
            else if (k >= FP && k < FP + F_IN) v = W11[(k - FP) * H1 + m];
        }
        g_s.W1c[i] = __float2half(v);
        return;
    }
    i -= CN1;
    if (i < CN2) {
        int k = i / M2B, m = i % M2B;
        float v = 0.f;
        if (k < H1) {
            if (m < H2P) { if (m < H2) v = W21[k * H2 + m]; }
            else { int mm = m - H2P; if (mm < H2) v = W20[k * H2 + mm]; }
        }
        g_s.W2c[i] = __float2half(v);
        return;
    }
    i -= CN2;
    if (i < CN3) {
        int k = i >> 7, m = i & 127;
        float v = (k < F_IN && m < H2) ? l1W[m * F_IN + k] : 0.f;
        g_s.L1[i] = __float2half(v);
        return;
    }
    i -= CN3;
    if (i < CN3) {
        int k = i >> 7, m = i & 127;
        float v = (k < F_IN && m < H2) ? l2W[m * F_IN + k] : 0.f;
        g_s.L2[i] = __float2half(v);
        return;
    }
    i -= CN3;
    if (i < H1P) { g_s.b1p[i] = (i < H1) ? b1[i] : 0.f; return; }
    i -= H1P;
    if (i < H2P) { g_s.b2p[i] = (i < H2) ? b2[i] : 0.f; return; }
    i -= H2P;
    if (i < H2P) { g_s.l1bp[i] = (i < H2) ? l1b[i] : 0.f; return; }
    i -= H2P;
    if (i < H2P) { g_s.l2bp[i] = (i < H2) ? l2b[i] : 0.f; return; }
}

// ---------------------------------------------------------------------------
// Stage-1 aggregation writing fp16 directly into xpA cols [64,128).
// ---------------------------------------------------------------------------
__global__ void aggx_kernel(const float* __restrict__ val, const int* __restrict__ csr_src,
                            const float* __restrict__ csr_norm, const int* __restrict__ rowptr,
                            __half* __restrict__ xpA, int n) {
    int node = (blockIdx.x * blockDim.x + threadIdx.x) >> 5;
    int lane = threadIdx.x & 31;
    if (node >= n) return;
    int beg = rowptr[node], end = rowptr[node + 1];
    float acc0 = 0.f, acc1 = 0.f;
    for (int j = beg; j < end; j++) {
        int s = csr_src[j];
        float w = csr_norm[j];
        const float* vrow = val + (long)s * FP;
        acc0 += vrow[lane] * w;
        if (lane + 32 < F_IN) acc1 += vrow[lane + 32] * w;
    }
    long o = (long)node * KA1 + FP + lane;
    xpA[o]      = __float2half(acc0);
    xpA[o + 32] = __float2half(acc1);
}

// ---------------------------------------------------------------------------
// agg2 over fp16 rows [N,128]: out fp32 [N,128].
// Lane covers cols {2l, 2l+1, 2l+64, 2l+65} via two half2 loads.
// ---------------------------------------------------------------------------
__global__ void agg2h_kernel(const __half* __restrict__ val, const int* __restrict__ csr_src,
                             const float* __restrict__ csr_norm, const int* __restrict__ rowptr,
                             float* __restrict__ out, int n) {
    int node = (blockIdx.x * blockDim.x + threadIdx.x) >> 5;
    int lane = threadIdx.x & 31;
    if (node >= n) return;
    int beg = rowptr[node], end = rowptr[node + 1];
    float a0 = 0.f, a1 = 0.f, a2 = 0.f, a3 = 0.f;
    for (int j = beg; j < end; j++) {
        int s = csr_src[j];
        float w = csr_norm[j];
        const __half2* vr = reinterpret_cast<const __half2*>(val + (long)s * H2P);
        float2 f0 = __half22float2(vr[lane]);
        float2 f1 = __half22float2(vr[lane + 32]);
        a0 += f0.x * w; a1 += f0.y * w;
        a2 += f1.x * w; a3 += f1.y * w;
    }
    float* orow = out + (long)node * H2P;
    orow[2 * lane]      = a0;
    orow[2 * lane + 1]  = a1;
    orow[2 * lane + 64] = a2;
    orow[2 * lane + 65] = a3;
}

// ---------------------------------------------------------------------------
// Single-pass fp16 tensor-core GEMM. BM=128, BN=64, BK=32, 8 warps 32x32.
// MODE 0: C1 = acc
// MODE 1: C1 = relu(acc + bias1)               (OUTFP16 -> Cb fp16, stride M)
// MODE 4: x1 = relu(addm[r*H2P+c] + addm2[r*H2P+c] + bias3[c])
//         C1 = x1 + relu(acc1 + bias1)   [xm fp32, stride M]
//         Cb = fp16(x1 + relu(acc2 + bias2)) at stride ZS, cols < ZS  [z]
// MODE 5: c<128 -> Cb[r*128+c] = fp16(acc); else C1[r*128+(c-128)] = acc
// ---------------------------------------------------------------------------
template <int MODE, bool DUALOUT, bool OUTFP16>
__global__ __launch_bounds__(256)
void hgemm_kernel(const __half* __restrict__ A, int lda, int K,
                  const __half* __restrict__ B1, const __half* __restrict__ B2,
                  const float* __restrict__ addm, const float* __restrict__ addm2,
                  const float* __restrict__ bias1, const float* __restrict__ bias2,
                  const float* __restrict__ bias3,
                  float* __restrict__ C1, __half* __restrict__ Cb,
                  int Nr, int M) {
    __shared__ __align__(16) __half As[128][40];
    __shared__ __align__(16) __half Bs[32][72];
    __shared__ __align__(16) __half Bs2[32][72];

    int tid = threadIdx.x;
    int bm = blockIdx.y * 128, bn = blockIdx.x * 64;
    int lane = tid & 31, wid = tid >> 5;
    int wm = (wid >> 1) * 32, wn = (wid & 1) * 32;

    float acc[2][4][4];
    float acc2[2][4][4];
    #pragma unroll
    for (int mf = 0; mf < 2; mf++)
        #pragma unroll
        for (int nf = 0; nf < 4; nf++)
            #pragma unroll
            for (int q = 0; q < 4; q++) { acc[mf][nf][q] = 0.f; acc2[mf][nf][q] = 0.f; }

    for (int k0 = 0; k0 < K; k0 += 32) {
        #pragma unroll
        for (int i = 0; i < 2; i++) {
            int c = tid * 2 + i;
            int row = c >> 2, seg = c & 3;
            int gr = bm + row;
            uint4 vh = make_uint4(0, 0, 0, 0);
            if (gr < Nr)
                vh = *reinterpret_cast<const uint4*>(A + (long)gr * lda + k0 + seg * 8);
            *reinterpret_cast<uint4*>(&As[row][seg * 8]) = vh;
        }
        {
            int row = tid >> 3, seg = tid & 7;
            long off = (long)(k0 + row) * M + bn + seg * 8;
            *reinterpret_cast<uint4*>(&Bs[row][seg * 8]) =
                *reinterpret_cast<const uint4*>(B1 + off);
            if constexpr (DUALOUT) {
                *reinterpret_cast<uint4*>(&Bs2[row][seg * 8]) =
                    *reinterpret_cast<const uint4*>(B2 + off);
            }
        }
        __syncthreads();

        #pragma unroll
        for (int s = 0; s < 32; s += 16) {
            uint32_t a[2][4];
            #pragma unroll
            for (int mf = 0; mf < 2; mf++) {
                int row = wm + mf * 16 + (lane & 15);
                int col = s + ((lane >> 4) << 3);
                ldm_x4(a[mf], smem_u32(&As[row][col]));
            }
            int kr = s + (lane & 7) + (lane & 8);
            int nshift = (lane >> 4) << 3;
            uint32_t b[4][2];
            #pragma unroll
            for (int g = 0; g < 2; g++) {
                int nc = wn + g * 16 + nshift;
                uint32_t r[4];
                ldm_x4_t(r, smem_u32(&Bs[kr][nc]));
                b[g * 2][0] = r[0]; b[g * 2][1] = r[1];
                b[g * 2 + 1][0] = r[2]; b[g * 2 + 1][1] = r[3];
            }
            #pragma unroll
            for (int mf = 0; mf < 2; mf++)
                #pragma unroll
                for (int nf = 0; nf < 4; nf++)
                    mma_fp16(acc[mf][nf], a[mf], b[nf]);
            if constexpr (DUALOUT) {
                uint32_t b2[4][2];
                #pragma unroll
                for (int g = 0; g < 2; g++) {
                    int nc = wn + g * 16 + nshift;
                    uint32_t r[4];
                    ldm_x4_t(r, smem_u32(&Bs2[kr][nc]));
                    b2[g * 2][0] = r[0]; b2[g * 2][1] = r[1];
                    b2[g * 2 + 1][0] = r[2]; b2[g * 2 + 1][1] = r[3];
                }
                #pragma unroll
                for (int mf = 0; mf < 2; mf++)
                    #pragma unroll
                    for (int nf = 0; nf < 4; nf++)
                        mma_fp16(acc2[mf][nf], a[mf], b2[nf]);
            }
        }
        __syncthreads();
    }

    // --- epilogue
    int gid = lane >> 2, tig = lane & 3;
    #pragma unroll
    for (int mf = 0; mf < 2; mf++) {
        #pragma unroll
        for (int nf = 0; nf < 4; nf++) {
            int c = bn + wn + nf * 8 + tig * 2;
            float bv0 = 0.f, bv1 = 0.f, b2v0 = 0.f, b2v1 = 0.f;
            if constexpr (MODE == 1 || MODE == 4) { bv0 = bias1[c]; bv1 = bias1[c + 1]; }
            if constexpr (DUALOUT) { b2v0 = bias2[c]; b2v1 = bias2[c + 1]; }
            #pragma unroll
            for (int half_i = 0; half_i < 2; half_i++) {
                int r = bm + wm + mf * 16 + gid + half_i * 8;
                if (r >= Nr) continue;
                float v0 = acc[mf][nf][half_i * 2 + 0];
                float v1 = acc[mf][nf][half_i * 2 + 1];
                if constexpr (MODE == 4) {
                    long base = (long)r * H2P + c;
                    float x10 = fmaxf(addm[base]     + addm2[base]     + bias3[c],     0.f);
                    float x11 = fmaxf(addm[base + 1] + addm2[base + 1] + bias3[c + 1], 0.f);
                    C1[base]     = x10 + fmaxf(v0 + bv0, 0.f);
                    C1[base + 1] = x11 + fmaxf(v1 + bv1, 0.f);
                    if (c < ZS) {
                        float z0 = x10 + fmaxf(acc2[mf][nf][half_i * 2 + 0] + b2v0, 0.f);
                        float z1 = x11 + fmaxf(acc2[mf][nf][half_i * 2 + 1] + b2v1, 0.f);
                        Cb[(long)r * ZS + c]     = __float2half(z0);
                        Cb[(long)r * ZS + c + 1] = __float2half(z1);
                    }
                } else if constexpr (MODE == 5) {
                    if (c < H2P) {
                        long base = (long)r * H2P + c;
                        Cb[base]     = __float2half(v0);
                        Cb[base + 1] = __float2half(v1);
                    } else {
                        long base = (long)r * H2P + (c - H2P);
                        C1[base] = v0; C1[base + 1] = v1;
                    }
                } else {
                    long base = (long)r * M + c;
                    if constexpr (MODE == 1) {
                        v0 = fmaxf(v0 + bv0, 0.f);
                        v1 = fmaxf(v1 + bv1, 0.f);
                    }
                    if constexpr (OUTFP16) {
                        Cb[base]     = __float2half(v0);
                        Cb[base + 1] = __float2half(v1);
                    } else {
                        C1[base] = v0; C1[base + 1] = v1;
                    }
                }
            }
        }
    }
}

// ---------------------------------------------------------------------------
// Stage-3 dual GEMV: s0 = xm@W3_0, s1 = xm@W3_1
// ---------------------------------------------------------------------------
__global__ void gemv3_kernel(const float* __restrict__ xm, const float* __restrict__ w0,
                             const float* __restrict__ w1, float* __restrict__ s0,
                             float* __restrict__ s1, int n) {
    int warp = (blockIdx.x * blockDim.x + threadIdx.x) >> 5;
    int lane = threadIdx.x & 31;
    if (warp >= n) return;
    float a0 = 0.f, a1 = 0.f;
    const float* row = xm + (long)warp * H2P;
    for (int f = lane; f < H2; f += 32) {
        float v = row[f];
        a0 += v * w0[f];
        a1 += v * w1[f];
    }
    #pragma unroll
    for (int d = 16; d; d >>= 1) {
        a0 += __shfl_down_sync(0xFFFFFFFFu, a0, d);
        a1 += __shfl_down_sync(0xFFFFFFFFu, a1, d);
    }
    if (lane == 0) { s0[warp] = a0; s1[warp] = a1; }
}

// ---------------------------------------------------------------------------
// Merged pos+neg edge score loss over compact fp16 z (stride ZS=104).
// 16 lanes per edge, 2 edges per warp iteration, uint4 per lane (13 used).
// ---------------------------------------------------------------------------
__global__ void score_kernel(const __half* __restrict__ zb, const int* __restrict__ ei,
                             const int* __restrict__ nei, int E_, float* __restrict__ accum) {
    int lane = threadIdx.x & 31;
    int grp = lane >> 4;           // 0 or 1: which edge in the pair
    int l = lane & 15;             // lane within edge group
    int warp_global = (blockIdx.x * blockDim.x + threadIdx.x) >> 5;
    int nwarps = (gridDim.x * blockDim.x) >> 5;
    int total = 2 * E_;
    float psum = 0.f, nsum = 0.f;
    for (int t0 = warp_global * 2; t0 < total; t0 += nwarps * 2) {
        int t = t0 + grp;
        float dot = 0.f;
        int which = 0;
        if (t < total) {
            which = (t >= E_);
            const int* p = which ? nei : ei;
            int e = which ? t - E_ : t;
            int a = p[e], b = p[e + E_];
            if (l < 13) {
                uint4 ua = reinterpret_cast<const uint4*>(zb + (long)a * ZS)[l];
                uint4 ub = reinterpret_cast<const uint4*>(zb + (long)b * ZS)[l];
                const __half2* ha = reinterpret_cast<const __half2*>(&ua);
                const __half2* hb = reinterpret_cast<const __half2*>(&ub);
                #pragma unroll
                for (int q = 0; q < 4; q++) {
                    float2 fa = __half22float2(ha[q]);
                    float2 fb = __half22float2(hb[q]);
                    dot += fa.x * fb.x + fa.y * fb.y;
                }
            }
        }
        #pragma unroll
        for (int dd = 8; dd; dd >>= 1) dot += __shfl_down_sync(0xFFFFFFFFu, dot, dd);
        if (l == 0 && t < total) {
            float sig = 1.f / (1.f + expf(-dot));
            if (which) nsum += logf(1.f - sig + 1e-15f);
            else       psum += logf(sig + 1e-15f);
        }
    }
    // lane0 (grp 0) and lane16 (grp 1) hold partials
    psum += __shfl_down_sync(0xFFFFFFFFu, psum, 16);
    nsum += __shfl_down_sync(0xFFFFFFFFu, nsum, 16);
    __shared__ float redp[32], redn[32];
    if (lane == 0) { redp[threadIdx.x >> 5] = psum; redn[threadIdx.x >> 5] = nsum; }
    __syncthreads();
    if (threadIdx.x < 32) {
        int nw = blockDim.x >> 5;
        float vp = (threadIdx.x < nw) ? redp[threadIdx.x] : 0.f;
        float vn = (threadIdx.x < nw) ? redn[threadIdx.x] : 0.f;
        #pragma unroll
        for (int dd = 16; dd; dd >>= 1) {
            vp += __shfl_down_sync(0xFFFFFFFFu, vp, dd);
            vn += __shfl_down_sync(0xFFFFFFFFu, vn, dd);
        }
        if (threadIdx.x == 0) {
            atomicAdd(&accum[0], vp);
            atomicAdd(&accum[1], vn);
        }
    }
}

// ---------------------------------------------------------------------------
// Final: out[i] = s0[i] + Agg(s1)[i] + b3 (F=1 aggregation fused).
// ---------------------------------------------------------------------------
__global__ void agg1final_kernel(const float* __restrict__ s0, const float* __restrict__ s1,
                                 const int* __restrict__ csr_src, const float* __restrict__ csr_norm,
                                 const int* __restrict__ rowptr, const float* __restrict__ b3,
                                 const float* __restrict__ accum, const float* __restrict__ c1,
                                 const float* __restrict__ c2, float* __restrict__ out,
                                 int n, float invE) {
    int i = blockIdx.x * blockDim.x + threadIdx.x;
    if (i < n) {
        float a = 0.f;
        int end = rowptr[i + 1];
        for (int j = rowptr[i]; j < end; j++)
            a += s1[csr_src[j]] * csr_norm[j];
        out[i] = s0[i] + a + b3[0];
    }
    if (i == 0) {
        out[n] = -(accum[0] + accum[1]) * invE;
        out[n + 1] = c1[0];
        out[n + 2] = c2[0];
    }
}

// ---------------------------------------------------------------------------
// Launch
// ---------------------------------------------------------------------------
extern "C" void kernel_launch(void* const* d_in, const int* in_sizes, int n_in,
                              void* d_out, int out_size) {
    const float* x      = (const float*)d_in[0];
    const int*   ei     = (const int*)d_in[1];
    const int*   nei    = (const int*)d_in[2];
    const float* W1_0   = (const float*)d_in[3];
    const float* W1_1   = (const float*)d_in[4];
    const float* b1     = (const float*)d_in[5];
    const float* W2_0   = (const float*)d_in[6];
    const float* W2_1   = (const float*)d_in[7];
    const float* b2     = (const float*)d_in[8];
    const float* W3_0   = (const float*)d_in[9];
    const float* W3_1   = (const float*)d_in[10];
    const float* b3     = (const float*)d_in[11];
    const float* lin1_W = (const float*)d_in[12];
    const float* lin1_b = (const float*)d_in[13];
    const float* lin2_W = (const float*)d_in[14];
    const float* lin2_b = (const float*)d_in[15];
    const float* c1     = (const float*)d_in[16];
    const float* c2     = (const float*)d_in[17];
    float* out = (float*)d_out;

    int n = in_sizes[0] / F_IN;   // 50000
    int e = in_sizes[1] / 2;      // 800000

    Scratch* sp = nullptr;
    cudaGetSymbolAddress((void**)&sp, g_s);

    const int* src = ei;
    const int* dst = ei + e;

    int nb_n = (n + 255) / 256;
    int nb_e = (e + 255) / 256;
    int agg_blocks = (n * 32 + 255) / 256;
    int nb_scan = (n + 1023) / 1024;
    int gy = (n + 127) / 128;

    // Setup + CSR
    pad_xc_kernel<<<(n * FP + 255) / 256, 256>>>(x, n);
    hist_kernel<<<nb_e, 256>>>(src, dst, sp->deg, sp->cnt, e);
    scan1dis_kernel<<<nb_scan, 1024>>>(sp->cnt, sp->deg, sp->rowptr, sp->bsum, sp->dis, n);
    scan2_kernel<<<1, 32>>>(sp->bsum, sp->boff, sp->rowptr, nb_scan, n);
    scan3_kernel<<<nb_scan, 1024>>>(sp->rowptr, sp->cursor, sp->boff, n);
    fill_kernel<<<nb_e, 256>>>(src, dst, sp->dis, sp->cursor, sp->csr_src, sp->csr_norm, e);

    // Weight conversion (single kernel)
    convall_kernel<<<(CTOT + 255) / 256, 256>>>(W1_0, W1_1, W2_0, W2_1, lin1_W, lin2_W,
                                                b1, b2, lin1_b, lin2_b);

    // Stage 1 aggregation -> xpA cols [64,128)
    aggx_kernel<<<agg_blocks, 256>>>(sp->xp, sp->csr_src, sp->csr_norm, sp->rowptr,
                                     sp->xpA, n);

    // G1: h(fp16) = relu([xp|tx1] @ W1cat + b1)   K=128, M=320
    hgemm_kernel<1, false, true><<<dim3(H1P / 64, gy), 256>>>(
        sp->xpA, KA1, KA1, sp->W1c, nullptr, nullptr, nullptr,
        sp->b1p, nullptr, nullptr, nullptr, sp->h_fp, n, H1P);

    // G2 (MODE 5): hW21f(fp16) | hW20(fp32) = h @ [W2_1 | W2_0]   K=320, M=256
    hgemm_kernel<5, false, false><<<dim3(M2B / 64, gy), 256>>>(
        sp->h_fp, KH, KH, sp->W2c, nullptr, nullptr, nullptr,
        nullptr, nullptr, nullptr, sp->hW20, sp->hW21f, n, M2B);

    // agg2 = Agg(hW21f) over fp16 rows
    agg2h_kernel<<<agg_blocks, 256>>>(sp->hW21f, sp->csr_src, sp->csr_norm,
                                      sp->rowptr, sp->agg2, n);

    // G4 (MODE 4): xm = x1 + relu(xp@L1+b); z = fp16(x1 + relu(xp@L2+b)) compact;
    //              x1 = relu(hW20 + agg2 + b2) in epilogue
    hgemm_kernel<4, true, false><<<dim3(H2P / 64, gy), 256>>>(
        sp->xpA, KA1, FP, sp->L1, sp->L2, sp->hW20, sp->agg2,
        sp->l1bp, sp->l2bp, sp->b2p, sp->xm, sp->z_fp, n, H2P);

    // Stage 3 + losses
    gemv3_kernel<<<agg_blocks, 256>>>(sp->xm, W3_0, W3_1, sp->s0, sp->s1, n);
    score_kernel<<<2048, 256>>>(sp->z_fp, ei, nei, e, sp->accum);
    agg1final_kernel<<<nb_n, 256>>>(sp->s0, sp->s1, sp->csr_src, sp->csr_norm, sp->rowptr,
                                    b3, sp->accum, c1, c2, out, n, 1.0f / (float)e);
}

// round 9
// speedup vs baseline: 2.1055x; 1.0450x over previous
#include <cuda_runtime.h>
#include <cuda_fp16.h>
#include <cstdint>
#include <math.h>

#define NN 50000
#define EE 800000
#define F_IN 58
#define FP 64
#define H1 300
#define H2 100
#define H1P 320
#define H2P 128
#define KA1 128   // GEMM1 K: [xp|tx1]
#define KH 320    // padded K for fused stage-2 GEMM
#define M2B 256   // fused stage-2 GEMM logical N: [W2_1|W2_0]
#define ZS 104    // compact z row stride (halves); cols 100..103 == 0

// ---------------------------------------------------------------------------
// Scratch (device-global, no runtime allocation).
// ---------------------------------------------------------------------------
struct alignas(16) Scratch {
    int   deg[NN];
    int   cnt[NN];
    int   rowptr[NN + 4];
    int   cursor[NN];
    int   csr_src[EE];
    float csr_norm[EE];
    int   bsum[64];
    int   boff[64];
    float dis[NN];
    __half xpA[NN * KA1];    // [x_fp16 | Agg(x)] fp16
    __half h_fp[NN * KH];    // relu(cheb1) fp16, [N,320]
    __half hW21f[NN * H2P];  // h @ W2_1 (fp16, gathered by agg2)
    float hW20[NN * H2P];    // h @ W2_0 (fp32)
    float agg2[NN * H2P];
    __half z_fp[NN * ZS];    // compact fp16 z
    __half W1c[KA1 * H1P];   // [128,320]
    __half W2c[KH * M2B];    // [320,256]
    __half L1[FP * H2P];     // [64,128]
    __half L2[FP * H2P];
    float b1p[H1P], b2p[H2P], l1bp[H2P], l2bp[H2P];
    float w30p[H2P], w31p[H2P];
    float s0[NN], s1[NN];
    float accum[2];
};
__device__ Scratch g_s;

// ---------------------------------------------------------------------------
// PTX helpers
// ---------------------------------------------------------------------------
__device__ __forceinline__ uint32_t smem_u32(const void* p) {
    return (uint32_t)__cvta_generic_to_shared(p);
}
__device__ __forceinline__ void ldm_x4(uint32_t* r, uint32_t addr) {
    asm volatile("ldmatrix.sync.aligned.m8n8.x4.shared.b16 {%0,%1,%2,%3}, [%4];"
                 : "=r"(r[0]), "=r"(r[1]), "=r"(r[2]), "=r"(r[3]) : "r"(addr));
}
__device__ __forceinline__ void ldm_x4_t(uint32_t* r, uint32_t addr) {
    asm volatile("ldmatrix.sync.aligned.m8n8.x4.trans.shared.b16 {%0,%1,%2,%3}, [%4];"
                 : "=r"(r[0]), "=r"(r[1]), "=r"(r[2]), "=r"(r[3]) : "r"(addr));
}
__device__ __forceinline__ void mma_fp16(float* c, const uint32_t* a, const uint32_t* b) {
    asm volatile("mma.sync.aligned.m16n8k16.row.col.f32.f16.f16.f32 "
                 "{%0,%1,%2,%3}, {%4,%5,%6,%7}, {%8,%9}, {%0,%1,%2,%3};"
                 : "+f"(c[0]), "+f"(c[1]), "+f"(c[2]), "+f"(c[3])
                 : "r"(a[0]), "r"(a[1]), "r"(a[2]), "r"(a[3]), "r"(b[0]), "r"(b[1]));
}

// ---------------------------------------------------------------------------
// pad_xc: zero deg/cnt/accum/s0/s1; write xpA cols [0,64) fp16.
// ---------------------------------------------------------------------------
__global__ void pad_xc_kernel(const float* __restrict__ x, int n) {
    int i = blockIdx.x * blockDim.x + threadIdx.x;
    if (i < n) { g_s.deg[i] = 0; g_s.cnt[i] = 0; g_s.s0[i] = 0.f; g_s.s1[i] = 0.f; }
    if (i < 2) g_s.accum[i] = 0.f;
    if (i >= n * FP) return;
    int r = i >> 6, f = i & 63;
    float v = (f < F_IN) ? x[(long)r * F_IN + f] : 0.f;
    g_s.xpA[(long)r * KA1 + f] = __float2half(v);
}

__global__ void hist_kernel(const int* __restrict__ src, const int* __restrict__ dst,
                            int* deg, int* cnt, int e) {
    int i = blockIdx.x * blockDim.x + threadIdx.x;
    if (i < e) {
        atomicAdd(&deg[src[i]], 1);
        atomicAdd(&cnt[dst[i]], 1);
    }
}

// scan stage 1 (+ dis folded in)
__global__ void scan1dis_kernel(const int* __restrict__ cnt, const int* __restrict__ deg,
                                int* __restrict__ rowptr, int* __restrict__ bsum,
                                float* __restrict__ dis, int n) {
    __shared__ int warp_sums[32];
    int tid = threadIdx.x;
    int i = blockIdx.x * 1024 + tid;
    if (i < n) {
        int d = deg[i];
        dis[i] = (d > 0) ? (1.0f / sqrtf((float)d)) : 0.0f;
    }
    int v = (i < n) ? cnt[i] : 0;
    int x = v;
    #pragma unroll
    for (int d = 1; d < 32; d <<= 1) {
        int y = __shfl_up_sync(0xFFFFFFFFu, x, d);
        if ((tid & 31) >= d) x += y;
    }
    if ((tid & 31) == 31) warp_sums[tid >> 5] = x;
    __syncthreads();
    if (tid < 32) {
        int y = warp_sums[tid];
        int zz = y;
        #pragma unroll
        for (int d = 1; d < 32; d <<= 1) {
            int w = __shfl_up_sync(0xFFFFFFFFu, zz, d);
            if (tid >= d) zz += w;
        }
        warp_sums[tid] = zz - y;
    }
    __syncthreads();
    int incl = x + warp_sums[tid >> 5];
    if (i < n) rowptr[i] = incl - v;
    if (tid == 1023) bsum[blockIdx.x] = incl;
}

__global__ void scan2_kernel(const int* __restrict__ bsum, int* __restrict__ boff,
                             int* __restrict__ rowptr, int nb, int n) {
    if (threadIdx.x == 0 && blockIdx.x == 0) {
        int run = 0;
        for (int b = 0; b < nb; b++) { boff[b] = run; run += bsum[b]; }
        rowptr[n] = run;
    }
}

__global__ void scan3_kernel(int* __restrict__ rowptr, int* __restrict__ cursor,
                             const int* __restrict__ boff, int n) {
    int i = blockIdx.x * 1024 + threadIdx.x;
    if (i < n) {
        int v = rowptr[i] + boff[blockIdx.x];
        rowptr[i] = v;
        cursor[i] = v;
    }
}

__global__ void fill_kernel(const int* __restrict__ src, const int* __restrict__ dst,
                            const float* __restrict__ dis, int* __restrict__ cursor,
                            int* __restrict__ csr_src, float* __restrict__ csr_norm, int e) {
    int i = blockIdx.x * blockDim.x + threadIdx.x;
    if (i < e) {
        int s = src[i], d = dst[i];
        int p = atomicAdd(&cursor[d], 1);
        csr_src[p] = s;
        csr_norm[p] = -(dis[s] * dis[d]);
    }
}

// ---------------------------------------------------------------------------
// All weight/bias conversions in ONE kernel (fp16 + padded fp32 vectors).
// ---------------------------------------------------------------------------
#define CN1 (KA1 * H1P)
#define CN2 (KH * M2B)
#define CN3 (FP * H2P)
#define CTOT (CN1 + CN2 + 2 * CN3 + H1P + 5 * H2P)
__global__ void convall_kernel(const float* __restrict__ W10, const float* __restrict__ W11,
                               const float* __restrict__ W20, const float* __restrict__ W21,
                               const float* __restrict__ l1W, const float* __restrict__ l2W,
                               const float* __restrict__ b1, const float* __restrict__ b2,
                               const float* __restrict__ l1b, const float* __restrict__ l2b,
                               const float* __restrict__ W30, const float* __restrict__ W31) {
    int i = blockIdx.x * blockDim.x + threadIdx.x;
    if (i < CN1) {
        int k = i / H1P, m = i % H1P;
        float v = 0.f;
        if (m < H1) {
            if (k < F_IN) v = W10[k * H1 + m];
            else if (k >= FP && k < FP + F_IN) v = W11[(k - FP) * H1 + m];
        }
        g_s.W1c[i] = __float2half(v);
        return;
    }
    i -= CN1;
    if (i < CN2) {
        int k = i / M2B, m = i % M2B;
        float v = 0.f;
        if (k < H1) {
            if (m < H2P) { if (m < H2) v = W21[k * H2 + m]; }
            else { int mm = m - H2P; if (mm < H2) v = W20[k * H2 + mm]; }
        }
        g_s.W2c[i] = __float2half(v);
        return;
    }
    i -= CN2;
    if (i < CN3) {
        int k = i >> 7, m = i & 127;
        float v = (k < F_IN && m < H2) ? l1W[m * F_IN + k] : 0.f;
        g_s.L1[i] = __float2half(v);
        return;
    }
    i -= CN3;
    if (i < CN3) {
        int k = i >> 7, m = i & 127;
        float v = (k < F_IN && m < H2) ? l2W[m * F_IN + k] : 0.f;
        g_s.L2[i] = __float2half(v);
        return;
    }
    i -= CN3;
    if (i < H1P) { g_s.b1p[i] = (i < H1) ? b1[i] : 0.f; return; }
    i -= H1P;
    if (i < H2P) { g_s.b2p[i] = (i < H2) ? b2[i] : 0.f; return; }
    i -= H2P;
    if (i < H2P) { g_s.l1bp[i] = (i < H2) ? l1b[i] : 0.f; return; }
    i -= H2P;
    if (i < H2P) { g_s.l2bp[i] = (i < H2) ? l2b[i] : 0.f; return; }
    i -= H2P;
    if (i < H2P) { g_s.w30p[i] = (i < H2) ? W30[i] : 0.f; return; }
    i -= H2P;
    if (i < H2P) { g_s.w31p[i] = (i < H2) ? W31[i] : 0.f; return; }
}

// ---------------------------------------------------------------------------
// Stage-1 aggregation over fp16 x rows (cols [0,58) of xpA), writing fp16
// into xpA cols [64,128). Lane l covers cols {2l, 2l+1}; lanes 29..31 pad 0.
// ---------------------------------------------------------------------------
__global__ void aggx_kernel(const int* __restrict__ csr_src,
                            const float* __restrict__ csr_norm, const int* __restrict__ rowptr,
                            __half* __restrict__ xpA, int n) {
    int node = (blockIdx.x * blockDim.x + threadIdx.x) >> 5;
    int lane = threadIdx.x & 31;
    if (node >= n) return;
    int beg = rowptr[node], end = rowptr[node + 1];
    float a0 = 0.f, a1 = 0.f;
    bool act = (lane < 29);
    for (int j = beg; j < end; j++) {
        int s = csr_src[j];
        float w = csr_norm[j];
        if (act) {
            __half2 v = *reinterpret_cast<const __half2*>(xpA + (long)s * KA1 + 2 * lane);
            float2 f = __half22float2(v);
            a0 += f.x * w;
            a1 += f.y * w;
        }
    }
    long o = (long)node * KA1 + FP + 2 * lane;
    *reinterpret_cast<__half2*>(xpA + o) =
        __floats2half2_rn(act ? a0 : 0.f, act ? a1 : 0.f);
}

// ---------------------------------------------------------------------------
// agg2 over fp16 rows [N,128], live cols [0,100): out fp32 [N,128].
// ---------------------------------------------------------------------------
__global__ void agg2h_kernel(const __half* __restrict__ val, const int* __restrict__ csr_src,
                             const float* __restrict__ csr_norm, const int* __restrict__ rowptr,
                             float* __restrict__ out, int n) {
    int node = (blockIdx.x * blockDim.x + threadIdx.x) >> 5;
    int lane = threadIdx.x & 31;
    if (node >= n) return;
    int beg = rowptr[node], end = rowptr[node + 1];
    float a0 = 0.f, a1 = 0.f, a2 = 0.f, a3 = 0.f;
    bool act2 = (lane < 18);
    for (int j = beg; j < end; j++) {
        int s = csr_src[j];
        float w = csr_norm[j];
        const __half2* vr = reinterpret_cast<const __half2*>(val + (long)s * H2P);
        float2 f0 = __half22float2(vr[lane]);
        a0 += f0.x * w; a1 += f0.y * w;
        if (act2) {
            float2 f1 = __half22float2(vr[32 + lane]);
            a2 += f1.x * w; a3 += f1.y * w;
        }
    }
    float* orow = out + (long)node * H2P;
    orow[2 * lane]      = a0;
    orow[2 * lane + 1]  = a1;
    orow[64 + 2 * lane] = act2 ? a2 : 0.f;
    orow[65 + 2 * lane] = act2 ? a3 : 0.f;
}

// ---------------------------------------------------------------------------
// Single-pass fp16 tensor-core GEMM. BM=128, BN=64, BK=32, 8 warps 32x32.
// MODE 1: Cb = fp16(relu(acc + bias1)), stride M
// MODE 4: x1 = relu(addm + addm2 + bias3)
//         xm = x1 + relu(acc1 + bias1); s0 += xm.w30, s1 += xm.w31 (atomic)
//         Cb = fp16(x1 + relu(acc2 + bias2)) at stride ZS, cols < ZS  [z]
// MODE 5: c<128 -> Cb[r*128+c] = fp16(acc); else C1[r*128+(c-128)] = acc
// ---------------------------------------------------------------------------
template <int MODE, bool DUALOUT, bool OUTFP16>
__global__ __launch_bounds__(256)
void hgemm_kernel(const __half* __restrict__ A, int lda, int K,
                  const __half* __restrict__ B1, const __half* __restrict__ B2,
                  const float* __restrict__ addm, const float* __restrict__ addm2,
                  const float* __restrict__ bias1, const float* __restrict__ bias2,
                  const float* __restrict__ bias3,
                  const float* __restrict__ w30, const float* __restrict__ w31,
                  float* __restrict__ C1, float* __restrict__ S0, float* __restrict__ S1,
                  __half* __restrict__ Cb,
                  int Nr, int M) {
    __shared__ __align__(16) __half As[128][40];
    __shared__ __align__(16) __half Bs[32][72];
    __shared__ __align__(16) __half Bs2[32][72];

    int tid = threadIdx.x;
    int bm = blockIdx.y * 128, bn = blockIdx.x * 64;
    int lane = tid & 31, wid = tid >> 5;
    int wm = (wid >> 1) * 32, wn = (wid & 1) * 32;

    float acc[2][4][4];
    float acc2[2][4][4];
    #pragma unroll
    for (int mf = 0; mf < 2; mf++)
        #pragma unroll
        for (int nf = 0; nf < 4; nf++)
            #pragma unroll
            for (int q = 0; q < 4; q++) { acc[mf][nf][q] = 0.f; acc2[mf][nf][q] = 0.f; }

    for (int k0 = 0; k0 < K; k0 += 32) {
        #pragma unroll
        for (int i = 0; i < 2; i++) {
            int c = tid * 2 + i;
            int row = c >> 2, seg = c & 3;
            int gr = bm + row;
            uint4 vh = make_uint4(0, 0, 0, 0);
            if (gr < Nr)
                vh = *reinterpret_cast<const uint4*>(A + (long)gr * lda + k0 + seg * 8);
            *reinterpret_cast<uint4*>(&As[row][seg * 8]) = vh;
        }
        {
            int row = tid >> 3, seg = tid & 7;
            long off = (long)(k0 + row) * M + bn + seg * 8;
            *reinterpret_cast<uint4*>(&Bs[row][seg * 8]) =
                *reinterpret_cast<const uint4*>(B1 + off);
            if constexpr (DUALOUT) {
                *reinterpret_cast<uint4*>(&Bs2[row][seg * 8]) =
                    *reinterpret_cast<const uint4*>(B2 + off);
            }
        }
        __syncthreads();

        #pragma unroll
        for (int s = 0; s < 32; s += 16) {
            uint32_t a[2][4];
            #pragma unroll
            for (int mf = 0; mf < 2; mf++) {
                int row = wm + mf * 16 + (lane & 15);
                int col = s + ((lane >> 4) << 3);
                ldm_x4(a[mf], smem_u32(&As[row][col]));
            }
            int kr = s + (lane & 7) + (lane & 8);
            int nshift = (lane >> 4) << 3;
            uint32_t b[4][2];
            #pragma unroll
            for (int g = 0; g < 2; g++) {
                int nc = wn + g * 16 + nshift;
                uint32_t r[4];
                ldm_x4_t(r, smem_u32(&Bs[kr][nc]));
                b[g * 2][0] = r[0]; b[g * 2][1] = r[1];
                b[g * 2 + 1][0] = r[2]; b[g * 2 + 1][1] = r[3];
            }
            #pragma unroll
            for (int mf = 0; mf < 2; mf++)
                #pragma unroll
                for (int nf = 0; nf < 4; nf++)
                    mma_fp16(acc[mf][nf], a[mf], b[nf]);
            if constexpr (DUALOUT) {
                uint32_t b2[4][2];
                #pragma unroll
                for (int g = 0; g < 2; g++) {
                    int nc = wn + g * 16 + nshift;
                    uint32_t r[4];
                    ldm_x4_t(r, smem_u32(&Bs2[kr][nc]));
                    b2[g * 2][0] = r[0]; b2[g * 2][1] = r[1];
                    b2[g * 2 + 1][0] = r[2]; b2[g * 2 + 1][1] = r[3];
                }
                #pragma unroll
                for (int mf = 0; mf < 2; mf++)
                    #pragma unroll
                    for (int nf = 0; nf < 4; nf++)
                        mma_fp16(acc2[mf][nf], a[mf], b2[nf]);
            }
        }
        __syncthreads();
    }

    // --- epilogue
    int gid = lane >> 2, tig = lane & 3;
    if constexpr (MODE == 4) {
        #pragma unroll
        for (int mf = 0; mf < 2; mf++) {
            #pragma unroll
            for (int half_i = 0; half_i < 2; half_i++) {
                int r = bm + wm + mf * 16 + gid + half_i * 8;
                bool valid = (r < Nr);
                float p0 = 0.f, p1 = 0.f;
                #pragma unroll
                for (int nf = 0; nf < 4; nf++) {
                    int c = bn + wn + nf * 8 + tig * 2;
                    if (valid) {
                        long base = (long)r * H2P + c;
                        float x10 = fmaxf(addm[base]     + addm2[base]     + bias3[c],     0.f);
                        float x11 = fmaxf(addm[base + 1] + addm2[base + 1] + bias3[c + 1], 0.f);
                        float xm0 = x10 + fmaxf(acc[mf][nf][half_i * 2 + 0] + bias1[c],     0.f);
                        float xm1 = x11 + fmaxf(acc[mf][nf][half_i * 2 + 1] + bias1[c + 1], 0.f);
                        p0 += xm0 * w30[c] + xm1 * w30[c + 1];
                        p1 += xm0 * w31[c] + xm1 * w31[c + 1];
                        if (c < ZS) {
                            float z0 = x10 + fmaxf(acc2[mf][nf][half_i * 2 + 0] + bias2[c],     0.f);
                            float z1 = x11 + fmaxf(acc2[mf][nf][half_i * 2 + 1] + bias2[c + 1], 0.f);
                            Cb[(long)r * ZS + c]     = __float2half(z0);
                            Cb[(long)r * ZS + c + 1] = __float2half(z1);
                        }
                    }
                }
                p0 += __shfl_down_sync(0xFFFFFFFFu, p0, 1);
                p0 += __shfl_down_sync(0xFFFFFFFFu, p0, 2);
                p1 += __shfl_down_sync(0xFFFFFFFFu, p1, 1);
                p1 += __shfl_down_sync(0xFFFFFFFFu, p1, 2);
                if (tig == 0 && valid) {
                    atomicAdd(&S0[r], p0);
                    atomicAdd(&S1[r], p1);
                }
            }
        }
    } else {
        #pragma unroll
        for (int mf = 0; mf < 2; mf++) {
            #pragma unroll
            for (int nf = 0; nf < 4; nf++) {
                int c = bn + wn + nf * 8 + tig * 2;
                float bv0 = 0.f, bv1 = 0.f;
                if constexpr (MODE == 1) { bv0 = bias1[c]; bv1 = bias1[c + 1]; }
                #pragma unroll
                for (int half_i = 0; half_i < 2; half_i++) {
                    int r = bm + wm + mf * 16 + gid + half_i * 8;
                    if (r >= Nr) continue;
                    float v0 = acc[mf][nf][half_i * 2 + 0];
                    float v1 = acc[mf][nf][half_i * 2 + 1];
                    if constexpr (MODE == 5) {
                        if (c < H2P) {
                            long base = (long)r * H2P + c;
                            Cb[base]     = __float2half(v0);
                            Cb[base + 1] = __float2half(v1);
                        } else {
                            long base = (long)r * H2P + (c - H2P);
                            C1[base] = v0; C1[base + 1] = v1;
                        }
                    } else {
                        long base = (long)r * M + c;
                        if constexpr (MODE == 1) {
                            v0 = fmaxf(v0 + bv0, 0.f);
                            v1 = fmaxf(v1 + bv1, 0.f);
                        }
                        if constexpr (OUTFP16) {
                            Cb[base]     = __float2half(v0);
                            Cb[base + 1] = __float2half(v1);
                        } else {
                            C1[base] = v0; C1[base + 1] = v1;
                        }
                    }
                }
            }
        }
    }
}

// ---------------------------------------------------------------------------
// Merged pos+neg edge score loss over compact fp16 z (stride ZS=104).
// 16 lanes per edge, 2 edges per warp iteration.
// ---------------------------------------------------------------------------
__global__ void score_kernel(const __half* __restrict__ zb, const int* __restrict__ ei,
                             const int* __restrict__ nei, int E_, float* __restrict__ accum) {
    int lane = threadIdx.x & 31;
    int grp = lane >> 4;
    int l = lane & 15;
    int warp_global = (blockIdx.x * blockDim.x + threadIdx.x) >> 5;
    int nwarps = (gridDim.x * blockDim.x) >> 5;
    int total = 2 * E_;
    float psum = 0.f, nsum = 0.f;
    for (int t0 = warp_global * 2; t0 < total; t0 += nwarps * 2) {
        int t = t0 + grp;
        float dot = 0.f;
        int which = 0;
        if (t < total) {
            which = (t >= E_);
            const int* p = which ? nei : ei;
            int e = which ? t - E_ : t;
            int a = p[e], b = p[e + E_];
            if (l < 13) {
                uint4 ua = reinterpret_cast<const uint4*>(zb + (long)a * ZS)[l];
                uint4 ub = reinterpret_cast<const uint4*>(zb + (long)b * ZS)[l];
                const __half2* ha = reinterpret_cast<const __half2*>(&ua);
                const __half2* hb = reinterpret_cast<const __half2*>(&ub);
                #pragma unroll
                for (int q = 0; q < 4; q++) {
                    float2 fa = __half22float2(ha[q]);
                    float2 fb = __half22float2(hb[q]);
                    dot += fa.x * fb.x + fa.y * fb.y;
                }
            }
        }
        #pragma unroll
        for (int dd = 8; dd; dd >>= 1) dot += __shfl_down_sync(0xFFFFFFFFu, dot, dd);
        if (l == 0 && t < total) {
            float sig = 1.f / (1.f + expf(-dot));
            if (which) nsum += logf(1.f - sig + 1e-15f);
            else       psum += logf(sig + 1e-15f);
        }
    }
    psum += __shfl_down_sync(0xFFFFFFFFu, psum, 16);
    nsum += __shfl_down_sync(0xFFFFFFFFu, nsum, 16);
    __shared__ float redp[32], redn[32];
    if (lane == 0) { redp[threadIdx.x >> 5] = psum; redn[threadIdx.x >> 5] = nsum; }
    __syncthreads();
    if (threadIdx.x < 32) {
        int nw = blockDim.x >> 5;
        float vp = (threadIdx.x < nw) ? redp[threadIdx.x] : 0.f;
        float vn = (threadIdx.x < nw) ? redn[threadIdx.x] : 0.f;
        #pragma unroll
        for (int dd = 16; dd; dd >>= 1) {
            vp += __shfl_down_sync(0xFFFFFFFFu, vp, dd);
            vn += __shfl_down_sync(0xFFFFFFFFu, vn, dd);
        }
        if (threadIdx.x == 0) {
            atomicAdd(&accum[0], vp);
            atomicAdd(&accum[1], vn);
        }
    }
}

// ---------------------------------------------------------------------------
// Final: out[i] = s0[i] + Agg(s1)[i] + b3 (F=1 aggregation fused).
// ---------------------------------------------------------------------------
__global__ void agg1final_kernel(const float* __restrict__ s0, const float* __restrict__ s1,
                                 const int* __restrict__ csr_src, const float* __restrict__ csr_norm,
                                 const int* __restrict__ rowptr, const float* __restrict__ b3,
                                 const float* __restrict__ accum, const float* __restrict__ c1,
                                 const float* __restrict__ c2, float* __restrict__ out,
                                 int n, float invE) {
    int i = blockIdx.x * blockDim.x + threadIdx.x;
    if (i < n) {
        float a = 0.f;
        int end = rowptr[i + 1];
        for (int j = rowptr[i]; j < end; j++)
            a += s1[csr_src[j]] * csr_norm[j];
        out[i] = s0[i] + a + b3[0];
    }
    if (i == 0) {
        out[n] = -(accum[0] + accum[1]) * invE;
        out[n + 1] = c1[0];
        out[n + 2] = c2[0];
    }
}

// ---------------------------------------------------------------------------
// Launch
// ---------------------------------------------------------------------------
extern "C" void kernel_launch(void* const* d_in, const int* in_sizes, int n_in,
                              void* d_out, int out_size) {
    const float* x      = (const float*)d_in[0];
    const int*   ei     = (const int*)d_in[1];
    const int*   nei    = (const int*)d_in[2];
    const float* W1_0   = (const float*)d_in[3];
    const float* W1_1   = (const float*)d_in[4];
    const float* b1     = (const float*)d_in[5];
    const float* W2_0   = (const float*)d_in[6];
    const float* W2_1   = (const float*)d_in[7];
    const float* b2     = (const float*)d_in[8];
    const float* W3_0   = (const float*)d_in[9];
    const float* W3_1   = (const float*)d_in[10];
    const float* b3     = (const float*)d_in[11];
    const float* lin1_W = (const float*)d_in[12];
    const float* lin1_b = (const float*)d_in[13];
    const float* lin2_W = (const float*)d_in[14];
    const float* lin2_b = (const float*)d_in[15];
    const float* c1     = (const float*)d_in[16];
    const float* c2     = (const float*)d_in[17];
    float* out = (float*)d_out;

    int n = in_sizes[0] / F_IN;   // 50000
    int e = in_sizes[1] / 2;      // 800000

    Scratch* sp = nullptr;
    cudaGetSymbolAddress((void**)&sp, g_s);

    const int* src = ei;
    const int* dst = ei + e;

    int nb_n = (n + 255) / 256;
    int nb_e = (e + 255) / 256;
    int agg_blocks = (n * 32 + 255) / 256;
    int nb_scan = (n + 1023) / 1024;
    int gy = (n + 127) / 128;

    // Setup + CSR
    pad_xc_kernel<<<(n * FP + 255) / 256, 256>>>(x, n);
    hist_kernel<<<nb_e, 256>>>(src, dst, sp->deg, sp->cnt, e);
    scan1dis_kernel<<<nb_scan, 1024>>>(sp->cnt, sp->deg, sp->rowptr, sp->bsum, sp->dis, n);
    scan2_kernel<<<1, 32>>>(sp->bsum, sp->boff, sp->rowptr, nb_scan, n);
    scan3_kernel<<<nb_scan, 1024>>>(sp->rowptr, sp->cursor, sp->boff, n);
    fill_kernel<<<nb_e, 256>>>(src, dst, sp->dis, sp->cursor, sp->csr_src, sp->csr_norm, e);

    // Weight conversion (single kernel)
    convall_kernel<<<(CTOT + 255) / 256, 256>>>(W1_0, W1_1, W2_0, W2_1, lin1_W, lin2_W,
                                                b1, b2, lin1_b, lin2_b, W3_0, W3_1);

    // Stage 1 aggregation (fp16 source) -> xpA cols [64,128)
    aggx_kernel<<<agg_blocks, 256>>>(sp->csr_src, sp->csr_norm, sp->rowptr, sp->xpA, n);

    // G1: h(fp16) = relu([xp|tx1] @ W1cat + b1)   K=128, M=320
    hgemm_kernel<1, false, true><<<dim3(H1P / 64, gy), 256>>>(
        sp->xpA, KA1, KA1, sp->W1c, nullptr, nullptr, nullptr,
        sp->b1p, nullptr, nullptr, nullptr, nullptr,
        nullptr, nullptr, nullptr, sp->h_fp, n, H1P);

    // G2 (MODE 5): hW21f(fp16) | hW20(fp32) = h @ [W2_1 | W2_0]   K=320, M=256
    hgemm_kernel<5, false, false><<<dim3(M2B / 64, gy), 256>>>(
        sp->h_fp, KH, KH, sp->W2c, nullptr, nullptr, nullptr,
        nullptr, nullptr, nullptr, nullptr, nullptr,
        sp->hW20, nullptr, nullptr, sp->hW21f, n, M2B);

    // agg2 = Agg(hW21f) over fp16 rows (live cols 0..99)
    agg2h_kernel<<<agg_blocks, 256>>>(sp->hW21f, sp->csr_src, sp->csr_norm,
                                      sp->rowptr, sp->agg2, n);

    // G4 (MODE 4): s0/s1 += (x1 + relu(xp@L1+b)) . W3_{0,1};
    //              z = fp16(x1 + relu(xp@L2+b)) compact;
    //              x1 = relu(hW20 + agg2 + b2) in epilogue
    hgemm_kernel<4, true, false><<<dim3(H2P / 64, gy), 256>>>(
        sp->xpA, KA1, FP, sp->L1, sp->L2, sp->hW20, sp->agg2,
        sp->l1bp, sp->l2bp, sp->b2p, sp->w30p, sp->w31p,
        nullptr, sp->s0, sp->s1, sp->z_fp, n, H2P);

    // Losses + final
    score_kernel<<<2048, 256>>>(sp->z_fp, ei, nei, e, sp->accum);
    agg1final_kernel<<<nb_n, 256>>>(sp->s0, sp->s1, sp->csr_src, sp->csr_norm, sp->rowptr,
                                    b3, sp->accum, c1, c2, out, n, 1.0f / (float)e);
}

// round 10
// speedup vs baseline: 2.2232x; 1.0559x over previous
#include <cuda_runtime.h>
#include <cuda_fp16.h>
#include <cstdint>
#include <math.h>

#define NN 50000
#define EE 800000
#define F_IN 58
#define FP 64
#define H1 300
#define H2 100
#define H1P 320
#define H2P 128
#define KA1 128   // GEMM1 K: [xp|tx1]
#define KH 320    // padded K for fused stage-2 GEMM
#define M2B 256   // fused stage-2 GEMM logical N: [W2_1|W2_0]
#define ZS 104    // compact z row stride (halves); cols 100..103 == 0

// ---------------------------------------------------------------------------
// Scratch (device-global, no runtime allocation).
// ---------------------------------------------------------------------------
struct alignas(16) Scratch {
    int   deg[NN];
    int   cnt[NN];
    int   rowptr[NN + 4];
    int   cursor[NN];
    int   csr_src[EE];
    float csr_norm[EE];
    int   bsum[64];
    float dis[NN];
    __half xpA[NN * KA1];    // [x_fp16 | Agg(x)] fp16
    __half h_fp[NN * KH];    // relu(cheb1) fp16, [N,320]
    __half hW21f[NN * H2P];  // h @ W2_1 (fp16, gathered by agg2)
    __half hW20h[NN * H2P];  // h @ W2_0 (fp16)
    float agg2[NN * H2P];
    __half z_fp[NN * ZS];    // compact fp16 z
    __half W1c[KA1 * H1P];   // [128,320]
    __half W2c[KH * M2B];    // [320,256]
    __half L1[FP * H2P];     // [64,128]
    __half L2[FP * H2P];
    float b1p[H1P], b2p[H2P], l1bp[H2P], l2bp[H2P];
    float w30p[H2P], w31p[H2P];
    float s0[NN], s1[NN];
    float accum[2];
};
__device__ Scratch g_s;

// ---------------------------------------------------------------------------
// PTX helpers
// ---------------------------------------------------------------------------
__device__ __forceinline__ uint32_t smem_u32(const void* p) {
    return (uint32_t)__cvta_generic_to_shared(p);
}
__device__ __forceinline__ void ldm_x4(uint32_t* r, uint32_t addr) {
    asm volatile("ldmatrix.sync.aligned.m8n8.x4.shared.b16 {%0,%1,%2,%3}, [%4];"
                 : "=r"(r[0]), "=r"(r[1]), "=r"(r[2]), "=r"(r[3]) : "r"(addr));
}
__device__ __forceinline__ void ldm_x4_t(uint32_t* r, uint32_t addr) {
    asm volatile("ldmatrix.sync.aligned.m8n8.x4.trans.shared.b16 {%0,%1,%2,%3}, [%4];"
                 : "=r"(r[0]), "=r"(r[1]), "=r"(r[2]), "=r"(r[3]) : "r"(addr));
}
__device__ __forceinline__ void mma_fp16(float* c, const uint32_t* a, const uint32_t* b) {
    asm volatile("mma.sync.aligned.m16n8k16.row.col.f32.f16.f16.f32 "
                 "{%0,%1,%2,%3}, {%4,%5,%6,%7}, {%8,%9}, {%0,%1,%2,%3};"
                 : "+f"(c[0]), "+f"(c[1]), "+f"(c[2]), "+f"(c[3])
                 : "r"(a[0]), "r"(a[1]), "r"(a[2]), "r"(a[3]), "r"(b[0]), "r"(b[1]));
}
__device__ __forceinline__ void cp_async16(uint32_t dst, const void* src, bool pred) {
    int sz = pred ? 16 : 0;
    asm volatile("cp.async.cg.shared.global [%0], [%1], 16, %2;\n"
                 :: "r"(dst), "l"(src), "r"(sz));
}
__device__ __forceinline__ void cp_commit() {
    asm volatile("cp.async.commit_group;\n");
}
template <int N>
__device__ __forceinline__ void cp_wait() {
    asm volatile("cp.async.wait_group %0;\n" :: "n"(N));
}

// ---------------------------------------------------------------------------
// pad_xc: zero deg/cnt/accum/s0/s1; write xpA cols [0,64) fp16.
// ---------------------------------------------------------------------------
__global__ void pad_xc_kernel(const float* __restrict__ x, int n) {
    int i = blockIdx.x * blockDim.x + threadIdx.x;
    if (i < n) { g_s.deg[i] = 0; g_s.cnt[i] = 0; g_s.s0[i] = 0.f; g_s.s1[i] = 0.f; }
    if (i < 2) g_s.accum[i] = 0.f;
    if (i >= n * FP) return;
    int r = i >> 6, f = i & 63;
    float v = (f < F_IN) ? x[(long)r * F_IN + f] : 0.f;
    g_s.xpA[(long)r * KA1 + f] = __float2half(v);
}

__global__ void hist_kernel(const int* __restrict__ src, const int* __restrict__ dst,
                            int* deg, int* cnt, int e) {
    int i = blockIdx.x * blockDim.x + threadIdx.x;
    if (i < e) {
        atomicAdd(&deg[src[i]], 1);
        atomicAdd(&cnt[dst[i]], 1);
    }
}

// scan stage 1 (+ dis folded in)
__global__ void scan1dis_kernel(const int* __restrict__ cnt, const int* __restrict__ deg,
                                int* __restrict__ rowptr, int* __restrict__ bsum,
                                float* __restrict__ dis, int n) {
    __shared__ int warp_sums[32];
    int tid = threadIdx.x;
    int i = blockIdx.x * 1024 + tid;
    if (i < n) {
        int d = deg[i];
        dis[i] = (d > 0) ? (1.0f / sqrtf((float)d)) : 0.0f;
    }
    int v = (i < n) ? cnt[i] : 0;
    int x = v;
    #pragma unroll
    for (int d = 1; d < 32; d <<= 1) {
        int y = __shfl_up_sync(0xFFFFFFFFu, x, d);
        if ((tid & 31) >= d) x += y;
    }
    if ((tid & 31) == 31) warp_sums[tid >> 5] = x;
    __syncthreads();
    if (tid < 32) {
        int y = warp_sums[tid];
        int zz = y;
        #pragma unroll
        for (int d = 1; d < 32; d <<= 1) {
            int w = __shfl_up_sync(0xFFFFFFFFu, zz, d);
            if (tid >= d) zz += w;
        }
        warp_sums[tid] = zz - y;
    }
    __syncthreads();
    int incl = x + warp_sums[tid >> 5];
    if (i < n) rowptr[i] = incl - v;
    if (tid == 1023) bsum[blockIdx.x] = incl;
}

// scan stages 2+3 merged: each block prefixes bsum locally.
__global__ void scan23_kernel(int* __restrict__ rowptr, int* __restrict__ cursor,
                              const int* __restrict__ bsum, int nb, int n) {
    __shared__ int s_off;
    int b = blockIdx.x;
    if (threadIdx.x == 0) {
        int run = 0;
        for (int j = 0; j < b; j++) run += bsum[j];
        s_off = run;
        if (b == nb - 1) rowptr[n] = run + bsum[b];
    }
    __syncthreads();
    int i = b * 1024 + threadIdx.x;
    if (i < n) {
        int v = rowptr[i] + s_off;
        rowptr[i] = v;
        cursor[i] = v;
    }
}

__global__ void fill_kernel(const int* __restrict__ src, const int* __restrict__ dst,
                            const float* __restrict__ dis, int* __restrict__ cursor,
                            int* __restrict__ csr_src, float* __restrict__ csr_norm, int e) {
    int i = blockIdx.x * blockDim.x + threadIdx.x;
    if (i < e) {
        int s = src[i], d = dst[i];
        int p = atomicAdd(&cursor[d], 1);
        csr_src[p] = s;
        csr_norm[p] = -(dis[s] * dis[d]);
    }
}

// ---------------------------------------------------------------------------
// All weight/bias conversions in ONE kernel (fp16 + padded fp32 vectors).
// ---------------------------------------------------------------------------
#define CN1 (KA1 * H1P)
#define CN2 (KH * M2B)
#define CN3 (FP * H2P)
#define CTOT (CN1 + CN2 + 2 * CN3 + H1P + 5 * H2P)
__global__ void convall_kernel(const float* __restrict__ W10, const float* __restrict__ W11,
                               const float* __restrict__ W20, const float* __restrict__ W21,
                               const float* __restrict__ l1W, const float* __restrict__ l2W,
                               const float* __restrict__ b1, const float* __restrict__ b2,
                               const float* __restrict__ l1b, const float* __restrict__ l2b,
                               const float* __restrict__ W30, const float* __restrict__ W31) {
    int i = blockIdx.x * blockDim.x + threadIdx.x;
    if (i < CN1) {
        int k = i / H1P, m = i % H1P;
        float v = 0.f;
        if (m < H1) {
            if (k < F_IN) v = W10[k * H1 + m];
            else if (k >= FP && k < FP + F_IN) v = W11[(k - FP) * H1 + m];
        }
        g_s.W1c[i] = __float2half(v);
        return;
    }
    i -= CN1;
    if (i < CN2) {
        int k = i / M2B, m = i % M2B;
        float v = 0.f;
        if (k < H1) {
            if (m < H2P) { if (m < H2) v = W21[k * H2 + m]; }
            else { int mm = m - H2P; if (mm < H2) v = W20[k * H2 + mm]; }
        }
        g_s.W2c[i] = __float2half(v);
        return;
    }
    i -= CN2;
    if (i < CN3) {
        int k = i >> 7, m = i & 127;
        float v = (k < F_IN && m < H2) ? l1W[m * F_IN + k] : 0.f;
        g_s.L1[i] = __float2half(v);
        return;
    }
    i -= CN3;
    if (i < CN3) {
        int k = i >> 7, m = i & 127;
        float v = (k < F_IN && m < H2) ? l2W[m * F_IN + k] : 0.f;
        g_s.L2[i] = __float2half(v);
        return;
    }
    i -= CN3;
    if (i < H1P) { g_s.b1p[i] = (i < H1) ? b1[i] : 0.f; return; }
    i -= H1P;
    if (i < H2P) { g_s.b2p[i] = (i < H2) ? b2[i] : 0.f; return; }
    i -= H2P;
    if (i < H2P) { g_s.l1bp[i] = (i < H2) ? l1b[i] : 0.f; return; }
    i -= H2P;
    if (i < H2P) { g_s.l2bp[i] = (i < H2) ? l2b[i] : 0.f; return; }
    i -= H2P;
    if (i < H2P) { g_s.w30p[i] = (i < H2) ? W30[i] : 0.f; return; }
    i -= H2P;
    if (i < H2P) { g_s.w31p[i] = (i < H2) ? W31[i] : 0.f; return; }
}

// ---------------------------------------------------------------------------
// Stage-1 aggregation over fp16 x rows (cols [0,58) of xpA), writing fp16
// into xpA cols [64,128). Lane l covers cols {2l, 2l+1}; lanes 29..31 pad 0.
// ---------------------------------------------------------------------------
__global__ void aggx_kernel(const int* __restrict__ csr_src,
                            const float* __restrict__ csr_norm, const int* __restrict__ rowptr,
                            __half* __restrict__ xpA, int n) {
    int node = (blockIdx.x * blockDim.x + threadIdx.x) >> 5;
    int lane = threadIdx.x & 31;
    if (node >= n) return;
    int beg = rowptr[node], end = rowptr[node + 1];
    float a0 = 0.f, a1 = 0.f;
    bool act = (lane < 29);
    for (int j = beg; j < end; j++) {
        int s = csr_src[j];
        float w = csr_norm[j];
        if (act) {
            __half2 v = *reinterpret_cast<const __half2*>(xpA + (long)s * KA1 + 2 * lane);
            float2 f = __half22float2(v);
            a0 += f.x * w;
            a1 += f.y * w;
        }
    }
    long o = (long)node * KA1 + FP + 2 * lane;
    *reinterpret_cast<__half2*>(xpA + o) =
        __floats2half2_rn(act ? a0 : 0.f, act ? a1 : 0.f);
}

// ---------------------------------------------------------------------------
// agg2 over fp16 rows [N,128], live cols [0,100): out fp32 [N,128].
// ---------------------------------------------------------------------------
__global__ void agg2h_kernel(const __half* __restrict__ val, const int* __restrict__ csr_src,
                             const float* __restrict__ csr_norm, const int* __restrict__ rowptr,
                             float* __restrict__ out, int n) {
    int node = (blockIdx.x * blockDim.x + threadIdx.x) >> 5;
    int lane = threadIdx.x & 31;
    if (node >= n) return;
    int beg = rowptr[node], end = rowptr[node + 1];
    float a0 = 0.f, a1 = 0.f, a2 = 0.f, a3 = 0.f;
    bool act2 = (lane < 18);
    for (int j = beg; j < end; j++) {
        int s = csr_src[j];
        float w = csr_norm[j];
        const __half2* vr = reinterpret_cast<const __half2*>(val + (long)s * H2P);
        float2 f0 = __half22float2(vr[lane]);
        a0 += f0.x * w; a1 += f0.y * w;
        if (act2) {
            float2 f1 = __half22float2(vr[32 + lane]);
            a2 += f1.x * w; a3 += f1.y * w;
        }
    }
    float* orow = out + (long)node * H2P;
    orow[2 * lane]      = a0;
    orow[2 * lane + 1]  = a1;
    orow[64 + 2 * lane] = act2 ? a2 : 0.f;
    orow[65 + 2 * lane] = act2 ? a3 : 0.f;
}

// ---------------------------------------------------------------------------
// Double-buffered (cp.async) fp16 tensor-core GEMM.
// BM=128, BN=64, BK=32, 8 warps 32x32 each, 2 smem stages.
// MODE 1: Cb = fp16(relu(acc + bias1)), stride M
// MODE 4: x1 = relu(addmh + addm2 + bias3)
//         xm = x1 + relu(acc1 + bias1); s0 += xm.w30, s1 += xm.w31 (atomic)
//         Cb = fp16(x1 + relu(acc2 + bias2)) at stride ZS, cols < ZS  [z]
// MODE 5: c<128 -> Cb[r*128+c] = fp16(acc); else Cb2[r*128+(c-128)] = fp16(acc)
// ---------------------------------------------------------------------------
template <int MODE, bool DUALOUT>
__global__ __launch_bounds__(256)
void hgemm_kernel(const __half* __restrict__ A, int lda, int K,
                  const __half* __restrict__ B1, const __half* __restrict__ B2,
                  const __half* __restrict__ addmh, const float* __restrict__ addm2,
                  const float* __restrict__ bias1, const float* __restrict__ bias2,
                  const float* __restrict__ bias3,
                  const float* __restrict__ w30, const float* __restrict__ w31,
                  float* __restrict__ S0, float* __restrict__ S1,
                  __half* __restrict__ Cb, __half* __restrict__ Cb2,
                  int Nr, int M) {
    __shared__ __align__(16) __half As[2][128][40];
    __shared__ __align__(16) __half Bs[2][32][72];
    __shared__ __align__(16) __half Bs2[DUALOUT ? 2 : 1][32][72];

    int tid = threadIdx.x;
    int bm = blockIdx.y * 128, bn = blockIdx.x * 64;
    int lane = tid & 31, wid = tid >> 5;
    int wm = (wid >> 1) * 32, wn = (wid & 1) * 32;

    // loader indices
    int a_row = tid >> 1;            // 0..127 (2 threads per row)
    int a_seg = (tid & 1) * 2;       // segs {0,1} or {2,3}
    int b_row = tid >> 3, b_seg = tid & 7;

    float acc[2][4][4];
    float acc2[2][4][4];
    #pragma unroll
    for (int mf = 0; mf < 2; mf++)
        #pragma unroll
        for (int nf = 0; nf < 4; nf++)
            #pragma unroll
            for (int q = 0; q < 4; q++) { acc[mf][nf][q] = 0.f; acc2[mf][nf][q] = 0.f; }

    int nIter = K >> 5;

    auto load_stage = [&](int it, int stg) {
        int k0 = it << 5;
        bool ok = (bm + a_row) < Nr;
        long aoff = (long)(bm + a_row) * lda + k0 + a_seg * 8;
        cp_async16(smem_u32(&As[stg][a_row][a_seg * 8]), A + aoff, ok);
        cp_async16(smem_u32(&As[stg][a_row][(a_seg + 1) * 8]), A + aoff + 8, ok);
        long boff = (long)(k0 + b_row) * M + bn + b_seg * 8;
        cp_async16(smem_u32(&Bs[stg][b_row][b_seg * 8]), B1 + boff, true);
        if constexpr (DUALOUT)
            cp_async16(smem_u32(&Bs2[stg][b_row][b_seg * 8]), B2 + boff, true);
    };

    load_stage(0, 0);
    cp_commit();

    for (int it = 0; it < nIter; it++) {
        int stg = it & 1;
        if (it > 0) __syncthreads();  // prior compute done before overwriting its stage
        if (it + 1 < nIter) {
            load_stage(it + 1, (it + 1) & 1);
            cp_commit();
            cp_wait<1>();
        } else {
            cp_wait<0>();
        }
        __syncthreads();

        #pragma unroll
        for (int s = 0; s < 32; s += 16) {
            uint32_t a[2][4];
            #pragma unroll
            for (int mf = 0; mf < 2; mf++) {
                int row = wm + mf * 16 + (lane & 15);
                int col = s + ((lane >> 4) << 3);
                ldm_x4(a[mf], smem_u32(&As[stg][row][col]));
            }
            int kr = s + (lane & 7) + (lane & 8);
            int nshift = (lane >> 4) << 3;
            uint32_t b[4][2];
            #pragma unroll
            for (int g = 0; g < 2; g++) {
                int nc = wn + g * 16 + nshift;
                uint32_t r[4];
                ldm_x4_t(r, smem_u32(&Bs[stg][kr][nc]));
                b[g * 2][0] = r[0]; b[g * 2][1] = r[1];
                b[g * 2 + 1][0] = r[2]; b[g * 2 + 1][1] = r[3];
            }
            #pragma unroll
            for (int mf = 0; mf < 2; mf++)
                #pragma unroll
                for (int nf = 0; nf < 4; nf++)
                    mma_fp16(acc[mf][nf], a[mf], b[nf]);
            if constexpr (DUALOUT) {
                uint32_t b2[4][2];
                #pragma unroll
                for (int g = 0; g < 2; g++) {
                    int nc = wn + g * 16 + nshift;
                    uint32_t r[4];
                    ldm_x4_t(r, smem_u32(&Bs2[stg][kr][nc]));
                    b2[g * 2][0] = r[0]; b2[g * 2][1] = r[1];
                    b2[g * 2 + 1][0] = r[2]; b2[g * 2 + 1][1] = r[3];
                }
                #pragma unroll
                for (int mf = 0; mf < 2; mf++)
                    #pragma unroll
                    for (int nf = 0; nf < 4; nf++)
                        mma_fp16(acc2[mf][nf], a[mf], b2[nf]);
            }
        }
    }

    // --- epilogue
    int gid = lane >> 2, tig = lane & 3;
    if constexpr (MODE == 4) {
        #pragma unroll
        for (int mf = 0; mf < 2; mf++) {
            #pragma unroll
            for (int half_i = 0; half_i < 2; half_i++) {
                int r = bm + wm + mf * 16 + gid + half_i * 8;
                bool valid = (r < Nr);
                float p0 = 0.f, p1 = 0.f;
                #pragma unroll
                for (int nf = 0; nf < 4; nf++) {
                    int c = bn + wn + nf * 8 + tig * 2;
                    if (valid) {
                        long base = (long)r * H2P + c;
                        float ah0 = __half2float(addmh[base]);
                        float ah1 = __half2float(addmh[base + 1]);
                        float x10 = fmaxf(ah0 + addm2[base]     + bias3[c],     0.f);
                        float x11 = fmaxf(ah1 + addm2[base + 1] + bias3[c + 1], 0.f);
                        float xm0 = x10 + fmaxf(acc[mf][nf][half_i * 2 + 0] + bias1[c],     0.f);
                        float xm1 = x11 + fmaxf(acc[mf][nf][half_i * 2 + 1] + bias1[c + 1], 0.f);
                        p0 += xm0 * w30[c] + xm1 * w30[c + 1];
                        p1 += xm0 * w31[c] + xm1 * w31[c + 1];
                        if (c < ZS) {
                            float z0 = x10 + fmaxf(acc2[mf][nf][half_i * 2 + 0] + bias2[c],     0.f);
                            float z1 = x11 + fmaxf(acc2[mf][nf][half_i * 2 + 1] + bias2[c + 1], 0.f);
                            Cb[(long)r * ZS + c]     = __float2half(z0);
                            Cb[(long)r * ZS + c + 1] = __float2half(z1);
                        }
                    }
                }
                p0 += __shfl_down_sync(0xFFFFFFFFu, p0, 1);
                p0 += __shfl_down_sync(0xFFFFFFFFu, p0, 2);
                p1 += __shfl_down_sync(0xFFFFFFFFu, p1, 1);
                p1 += __shfl_down_sync(0xFFFFFFFFu, p1, 2);
                if (tig == 0 && valid) {
                    atomicAdd(&S0[r], p0);
                    atomicAdd(&S1[r], p1);
                }
            }
        }
    } else {
        #pragma unroll
        for (int mf = 0; mf < 2; mf++) {
            #pragma unroll
            for (int nf = 0; nf < 4; nf++) {
                int c = bn + wn + nf * 8 + tig * 2;
                float bv0 = 0.f, bv1 = 0.f;
                if constexpr (MODE == 1) { bv0 = bias1[c]; bv1 = bias1[c + 1]; }
                #pragma unroll
                for (int half_i = 0; half_i < 2; half_i++) {
                    int r = bm + wm + mf * 16 + gid + half_i * 8;
                    if (r >= Nr) continue;
                    float v0 = acc[mf][nf][half_i * 2 + 0];
                    float v1 = acc[mf][nf][half_i * 2 + 1];
                    if constexpr (MODE == 5) {
                        if (c < H2P) {
                            long base = (long)r * H2P + c;
                            Cb[base]     = __float2half(v0);
                            Cb[base + 1] = __float2half(v1);
                        } else {
                            long base = (long)r * H2P + (c - H2P);
                            Cb2[base]     = __float2half(v0);
                            Cb2[base + 1] = __float2half(v1);
                        }
                    } else {
                        long base = (long)r * M + c;
                        v0 = fmaxf(v0 + bv0, 0.f);
                        v1 = fmaxf(v1 + bv1, 0.f);
                        Cb[base]     = __float2half(v0);
                        Cb[base + 1] = __float2half(v1);
                    }
                }
            }
        }
    }
}

// ---------------------------------------------------------------------------
// Merged pos+neg edge score loss over compact fp16 z (stride ZS=104).
// 16 lanes per edge, 2 edges per warp iteration.
// ---------------------------------------------------------------------------
__global__ void score_kernel(const __half* __restrict__ zb, const int* __restrict__ ei,
                             const int* __restrict__ nei, int E_, float* __restrict__ accum) {
    int lane = threadIdx.x & 31;
    int grp = lane >> 4;
    int l = lane & 15;
    int warp_global = (blockIdx.x * blockDim.x + threadIdx.x) >> 5;
    int nwarps = (gridDim.x * blockDim.x) >> 5;
    int total = 2 * E_;
    float psum = 0.f, nsum = 0.f;
    for (int t0 = warp_global * 2; t0 < total; t0 += nwarps * 2) {
        int t = t0 + grp;
        float dot = 0.f;
        int which = 0;
        if (t < total) {
            which = (t >= E_);
            const int* p = which ? nei : ei;
            int e = which ? t - E_ : t;
            int a = p[e], b = p[e + E_];
            if (l < 13) {
                uint4 ua = reinterpret_cast<const uint4*>(zb + (long)a * ZS)[l];
                uint4 ub = reinterpret_cast<const uint4*>(zb + (long)b * ZS)[l];
                const __half2* ha = reinterpret_cast<const __half2*>(&ua);
                const __half2* hb = reinterpret_cast<const __half2*>(&ub);
                #pragma unroll
                for (int q = 0; q < 4; q++) {
                    float2 fa = __half22float2(ha[q]);
                    float2 fb = __half22float2(hb[q]);
                    dot += fa.x * fb.x + fa.y * fb.y;
                }
            }
        }
        #pragma unroll
        for (int dd = 8; dd; dd >>= 1) dot += __shfl_down_sync(0xFFFFFFFFu, dot, dd);
        if (l == 0 && t < total) {
            float sig = 1.f / (1.f + expf(-dot));
            if (which) nsum += logf(1.f - sig + 1e-15f);
            else       psum += logf(sig + 1e-15f);
        }
    }
    psum += __shfl_down_sync(0xFFFFFFFFu, psum, 16);
    nsum += __shfl_down_sync(0xFFFFFFFFu, nsum, 16);
    __shared__ float redp[32], redn[32];
    if (lane == 0) { redp[threadIdx.x >> 5] = psum; redn[threadIdx.x >> 5] = nsum; }
    __syncthreads();
    if (threadIdx.x < 32) {
        int nw = blockDim.x >> 5;
        float vp = (threadIdx.x < nw) ? redp[threadIdx.x] : 0.f;
        float vn = (threadIdx.x < nw) ? redn[threadIdx.x] : 0.f;
        #pragma unroll
        for (int dd = 16; dd; dd >>= 1) {
            vp += __shfl_down_sync(0xFFFFFFFFu, vp, dd);
            vn += __shfl_down_sync(0xFFFFFFFFu, vn, dd);
        }
        if (threadIdx.x == 0) {
            atomicAdd(&accum[0], vp);
            atomicAdd(&accum[1], vn);
        }
    }
}

// ---------------------------------------------------------------------------
// Final: out[i] = s0[i] + Agg(s1)[i] + b3 (F=1 aggregation fused).
// ---------------------------------------------------------------------------
__global__ void agg1final_kernel(const float* __restrict__ s0, const float* __restrict__ s1,
                                 const int* __restrict__ csr_src, const float* __restrict__ csr_norm,
                                 const int* __restrict__ rowptr, const float* __restrict__ b3,
                                 const float* __restrict__ accum, const float* __restrict__ c1,
                                 const float* __restrict__ c2, float* __restrict__ out,
                                 int n, float invE) {
    int i = blockIdx.x * blockDim.x + threadIdx.x;
    if (i < n) {
        float a = 0.f;
        int end = rowptr[i + 1];
        for (int j = rowptr[i]; j < end; j++)
            a += s1[csr_src[j]] * csr_norm[j];
        out[i] = s0[i] + a + b3[0];
    }
    if (i == 0) {
        out[n] = -(accum[0] + accum[1]) * invE;
        out[n + 1] = c1[0];
        out[n + 2] = c2[0];
    }
}

// ---------------------------------------------------------------------------
// Launch
// ---------------------------------------------------------------------------
extern "C" void kernel_launch(void* const* d_in, const int* in_sizes, int n_in,
                              void* d_out, int out_size) {
    const float* x      = (const float*)d_in[0];
    const int*   ei     = (const int*)d_in[1];
    const int*   nei    = (const int*)d_in[2];
    const float* W1_0   = (const float*)d_in[3];
    const float* W1_1   = (const float*)d_in[4];
    const float* b1     = (const float*)d_in[5];
    const float* W2_0   = (const float*)d_in[6];
    const float* W2_1   = (const float*)d_in[7];
    const float* b2     = (const float*)d_in[8];
    const float* W3_0   = (const float*)d_in[9];
    const float* W3_1   = (const float*)d_in[10];
    const float* b3     = (const float*)d_in[11];
    const float* lin1_W = (const float*)d_in[12];
    const float* lin1_b = (const float*)d_in[13];
    const float* lin2_W = (const float*)d_in[14];
    const float* lin2_b = (const float*)d_in[15];
    const float* c1     = (const float*)d_in[16];
    const float* c2     = (const float*)d_in[17];
    float* out = (float*)d_out;

    int n = in_sizes[0] / F_IN;   // 50000
    int e = in_sizes[1] / 2;      // 800000

    Scratch* sp = nullptr;
    cudaGetSymbolAddress((void**)&sp, g_s);

    const int* src = ei;
    const int* dst = ei + e;

    int nb_n = (n + 255) / 256;
    int nb_e = (e + 255) / 256;
    int agg_blocks = (n * 32 + 255) / 256;
    int nb_scan = (n + 1023) / 1024;
    int gy = (n + 127) / 128;

    // Setup + CSR
    pad_xc_kernel<<<(n * FP + 255) / 256, 256>>>(x, n);
    hist_kernel<<<nb_e, 256>>>(src, dst, sp->deg, sp->cnt, e);
    scan1dis_kernel<<<nb_scan, 1024>>>(sp->cnt, sp->deg, sp->rowptr, sp->bsum, sp->dis, n);
    scan23_kernel<<<nb_scan, 1024>>>(sp->rowptr, sp->cursor, sp->bsum, nb_scan, n);
    fill_kernel<<<nb_e, 256>>>(src, dst, sp->dis, sp->cursor, sp->csr_src, sp->csr_norm, e);

    // Weight conversion (single kernel)
    convall_kernel<<<(CTOT + 255) / 256, 256>>>(W1_0, W1_1, W2_0, W2_1, lin1_W, lin2_W,
                                                b1, b2, lin1_b, lin2_b, W3_0, W3_1);

    // Stage 1 aggregation (fp16 source) -> xpA cols [64,128)
    aggx_kernel<<<agg_blocks, 256>>>(sp->csr_src, sp->csr_norm, sp->rowptr, sp->xpA, n);

    // G1 (MODE 1): h(fp16) = relu([xp|tx1] @ W1cat + b1)   K=128, M=320
    hgemm_kernel<1, false><<<dim3(H1P / 64, gy), 256>>>(
        sp->xpA, KA1, KA1, sp->W1c, nullptr, nullptr, nullptr,
        sp->b1p, nullptr, nullptr, nullptr, nullptr,
        nullptr, nullptr, sp->h_fp, nullptr, n, H1P);

    // G2 (MODE 5): hW21f(fp16) | hW20h(fp16) = h @ [W2_1 | W2_0]   K=320, M=256
    hgemm_kernel<5, false><<<dim3(M2B / 64, gy), 256>>>(
        sp->h_fp, KH, KH, sp->W2c, nullptr, nullptr, nullptr,
        nullptr, nullptr, nullptr, nullptr, nullptr,
        nullptr, nullptr, sp->hW21f, sp->hW20h, n, M2B);

    // agg2 = Agg(hW21f) over fp16 rows (live cols 0..99)
    agg2h_kernel<<<agg_blocks, 256>>>(sp->hW21f, sp->csr_src, sp->csr_norm,
                                      sp->rowptr, sp->agg2, n);

    // G4 (MODE 4): s0/s1 += (x1 + relu(xp@L1+b)) . W3_{0,1};
    //              z = fp16(x1 + relu(xp@L2+b)) compact;
    //              x1 = relu(hW20h + agg2 + b2) in epilogue
    hgemm_kernel<4, true><<<dim3(H2P / 64, gy), 256>>>(
        sp->xpA, KA1, FP, sp->L1, sp->L2, sp->hW20h, sp->agg2,
        sp->l1bp, sp->l2bp, sp->b2p, sp->w30p, sp->w31p,
        sp->s0, sp->s1, sp->z_fp, nullptr, n, H2P);

    // Losses + final
    score_kernel<<<2048, 256>>>(sp->z_fp, ei, nei, e, sp->accum);
    agg1final_kernel<<<nb_n, 256>>>(sp->s0, sp->s1, sp->csr_src, sp->csr_norm, sp->rowptr,
                                    b3, sp->accum, c1, c2, out, n, 1.0f / (float)e);
}

// round 12
// speedup vs baseline: 2.2808x; 1.0259x over previous
#include <cuda_runtime.h>
#include <cuda_fp16.h>
#include <cstdint>
#include <math.h>

#define NN 50000
#define EE 800000
#define F_IN 58
#define FP 64
#define H1 300
#define H2 100
#define H1P 320
#define H2P 128
#define KA1 128   // GEMM1 K: [xp|tx1]
#define KH 320    // padded K for fused stage-2 GEMM
#define M2B 256   // fused stage-2 GEMM logical N: [W2_1|W2_0]
#define ZS 104    // compact z row stride (halves); cols 100..103 == 0

// ---------------------------------------------------------------------------
// Scratch (device-global, no runtime allocation).
// ---------------------------------------------------------------------------
struct alignas(16) Scratch {
    int   deg[NN];
    int   cnt[NN];
    int   rowptr[NN + 4];
    int   cursor[NN];
    int   csr_src[EE];
    float csr_norm[EE];
    int   bsum[64];
    float dis[NN];
    __half xpA[NN * KA1];    // [x_fp16 | Agg(x)] fp16
    __half h_fp[NN * KH];    // relu(cheb1) fp16, [N,320]
    __half hW21f[NN * H2P];  // h @ W2_1 (fp16, gathered by agg2)
    __half hW20h[NN * H2P];  // h @ W2_0 (fp16)
    float agg2[NN * H2P];
    __half z_fp[NN * ZS];    // compact fp16 z
    __half W1c[KA1 * H1P];   // [128,320]
    __half W2c[KH * M2B];    // [320,256]
    __half L1[FP * H2P];     // [64,128]
    __half L2[FP * H2P];
    float b1p[H1P], b2p[H2P], l1bp[H2P], l2bp[H2P];
    float w30p[H2P], w31p[H2P];
    float s0[NN], s1[NN];
    float accum[2];
};
__device__ Scratch g_s;

// ---------------------------------------------------------------------------
// PTX helpers
// ---------------------------------------------------------------------------
__device__ __forceinline__ uint32_t smem_u32(const void* p) {
    return (uint32_t)__cvta_generic_to_shared(p);
}
__device__ __forceinline__ void ldm_x4(uint32_t* r, uint32_t addr) {
    asm volatile("ldmatrix.sync.aligned.m8n8.x4.shared.b16 {%0,%1,%2,%3}, [%4];"
                 : "=r"(r[0]), "=r"(r[1]), "=r"(r[2]), "=r"(r[3]) : "r"(addr));
}
__device__ __forceinline__ void ldm_x4_t(uint32_t* r, uint32_t addr) {
    asm volatile("ldmatrix.sync.aligned.m8n8.x4.trans.shared.b16 {%0,%1,%2,%3}, [%4];"
                 : "=r"(r[0]), "=r"(r[1]), "=r"(r[2]), "=r"(r[3]) : "r"(addr));
}
__device__ __forceinline__ void mma_fp16(float* c, const uint32_t* a, const uint32_t* b) {
    asm volatile("mma.sync.aligned.m16n8k16.row.col.f32.f16.f16.f32 "
                 "{%0,%1,%2,%3}, {%4,%5,%6,%7}, {%8,%9}, {%0,%1,%2,%3};"
                 : "+f"(c[0]), "+f"(c[1]), "+f"(c[2]), "+f"(c[3])
                 : "r"(a[0]), "r"(a[1]), "r"(a[2]), "r"(a[3]), "r"(b[0]), "r"(b[1]));
}
__device__ __forceinline__ void cp_async16(uint32_t dst, const void* src, bool pred) {
    int sz = pred ? 16 : 0;
    asm volatile("cp.async.cg.shared.global [%0], [%1], 16, %2;\n"
                 :: "r"(dst), "l"(src), "r"(sz));
}
__device__ __forceinline__ void cp_commit() {
    asm volatile("cp.async.commit_group;\n");
}
template <int N>
__device__ __forceinline__ void cp_wait() {
    asm volatile("cp.async.wait_group %0;\n" :: "n"(N));
}

// ---------------------------------------------------------------------------
// Fused setup (RACE-FREE): zero/pad-x in blocks [0,nbA); weight conversions in
// blocks [nbA,..). All writes independent; histogram runs in a LATER kernel.
// ---------------------------------------------------------------------------
#define CN1 (KA1 * H1P)
#define CN2 (KH * M2B)
#define CN3 (FP * H2P)
#define CTOT (CN1 + CN2 + 2 * CN3 + H1P + 5 * H2P)
__global__ void setup_kernel(const float* __restrict__ x,
                             const float* __restrict__ W10, const float* __restrict__ W11,
                             const float* __restrict__ W20, const float* __restrict__ W21,
                             const float* __restrict__ l1W, const float* __restrict__ l2W,
                             const float* __restrict__ b1, const float* __restrict__ b2,
                             const float* __restrict__ l1b, const float* __restrict__ l2b,
                             const float* __restrict__ W30, const float* __restrict__ W31,
                             int n, int nbA) {
    if (blockIdx.x < (unsigned)nbA) {
        int i = blockIdx.x * 256 + threadIdx.x;
        if (i < n) { g_s.deg[i] = 0; g_s.cnt[i] = 0; g_s.s0[i] = 0.f; g_s.s1[i] = 0.f; }
        if (i < 2) g_s.accum[i] = 0.f;
        if (i < n * FP) {
            int r = i >> 6, f = i & 63;
            float v = (f < F_IN) ? x[(long)r * F_IN + f] : 0.f;
            g_s.xpA[(long)r * KA1 + f] = __float2half(v);
        }
        return;
    }
    int i = (blockIdx.x - nbA) * 256 + threadIdx.x;
    if (i < CN1) {
        int k = i / H1P, m = i % H1P;
        float v = 0.f;
        if (m < H1) {
            if (k < F_IN) v = W10[k * H1 + m];
            else if (k >= FP && k < FP + F_IN) v = W11[(k - FP) * H1 + m];
        }
        g_s.W1c[i] = __float2half(v);
        return;
    }
    i -= CN1;
    if (i < CN2) {
        int k = i / M2B, m = i % M2B;
        float v = 0.f;
        if (k < H1) {
            if (m < H2P) { if (m < H2) v = W21[k * H2 + m]; }
            else { int mm = m - H2P; if (mm < H2) v = W20[k * H2 + mm]; }
        }
        g_s.W2c[i] = __float2half(v);
        return;
    }
    i -= CN2;
    if (i < CN3) {
        int k = i >> 7, m = i & 127;
        float v = (k < F_IN && m < H2) ? l1W[m * F_IN + k] : 0.f;
        g_s.L1[i] = __float2half(v);
        return;
    }
    i -= CN3;
    if (i < CN3) {
        int k = i >> 7, m = i & 127;
        float v = (k < F_IN && m < H2) ? l2W[m * F_IN + k] : 0.f;
        g_s.L2[i] = __float2half(v);
        return;
    }
    i -= CN3;
    if (i < H1P) { g_s.b1p[i] = (i < H1) ? b1[i] : 0.f; return; }
    i -= H1P;
    if (i < H2P) { g_s.b2p[i] = (i < H2) ? b2[i] : 0.f; return; }
    i -= H2P;
    if (i < H2P) { g_s.l1bp[i] = (i < H2) ? l1b[i] : 0.f; return; }
    i -= H2P;
    if (i < H2P) { g_s.l2bp[i] = (i < H2) ? l2b[i] : 0.f; return; }
    i -= H2P;
    if (i < H2P) { g_s.w30p[i] = (i < H2) ? W30[i] : 0.f; return; }
    i -= H2P;
    if (i < H2P) { g_s.w31p[i] = (i < H2) ? W31[i] : 0.f; return; }
}

// Histogram — MUST run strictly after setup_kernel (separate launch).
__global__ void hist_kernel(const int* __restrict__ src, const int* __restrict__ dst,
                            int* deg, int* cnt, int e) {
    int i = blockIdx.x * blockDim.x + threadIdx.x;
    if (i < e) {
        atomicAdd(&deg[src[i]], 1);
        atomicAdd(&cnt[dst[i]], 1);
    }
}

// scan stage 1 (+ dis folded in)
__global__ void scan1dis_kernel(const int* __restrict__ cnt, const int* __restrict__ deg,
                                int* __restrict__ rowptr, int* __restrict__ bsum,
                                float* __restrict__ dis, int n) {
    __shared__ int warp_sums[32];
    int tid = threadIdx.x;
    int i = blockIdx.x * 1024 + tid;
    if (i < n) {
        int d = deg[i];
        dis[i] = (d > 0) ? (1.0f / sqrtf((float)d)) : 0.0f;
    }
    int v = (i < n) ? cnt[i] : 0;
    int x = v;
    #pragma unroll
    for (int d = 1; d < 32; d <<= 1) {
        int y = __shfl_up_sync(0xFFFFFFFFu, x, d);
        if ((tid & 31) >= d) x += y;
    }
    if ((tid & 31) == 31) warp_sums[tid >> 5] = x;
    __syncthreads();
    if (tid < 32) {
        int y = warp_sums[tid];
        int zz = y;
        #pragma unroll
        for (int d = 1; d < 32; d <<= 1) {
            int w = __shfl_up_sync(0xFFFFFFFFu, zz, d);
            if (tid >= d) zz += w;
        }
        warp_sums[tid] = zz - y;
    }
    __syncthreads();
    int incl = x + warp_sums[tid >> 5];
    if (i < n) rowptr[i] = incl - v;
    if (tid == 1023) bsum[blockIdx.x] = incl;
}

// scan stages 2+3 merged: each block prefixes bsum locally.
__global__ void scan23_kernel(int* __restrict__ rowptr, int* __restrict__ cursor,
                              const int* __restrict__ bsum, int nb, int n) {
    __shared__ int s_off;
    int b = blockIdx.x;
    if (threadIdx.x == 0) {
        int run = 0;
        for (int j = 0; j < b; j++) run += bsum[j];
        s_off = run;
        if (b == nb - 1) rowptr[n] = run + bsum[b];
    }
    __syncthreads();
    int i = b * 1024 + threadIdx.x;
    if (i < n) {
        int v = rowptr[i] + s_off;
        rowptr[i] = v;
        cursor[i] = v;
    }
}

__global__ void fill_kernel(const int* __restrict__ src, const int* __restrict__ dst,
                            const float* __restrict__ dis, int* __restrict__ cursor,
                            int* __restrict__ csr_src, float* __restrict__ csr_norm, int e) {
    int i = blockIdx.x * blockDim.x + threadIdx.x;
    if (i < e) {
        int s = src[i], d = dst[i];
        int p = atomicAdd(&cursor[d], 1);
        csr_src[p] = s;
        csr_norm[p] = -(dis[s] * dis[d]);
    }
}

// ---------------------------------------------------------------------------
// Stage-1 aggregation over fp16 x rows (cols [0,58) of xpA), writing fp16
// into xpA cols [64,128). Lane l covers cols {2l, 2l+1}; lanes 29..31 pad 0.
// ---------------------------------------------------------------------------
__global__ void aggx_kernel(const int* __restrict__ csr_src,
                            const float* __restrict__ csr_norm, const int* __restrict__ rowptr,
                            __half* __restrict__ xpA, int n) {
    int node = (blockIdx.x * blockDim.x + threadIdx.x) >> 5;
    int lane = threadIdx.x & 31;
    if (node >= n) return;
    int beg = rowptr[node], end = rowptr[node + 1];
    float a0 = 0.f, a1 = 0.f;
    bool act = (lane < 29);
    for (int j = beg; j < end; j++) {
        int s = csr_src[j];
        float w = csr_norm[j];
        if (act) {
            __half2 v = *reinterpret_cast<const __half2*>(xpA + (long)s * KA1 + 2 * lane);
            float2 f = __half22float2(v);
            a0 += f.x * w;
            a1 += f.y * w;
        }
    }
    long o = (long)node * KA1 + FP + 2 * lane;
    *reinterpret_cast<__half2*>(xpA + o) =
        __floats2half2_rn(act ? a0 : 0.f, act ? a1 : 0.f);
}

// ---------------------------------------------------------------------------
// agg2 over fp16 rows [N,128], live cols [0,100): out fp32 [N,128].
// ---------------------------------------------------------------------------
__global__ void agg2h_kernel(const __half* __restrict__ val, const int* __restrict__ csr_src,
                             const float* __restrict__ csr_norm, const int* __restrict__ rowptr,
                             float* __restrict__ out, int n) {
    int node = (blockIdx.x * blockDim.x + threadIdx.x) >> 5;
    int lane = threadIdx.x & 31;
    if (node >= n) return;
    int beg = rowptr[node], end = rowptr[node + 1];
    float a0 = 0.f, a1 = 0.f, a2 = 0.f, a3 = 0.f;
    bool act2 = (lane < 18);
    for (int j = beg; j < end; j++) {
        int s = csr_src[j];
        float w = csr_norm[j];
        const __half2* vr = reinterpret_cast<const __half2*>(val + (long)s * H2P);
        float2 f0 = __half22float2(vr[lane]);
        a0 += f0.x * w; a1 += f0.y * w;
        if (act2) {
            float2 f1 = __half22float2(vr[32 + lane]);
            a2 += f1.x * w; a3 += f1.y * w;
        }
    }
    float* orow = out + (long)node * H2P;
    orow[2 * lane]      = a0;
    orow[2 * lane + 1]  = a1;
    orow[64 + 2 * lane] = act2 ? a2 : 0.f;
    orow[65 + 2 * lane] = act2 ? a3 : 0.f;
}

// ---------------------------------------------------------------------------
// Double-buffered (cp.async) fp16 tensor-core GEMM.
// BM=128, BN=64, BK=32, 8 warps 32x32 each, 2 smem stages.
// MODE 1: Cb = fp16(relu(acc + bias1)), stride M
// MODE 4: x1 = relu(addmh + addm2 + bias3)
//         xm = x1 + relu(acc1 + bias1); s0 += xm.w30, s1 += xm.w31 (atomic)
//         Cb = fp16(x1 + relu(acc2 + bias2)) at stride ZS, cols < ZS  [z]
// MODE 5: c<128 -> Cb[r*128+c] = fp16(acc); else Cb2[r*128+(c-128)] = fp16(acc)
// ---------------------------------------------------------------------------
template <int MODE, bool DUALOUT>
__global__ __launch_bounds__(256)
void hgemm_kernel(const __half* __restrict__ A, int lda, int K,
                  const __half* __restrict__ B1, const __half* __restrict__ B2,
                  const __half* __restrict__ addmh, const float* __restrict__ addm2,
                  const float* __restrict__ bias1, const float* __restrict__ bias2,
                  const float* __restrict__ bias3,
                  const float* __restrict__ w30, const float* __restrict__ w31,
                  float* __restrict__ S0, float* __restrict__ S1,
                  __half* __restrict__ Cb, __half* __restrict__ Cb2,
                  int Nr, int M) {
    __shared__ __align__(16) __half As[2][128][40];
    __shared__ __align__(16) __half Bs[2][32][72];
    __shared__ __align__(16) __half Bs2[DUALOUT ? 2 : 1][32][72];

    int tid = threadIdx.x;
    int bm = blockIdx.y * 128, bn = blockIdx.x * 64;
    int lane = tid & 31, wid = tid >> 5;
    int wm = (wid >> 1) * 32, wn = (wid & 1) * 32;

    int a_row = tid >> 1;
    int a_seg = (tid & 1) * 2;
    int b_row = tid >> 3, b_seg = tid & 7;

    float acc[2][4][4];
    float acc2[2][4][4];
    #pragma unroll
    for (int mf = 0; mf < 2; mf++)
        #pragma unroll
        for (int nf = 0; nf < 4; nf++)
            #pragma unroll
            for (int q = 0; q < 4; q++) { acc[mf][nf][q] = 0.f; acc2[mf][nf][q] = 0.f; }

    int nIter = K >> 5;

    auto load_stage = [&](int it, int stg) {
        int k0 = it << 5;
        bool ok = (bm + a_row) < Nr;
        long aoff = (long)(bm + a_row) * lda + k0 + a_seg * 8;
        cp_async16(smem_u32(&As[stg][a_row][a_seg * 8]), A + aoff, ok);
        cp_async16(smem_u32(&As[stg][a_row][(a_seg + 1) * 8]), A + aoff + 8, ok);
        long boff = (long)(k0 + b_row) * M + bn + b_seg * 8;
        cp_async16(smem_u32(&Bs[stg][b_row][b_seg * 8]), B1 + boff, true);
        if constexpr (DUALOUT)
            cp_async16(smem_u32(&Bs2[stg][b_row][b_seg * 8]), B2 + boff, true);
    };

    load_stage(0, 0);
    cp_commit();

    for (int it = 0; it < nIter; it++) {
        int stg = it & 1;
        if (it > 0) __syncthreads();
        if (it + 1 < nIter) {
            load_stage(it + 1, (it + 1) & 1);
            cp_commit();
            cp_wait<1>();
        } else {
            cp_wait<0>();
        }
        __syncthreads();

        #pragma unroll
        for (int s = 0; s < 32; s += 16) {
            uint32_t a[2][4];
            #pragma unroll
            for (int mf = 0; mf < 2; mf++) {
                int row = wm + mf * 16 + (lane & 15);
                int col = s + ((lane >> 4) << 3);
                ldm_x4(a[mf], smem_u32(&As[stg][row][col]));
            }
            int kr = s + (lane & 7) + (lane & 8);
            int nshift = (lane >> 4) << 3;
            uint32_t b[4][2];
            #pragma unroll
            for (int g = 0; g < 2; g++) {
                int nc = wn + g * 16 + nshift;
                uint32_t r[4];
                ldm_x4_t(r, smem_u32(&Bs[stg][kr][nc]));
                b[g * 2][0] = r[0]; b[g * 2][1] = r[1];
                b[g * 2 + 1][0] = r[2]; b[g * 2 + 1][1] = r[3];
            }
            #pragma unroll
            for (int mf = 0; mf < 2; mf++)
                #pragma unroll
                for (int nf = 0; nf < 4; nf++)
                    mma_fp16(acc[mf][nf], a[mf], b[nf]);
            if constexpr (DUALOUT) {
                uint32_t b2[4][2];
                #pragma unroll
                for (int g = 0; g < 2; g++) {
                    int nc = wn + g * 16 + nshift;
                    uint32_t r[4];
                    ldm_x4_t(r, smem_u32(&Bs2[stg][kr][nc]));
                    b2[g * 2][0] = r[0]; b2[g * 2][1] = r[1];
                    b2[g * 2 + 1][0] = r[2]; b2[g * 2 + 1][1] = r[3];
                }
                #pragma unroll
                for (int mf = 0; mf < 2; mf++)
                    #pragma unroll
                    for (int nf = 0; nf < 4; nf++)
                        mma_fp16(acc2[mf][nf], a[mf], b2[nf]);
            }
        }
    }

    // --- epilogue
    int gid = lane >> 2, tig = lane & 3;
    if constexpr (MODE == 4) {
        #pragma unroll
        for (int mf = 0; mf < 2; mf++) {
            #pragma unroll
            for (int half_i = 0; half_i < 2; half_i++) {
                int r = bm + wm + mf * 16 + gid + half_i * 8;
                bool valid = (r < Nr);
                float p0 = 0.f, p1 = 0.f;
                #pragma unroll
                for (int nf = 0; nf < 4; nf++) {
                    int c = bn + wn + nf * 8 + tig * 2;
                    if (valid) {
                        long base = (long)r * H2P + c;
                        float ah0 = __half2float(addmh[base]);
                        float ah1 = __half2float(addmh[base + 1]);
                        float x10 = fmaxf(ah0 + addm2[base]     + bias3[c],     0.f);
                        float x11 = fmaxf(ah1 + addm2[base + 1] + bias3[c + 1], 0.f);
                        float xm0 = x10 + fmaxf(acc[mf][nf][half_i * 2 + 0] + bias1[c],     0.f);
                        float xm1 = x11 + fmaxf(acc[mf][nf][half_i * 2 + 1] + bias1[c + 1], 0.f);
                        p0 += xm0 * w30[c] + xm1 * w30[c + 1];
                        p1 += xm0 * w31[c] + xm1 * w31[c + 1];
                        if (c < ZS) {
                            float z0 = x10 + fmaxf(acc2[mf][nf][half_i * 2 + 0] + bias2[c],     0.f);
                            float z1 = x11 + fmaxf(acc2[mf][nf][half_i * 2 + 1] + bias2[c + 1], 0.f);
                            Cb[(long)r * ZS + c]     = __float2half(z0);
                            Cb[(long)r * ZS + c + 1] = __float2half(z1);
                        }
                    }
                }
                p0 += __shfl_down_sync(0xFFFFFFFFu, p0, 1);
                p0 += __shfl_down_sync(0xFFFFFFFFu, p0, 2);
                p1 += __shfl_down_sync(0xFFFFFFFFu, p1, 1);
                p1 += __shfl_down_sync(0xFFFFFFFFu, p1, 2);
                if (tig == 0 && valid) {
                    atomicAdd(&S0[r], p0);
                    atomicAdd(&S1[r], p1);
                }
            }
        }
    } else {
        #pragma unroll
        for (int mf = 0; mf < 2; mf++) {
            #pragma unroll
            for (int nf = 0; nf < 4; nf++) {
                int c = bn + wn + nf * 8 + tig * 2;
                float bv0 = 0.f, bv1 = 0.f;
                if constexpr (MODE == 1) { bv0 = bias1[c]; bv1 = bias1[c + 1]; }
                #pragma unroll
                for (int half_i = 0; half_i < 2; half_i++) {
                    int r = bm + wm + mf * 16 + gid + half_i * 8;
                    if (r >= Nr) continue;
                    float v0 = acc[mf][nf][half_i * 2 + 0];
                    float v1 = acc[mf][nf][half_i * 2 + 1];
                    if constexpr (MODE == 5) {
                        if (c < H2P) {
                            long base = (long)r * H2P + c;
                            Cb[base]     = __float2half(v0);
                            Cb[base + 1] = __float2half(v1);
                        } else {
                            long base = (long)r * H2P + (c - H2P);
                            Cb2[base]     = __float2half(v0);
                            Cb2[base + 1] = __float2half(v1);
                        }
                    } else {
                        long base = (long)r * M + c;
                        v0 = fmaxf(v0 + bv0, 0.f);
                        v1 = fmaxf(v1 + bv1, 0.f);
                        Cb[base]     = __float2half(v0);
                        Cb[base + 1] = __float2half(v1);
                    }
                }
            }
        }
    }
}

// ---------------------------------------------------------------------------
// Merged score + agg1: blocks [0,SB) compute the edge losses over compact
// fp16 z; blocks [SB,..) compute out[i] = s0[i] + Agg(s1)[i] + b3 (overlapped).
// (No race: reads s0/s1/z/rowptr/csr written by PRIOR kernels.)
// ---------------------------------------------------------------------------
#define SB 2048
__global__ void score_agg1_kernel(const __half* __restrict__ zb, const int* __restrict__ ei,
                                  const int* __restrict__ nei, int E_, float* __restrict__ accum,
                                  const float* __restrict__ s0, const float* __restrict__ s1,
                                  const int* __restrict__ csr_src,
                                  const float* __restrict__ csr_norm,
                                  const int* __restrict__ rowptr, const float* __restrict__ b3,
                                  float* __restrict__ out, int n) {
    if (blockIdx.x >= SB) {
        int i = (blockIdx.x - SB) * 256 + threadIdx.x;
        if (i < n) {
            float a = 0.f;
            int end = rowptr[i + 1];
            for (int j = rowptr[i]; j < end; j++)
                a += s1[csr_src[j]] * csr_norm[j];
            out[i] = s0[i] + a + b3[0];
        }
        return;
    }
    int lane = threadIdx.x & 31;
    int grp = lane >> 4;
    int l = lane & 15;
    int warp_global = (blockIdx.x * blockDim.x + threadIdx.x) >> 5;
    int nwarps = (SB * 256) >> 5;
    int total = 2 * E_;
    float psum = 0.f, nsum = 0.f;
    for (int t0 = warp_global * 2; t0 < total; t0 += nwarps * 2) {
        int t = t0 + grp;
        float dot = 0.f;
        int which = 0;
        if (t < total) {
            which = (t >= E_);
            const int* p = which ? nei : ei;
            int e = which ? t - E_ : t;
            int a = p[e], b = p[e + E_];
            if (l < 13) {
                uint4 ua = reinterpret_cast<const uint4*>(zb + (long)a * ZS)[l];
                uint4 ub = reinterpret_cast<const uint4*>(zb + (long)b * ZS)[l];
                const __half2* ha = reinterpret_cast<const __half2*>(&ua);
                const __half2* hb = reinterpret_cast<const __half2*>(&ub);
                #pragma unroll
                for (int q = 0; q < 4; q++) {
                    float2 fa = __half22float2(ha[q]);
                    float2 fb = __half22float2(hb[q]);
                    dot += fa.x * fb.x + fa.y * fb.y;
                }
            }
        }
        #pragma unroll
        for (int dd = 8; dd; dd >>= 1) dot += __shfl_down_sync(0xFFFFFFFFu, dot, dd);
        if (l == 0 && t < total) {
            float sig = 1.f / (1.f + expf(-dot));
            if (which) nsum += logf(1.f - sig + 1e-15f);
            else       psum += logf(sig + 1e-15f);
        }
    }
    psum += __shfl_down_sync(0xFFFFFFFFu, psum, 16);
    nsum += __shfl_down_sync(0xFFFFFFFFu, nsum, 16);
    __shared__ float redp[32], redn[32];
    if (lane == 0) { redp[threadIdx.x >> 5] = psum; redn[threadIdx.x >> 5] = nsum; }
    __syncthreads();
    if (threadIdx.x < 32) {
        int nw = blockDim.x >> 5;
        float vp = (threadIdx.x < nw) ? redp[threadIdx.x] : 0.f;
        float vn = (threadIdx.x < nw) ? redn[threadIdx.x] : 0.f;
        #pragma unroll
        for (int dd = 16; dd; dd >>= 1) {
            vp += __shfl_down_sync(0xFFFFFFFFu, vp, dd);
            vn += __shfl_down_sync(0xFFFFFFFFu, vn, dd);
        }
        if (threadIdx.x == 0) {
            atomicAdd(&accum[0], vp);
            atomicAdd(&accum[1], vn);
        }
    }
}

// Tiny tail: out[n]=loss, out[n+1]=c1, out[n+2]=c2.
__global__ void final_kernel(const float* __restrict__ accum, const float* __restrict__ c1,
                             const float* __restrict__ c2, float* __restrict__ out,
                             int n, float invE) {
    if (threadIdx.x == 0) {
        out[n] = -(accum[0] + accum[1]) * invE;
        out[n + 1] = c1[0];
        out[n + 2] = c2[0];
    }
}

// ---------------------------------------------------------------------------
// Launch
// ---------------------------------------------------------------------------
extern "C" void kernel_launch(void* const* d_in, const int* in_sizes, int n_in,
                              void* d_out, int out_size) {
    const float* x      = (const float*)d_in[0];
    const int*   ei     = (const int*)d_in[1];
    const int*   nei    = (const int*)d_in[2];
    const float* W1_0   = (const float*)d_in[3];
    const float* W1_1   = (const float*)d_in[4];
    const float* b1     = (const float*)d_in[5];
    const float* W2_0   = (const float*)d_in[6];
    const float* W2_1   = (const float*)d_in[7];
    const float* b2     = (const float*)d_in[8];
    const float* W3_0   = (const float*)d_in[9];
    const float* W3_1   = (const float*)d_in[10];
    const float* b3     = (const float*)d_in[11];
    const float* lin1_W = (const float*)d_in[12];
    const float* lin1_b = (const float*)d_in[13];
    const float* lin2_W = (const float*)d_in[14];
    const float* lin2_b = (const float*)d_in[15];
    const float* c1     = (const float*)d_in[16];
    const float* c2     = (const float*)d_in[17];
    float* out = (float*)d_out;

    int n = in_sizes[0] / F_IN;   // 50000
    int e = in_sizes[1] / 2;      // 800000

    Scratch* sp = nullptr;
    cudaGetSymbolAddress((void**)&sp, g_s);

    const int* src = ei;
    const int* dst = ei + e;

    int nb_n = (n + 255) / 256;
    int nb_e = (e + 255) / 256;
    int agg_blocks = (n * 32 + 255) / 256;
    int nb_scan = (n + 1023) / 1024;
    int gy = (n + 127) / 128;
    int nbA = (n * FP + 255) / 256;
    int nbC = (CTOT + 255) / 256;

    // Setup (zero + pad-x + weight conversions) — no atomics, race-free
    setup_kernel<<<nbA + nbC, 256>>>(x, W1_0, W1_1, W2_0, W2_1,
                                     lin1_W, lin2_W, b1, b2, lin1_b, lin2_b,
                                     W3_0, W3_1, n, nbA);

    // Histogram (strictly after zeroing)
    hist_kernel<<<nb_e, 256>>>(src, dst, sp->deg, sp->cnt, e);

    // CSR build
    scan1dis_kernel<<<nb_scan, 1024>>>(sp->cnt, sp->deg, sp->rowptr, sp->bsum, sp->dis, n);
    scan23_kernel<<<nb_scan, 1024>>>(sp->rowptr, sp->cursor, sp->bsum, nb_scan, n);
    fill_kernel<<<nb_e, 256>>>(src, dst, sp->dis, sp->cursor, sp->csr_src, sp->csr_norm, e);

    // Stage 1 aggregation (fp16 source) -> xpA cols [64,128)
    aggx_kernel<<<agg_blocks, 256>>>(sp->csr_src, sp->csr_norm, sp->rowptr, sp->xpA, n);

    // G1 (MODE 1): h(fp16) = relu([xp|tx1] @ W1cat + b1)   K=128, M=320
    hgemm_kernel<1, false><<<dim3(H1P / 64, gy), 256>>>(
        sp->xpA, KA1, KA1, sp->W1c, nullptr, nullptr, nullptr,
        sp->b1p, nullptr, nullptr, nullptr, nullptr,
        nullptr, nullptr, sp->h_fp, nullptr, n, H1P);

    // G2 (MODE 5): hW21f(fp16) | hW20h(fp16) = h @ [W2_1 | W2_0]   K=320, M=256
    hgemm_kernel<5, false><<<dim3(M2B / 64, gy), 256>>>(
        sp->h_fp, KH, KH, sp->W2c, nullptr, nullptr, nullptr,
        nullptr, nullptr, nullptr, nullptr, nullptr,
        nullptr, nullptr, sp->hW21f, sp->hW20h, n, M2B);

    // agg2 = Agg(hW21f) over fp16 rows (live cols 0..99)
    agg2h_kernel<<<agg_blocks, 256>>>(sp->hW21f, sp->csr_src, sp->csr_norm,
                                      sp->rowptr, sp->agg2, n);

    // G4 (MODE 4): s0/s1 += (x1 + relu(xp@L1+b)) . W3_{0,1};
    //              z = fp16(x1 + relu(xp@L2+b)) compact;
    //              x1 = relu(hW20h + agg2 + b2) in epilogue
    hgemm_kernel<4, true><<<dim3(H2P / 64, gy), 256>>>(
        sp->xpA, KA1, FP, sp->L1, sp->L2, sp->hW20h, sp->agg2,
        sp->l1bp, sp->l2bp, sp->b2p, sp->w30p, sp->w31p,
        sp->s0, sp->s1, sp->z_fp, nullptr, n, H2P);

    // Losses + node outputs (overlapped in one grid)
    score_agg1_kernel<<<SB + nb_n, 256>>>(sp->z_fp, ei, nei, e, sp->accum,
                                          sp->s0, sp->s1, sp->csr_src, sp->csr_norm,
                                          sp->rowptr, b3, out, n);
    final_kernel<<<1, 32>>>(sp->accum, c1, c2, out, n, 1.0f / (float)e);
}

// round 13
// speedup vs baseline: 2.6170x; 1.1474x over previous
#include <cuda_runtime.h>
#include <cuda_fp16.h>
#include <cuda_fp8.h>
#include <cstdint>
#include <math.h>

#define NN 50000
#define EE 800000
#define F_IN 58
#define FP 64
#define H1 300
#define H2 100
#define H1P 320
#define H2P 128
#define KA1 128   // GEMM1 K: [xp|tx1]
#define KH 320    // padded K for fused stage-2 GEMM
#define M2B 256   // fused stage-2 GEMM logical N: [W2_1|W2_0]
#define ZSB 112   // z row stride in BYTES (fp8); cols 100..111 == 0

// ---------------------------------------------------------------------------
// Scratch (device-global, no runtime allocation).
// ---------------------------------------------------------------------------
struct alignas(16) Scratch {
    int   deg[NN];
    int   cnt[NN];
    int   rowptr[NN + 4];
    int   cursor[NN];
    int2  csr_sn[EE];        // packed (src, norm-bits) in CSR(dst) order
    int   bsum[64];
    float dis[NN];
    __half xpA[NN * KA1];    // [x_fp16 | Agg(x)] fp16
    __half h_fp[NN * KH];    // relu(cheb1) fp16, [N,320]
    __half hW21f[NN * H2P];  // h @ W2_1 (fp16, gathered by agg2)
    __half hW20h[NN * H2P];  // h @ W2_0 (fp16)
    float agg2[NN * H2P];
    uint8_t z8[NN * ZSB];    // compact fp8(e4m3) z
    __half W1c[KA1 * H1P];   // [128,320]
    __half W2c[KH * M2B];    // [320,256]
    __half L1[FP * H2P];     // [64,128]
    __half L2[FP * H2P];
    float b1p[H1P], b2p[H2P], l1bp[H2P], l2bp[H2P];
    float w30p[H2P], w31p[H2P];
    float s0[NN], s1[NN];
    float accum[2];
};
__device__ Scratch g_s;

// ---------------------------------------------------------------------------
// PTX helpers
// ---------------------------------------------------------------------------
__device__ __forceinline__ uint32_t smem_u32(const void* p) {
    return (uint32_t)__cvta_generic_to_shared(p);
}
__device__ __forceinline__ void ldm_x4(uint32_t* r, uint32_t addr) {
    asm volatile("ldmatrix.sync.aligned.m8n8.x4.shared.b16 {%0,%1,%2,%3}, [%4];"
                 : "=r"(r[0]), "=r"(r[1]), "=r"(r[2]), "=r"(r[3]) : "r"(addr));
}
__device__ __forceinline__ void ldm_x4_t(uint32_t* r, uint32_t addr) {
    asm volatile("ldmatrix.sync.aligned.m8n8.x4.trans.shared.b16 {%0,%1,%2,%3}, [%4];"
                 : "=r"(r[0]), "=r"(r[1]), "=r"(r[2]), "=r"(r[3]) : "r"(addr));
}
__device__ __forceinline__ void mma_fp16(float* c, const uint32_t* a, const uint32_t* b) {
    asm volatile("mma.sync.aligned.m16n8k16.row.col.f32.f16.f16.f32 "
                 "{%0,%1,%2,%3}, {%4,%5,%6,%7}, {%8,%9}, {%0,%1,%2,%3};"
                 : "+f"(c[0]), "+f"(c[1]), "+f"(c[2]), "+f"(c[3])
                 : "r"(a[0]), "r"(a[1]), "r"(a[2]), "r"(a[3]), "r"(b[0]), "r"(b[1]));
}
__device__ __forceinline__ void cp_async16(uint32_t dst, const void* src, bool pred) {
    int sz = pred ? 16 : 0;
    asm volatile("cp.async.cg.shared.global [%0], [%1], 16, %2;\n"
                 :: "r"(dst), "l"(src), "r"(sz));
}
__device__ __forceinline__ void cp_commit() {
    asm volatile("cp.async.commit_group;\n");
}
template <int N>
__device__ __forceinline__ void cp_wait() {
    asm volatile("cp.async.wait_group %0;\n" :: "n"(N));
}

// ---------------------------------------------------------------------------
// Fused setup (race-free): zero/pad-x in blocks [0,nbA); weight conversions
// in blocks [nbA,..). Histogram runs in a LATER kernel.
// ---------------------------------------------------------------------------
#define CN1 (KA1 * H1P)
#define CN2 (KH * M2B)
#define CN3 (FP * H2P)
#define CTOT (CN1 + CN2 + 2 * CN3 + H1P + 5 * H2P)
__global__ void setup_kernel(const float* __restrict__ x,
                             const float* __restrict__ W10, const float* __restrict__ W11,
                             const float* __restrict__ W20, const float* __restrict__ W21,
                             const float* __restrict__ l1W, const float* __restrict__ l2W,
                             const float* __restrict__ b1, const float* __restrict__ b2,
                             const float* __restrict__ l1b, const float* __restrict__ l2b,
                             const float* __restrict__ W30, const float* __restrict__ W31,
                             int n, int nbA) {
    if (blockIdx.x < (unsigned)nbA) {
        int i = blockIdx.x * 256 + threadIdx.x;
        if (i < n) { g_s.deg[i] = 0; g_s.cnt[i] = 0; g_s.s0[i] = 0.f; g_s.s1[i] = 0.f; }
        if (i < 2) g_s.accum[i] = 0.f;
        if (i < n * FP) {
            int r = i >> 6, f = i & 63;
            float v = (f < F_IN) ? x[(long)r * F_IN + f] : 0.f;
            g_s.xpA[(long)r * KA1 + f] = __float2half(v);
        }
        return;
    }
    int i = (blockIdx.x - nbA) * 256 + threadIdx.x;
    if (i < CN1) {
        int k = i / H1P, m = i % H1P;
        float v = 0.f;
        if (m < H1) {
            if (k < F_IN) v = W10[k * H1 + m];
            else if (k >= FP && k < FP + F_IN) v = W11[(k - FP) * H1 + m];
        }
        g_s.W1c[i] = __float2half(v);
        return;
    }
    i -= CN1;
    if (i < CN2) {
        int k = i / M2B, m = i % M2B;
        float v = 0.f;
        if (k < H1) {
            if (m < H2P) { if (m < H2) v = W21[k * H2 + m]; }
            else { int mm = m - H2P; if (mm < H2) v = W20[k * H2 + mm]; }
        }
        g_s.W2c[i] = __float2half(v);
        return;
    }
    i -= CN2;
    if (i < CN3) {
        int k = i >> 7, m = i & 127;
        float v = (k < F_IN && m < H2) ? l1W[m * F_IN + k] : 0.f;
        g_s.L1[i] = __float2half(v);
        return;
    }
    i -= CN3;
    if (i < CN3) {
        int k = i >> 7, m = i & 127;
        float v = (k < F_IN && m < H2) ? l2W[m * F_IN + k] : 0.f;
        g_s.L2[i] = __float2half(v);
        return;
    }
    i -= CN3;
    if (i < H1P) { g_s.b1p[i] = (i < H1) ? b1[i] : 0.f; return; }
    i -= H1P;
    if (i < H2P) { g_s.b2p[i] = (i < H2) ? b2[i] : 0.f; return; }
    i -= H2P;
    if (i < H2P) { g_s.l1bp[i] = (i < H2) ? l1b[i] : 0.f; return; }
    i -= H2P;
    if (i < H2P) { g_s.l2bp[i] = (i < H2) ? l2b[i] : 0.f; return; }
    i -= H2P;
    if (i < H2P) { g_s.w30p[i] = (i < H2) ? W30[i] : 0.f; return; }
    i -= H2P;
    if (i < H2P) { g_s.w31p[i] = (i < H2) ? W31[i] : 0.f; return; }
}

// Histogram — strictly after setup_kernel.
__global__ void hist_kernel(const int* __restrict__ src, const int* __restrict__ dst,
                            int* deg, int* cnt, int e) {
    int i = blockIdx.x * blockDim.x + threadIdx.x;
    if (i < e) {
        atomicAdd(&deg[src[i]], 1);
        atomicAdd(&cnt[dst[i]], 1);
    }
}

// scan stage 1 (+ dis folded in)
__global__ void scan1dis_kernel(const int* __restrict__ cnt, const int* __restrict__ deg,
                                int* __restrict__ rowptr, int* __restrict__ bsum,
                                float* __restrict__ dis, int n) {
    __shared__ int warp_sums[32];
    int tid = threadIdx.x;
    int i = blockIdx.x * 1024 + tid;
    if (i < n) {
        int d = deg[i];
        dis[i] = (d > 0) ? (1.0f / sqrtf((float)d)) : 0.0f;
    }
    int v = (i < n) ? cnt[i] : 0;
    int x = v;
    #pragma unroll
    for (int d = 1; d < 32; d <<= 1) {
        int y = __shfl_up_sync(0xFFFFFFFFu, x, d);
        if ((tid & 31) >= d) x += y;
    }
    if ((tid & 31) == 31) warp_sums[tid >> 5] = x;
    __syncthreads();
    if (tid < 32) {
        int y = warp_sums[tid];
        int zz = y;
        #pragma unroll
        for (int d = 1; d < 32; d <<= 1) {
            int w = __shfl_up_sync(0xFFFFFFFFu, zz, d);
            if (tid >= d) zz += w;
        }
        warp_sums[tid] = zz - y;
    }
    __syncthreads();
    int incl = x + warp_sums[tid >> 5];
    if (i < n) rowptr[i] = incl - v;
    if (tid == 1023) bsum[blockIdx.x] = incl;
}

// scan stages 2+3 merged.
__global__ void scan23_kernel(int* __restrict__ rowptr, int* __restrict__ cursor,
                              const int* __restrict__ bsum, int nb, int n) {
    __shared__ int s_off;
    int b = blockIdx.x;
    if (threadIdx.x == 0) {
        int run = 0;
        for (int j = 0; j < b; j++) run += bsum[j];
        s_off = run;
        if (b == nb - 1) rowptr[n] = run + bsum[b];
    }
    __syncthreads();
    int i = b * 1024 + threadIdx.x;
    if (i < n) {
        int v = rowptr[i] + s_off;
        rowptr[i] = v;
        cursor[i] = v;
    }
}

// fill: single packed int2 scattered store per edge.
__global__ void fill_kernel(const int* __restrict__ src, const int* __restrict__ dst,
                            const float* __restrict__ dis, int* __restrict__ cursor,
                            int2* __restrict__ csr_sn, int e) {
    int i = blockIdx.x * blockDim.x + threadIdx.x;
    if (i < e) {
        int s = src[i], d = dst[i];
        int p = atomicAdd(&cursor[d], 1);
        float w = -(dis[s] * dis[d]);
        csr_sn[p] = make_int2(s, __float_as_int(w));
    }
}

// ---------------------------------------------------------------------------
// Stage-1 aggregation over fp16 x rows (cols [0,58) of xpA) -> xpA cols [64,128).
// ---------------------------------------------------------------------------
__global__ void aggx_kernel(const int2* __restrict__ csr_sn, const int* __restrict__ rowptr,
                            __half* __restrict__ xpA, int n) {
    int node = (blockIdx.x * blockDim.x + threadIdx.x) >> 5;
    int lane = threadIdx.x & 31;
    if (node >= n) return;
    int beg = rowptr[node], end = rowptr[node + 1];
    float a0 = 0.f, a1 = 0.f;
    bool act = (lane < 29);
    for (int j = beg; j < end; j++) {
        int2 sn = csr_sn[j];
        float w = __int_as_float(sn.y);
        if (act) {
            __half2 v = *reinterpret_cast<const __half2*>(xpA + (long)sn.x * KA1 + 2 * lane);
            float2 f = __half22float2(v);
            a0 += f.x * w;
            a1 += f.y * w;
        }
    }
    long o = (long)node * KA1 + FP + 2 * lane;
    *reinterpret_cast<__half2*>(xpA + o) =
        __floats2half2_rn(act ? a0 : 0.f, act ? a1 : 0.f);
}

// ---------------------------------------------------------------------------
// agg2 over fp16 rows [N,128], live cols [0,100): out fp32 [N,128].
// ---------------------------------------------------------------------------
__global__ void agg2h_kernel(const __half* __restrict__ val, const int2* __restrict__ csr_sn,
                             const int* __restrict__ rowptr, float* __restrict__ out, int n) {
    int node = (blockIdx.x * blockDim.x + threadIdx.x) >> 5;
    int lane = threadIdx.x & 31;
    if (node >= n) return;
    int beg = rowptr[node], end = rowptr[node + 1];
    float a0 = 0.f, a1 = 0.f, a2 = 0.f, a3 = 0.f;
    bool act2 = (lane < 18);
    for (int j = beg; j < end; j++) {
        int2 sn = csr_sn[j];
        float w = __int_as_float(sn.y);
        const __half2* vr = reinterpret_cast<const __half2*>(val + (long)sn.x * H2P);
        float2 f0 = __half22float2(vr[lane]);
        a0 += f0.x * w; a1 += f0.y * w;
        if (act2) {
            float2 f1 = __half22float2(vr[32 + lane]);
            a2 += f1.x * w; a3 += f1.y * w;
        }
    }
    float* orow = out + (long)node * H2P;
    orow[2 * lane]      = a0;
    orow[2 * lane + 1]  = a1;
    orow[64 + 2 * lane] = act2 ? a2 : 0.f;
    orow[65 + 2 * lane] = act2 ? a3 : 0.f;
}

// ---------------------------------------------------------------------------
// Double-buffered (cp.async) fp16 tensor-core GEMM.
// MODE 1: Cb = fp16(relu(acc + bias1)), stride M
// MODE 4: x1 = relu(addmh + addm2 + bias3)
//         xm = x1 + relu(acc1 + bias1); s0 += xm.w30, s1 += xm.w31 (atomic)
//         Z8 = fp8(x1 + relu(acc2 + bias2)) at byte stride ZSB, cols < 100
// MODE 5: c<128 -> Cb[r*128+c] = fp16(acc); else Cb2[r*128+(c-128)] = fp16(acc)
// ---------------------------------------------------------------------------
template <int MODE, bool DUALOUT>
__global__ __launch_bounds__(256)
void hgemm_kernel(const __half* __restrict__ A, int lda, int K,
                  const __half* __restrict__ B1, const __half* __restrict__ B2,
                  const __half* __restrict__ addmh, const float* __restrict__ addm2,
                  const float* __restrict__ bias1, const float* __restrict__ bias2,
                  const float* __restrict__ bias3,
                  const float* __restrict__ w30, const float* __restrict__ w31,
                  float* __restrict__ S0, float* __restrict__ S1,
                  __half* __restrict__ Cb, __half* __restrict__ Cb2,
                  uint8_t* __restrict__ Z8,
                  int Nr, int M) {
    __shared__ __align__(16) __half As[2][128][40];
    __shared__ __align__(16) __half Bs[2][32][72];
    __shared__ __align__(16) __half Bs2[DUALOUT ? 2 : 1][32][72];

    int tid = threadIdx.x;
    int bm = blockIdx.y * 128, bn = blockIdx.x * 64;
    int lane = tid & 31, wid = tid >> 5;
    int wm = (wid >> 1) * 32, wn = (wid & 1) * 32;

    int a_row = tid >> 1;
    int a_seg = (tid & 1) * 2;
    int b_row = tid >> 3, b_seg = tid & 7;

    float acc[2][4][4];
    float acc2[2][4][4];
    #pragma unroll
    for (int mf = 0; mf < 2; mf++)
        #pragma unroll
        for (int nf = 0; nf < 4; nf++)
            #pragma unroll
            for (int q = 0; q < 4; q++) { acc[mf][nf][q] = 0.f; acc2[mf][nf][q] = 0.f; }

    int nIter = K >> 5;

    auto load_stage = [&](int it, int stg) {
        int k0 = it << 5;
        bool ok = (bm + a_row) < Nr;
        long aoff = (long)(bm + a_row) * lda + k0 + a_seg * 8;
        cp_async16(smem_u32(&As[stg][a_row][a_seg * 8]), A + aoff, ok);
        cp_async16(smem_u32(&As[stg][a_row][(a_seg + 1) * 8]), A + aoff + 8, ok);
        long boff = (long)(k0 + b_row) * M + bn + b_seg * 8;
        cp_async16(smem_u32(&Bs[stg][b_row][b_seg * 8]), B1 + boff, true);
        if constexpr (DUALOUT)
            cp_async16(smem_u32(&Bs2[stg][b_row][b_seg * 8]), B2 + boff, true);
    };

    load_stage(0, 0);
    cp_commit();

    for (int it = 0; it < nIter; it++) {
        int stg = it & 1;
        if (it > 0) __syncthreads();
        if (it + 1 < nIter) {
            load_stage(it + 1, (it + 1) & 1);
            cp_commit();
            cp_wait<1>();
        } else {
            cp_wait<0>();
        }
        __syncthreads();

        #pragma unroll
        for (int s = 0; s < 32; s += 16) {
            uint32_t a[2][4];
            #pragma unroll
            for (int mf = 0; mf < 2; mf++) {
                int row = wm + mf * 16 + (lane & 15);
                int col = s + ((lane >> 4) << 3);
                ldm_x4(a[mf], smem_u32(&As[stg][row][col]));
            }
            int kr = s + (lane & 7) + (lane & 8);
            int nshift = (lane >> 4) << 3;
            uint32_t b[4][2];
            #pragma unroll
            for (int g = 0; g < 2; g++) {
                int nc = wn + g * 16 + nshift;
                uint32_t r[4];
                ldm_x4_t(r, smem_u32(&Bs[stg][kr][nc]));
                b[g * 2][0] = r[0]; b[g * 2][1] = r[1];
                b[g * 2 + 1][0] = r[2]; b[g * 2 + 1][1] = r[3];
            }
            #pragma unroll
            for (int mf = 0; mf < 2; mf++)
                #pragma unroll
                for (int nf = 0; nf < 4; nf++)
                    mma_fp16(acc[mf][nf], a[mf], b[nf]);
            if constexpr (DUALOUT) {
                uint32_t b2[4][2];
                #pragma unroll
                for (int g = 0; g < 2; g++) {
                    int nc = wn + g * 16 + nshift;
                    uint32_t r[4];
                    ldm_x4_t(r, smem_u32(&Bs2[stg][kr][nc]));
                    b2[g * 2][0] = r[0]; b2[g * 2][1] = r[1];
                    b2[g * 2 + 1][0] = r[2]; b2[g * 2 + 1][1] = r[3];
                }
                #pragma unroll
                for (int mf = 0; mf < 2; mf++)
                    #pragma unroll
                    for (int nf = 0; nf < 4; nf++)
                        mma_fp16(acc2[mf][nf], a[mf], b2[nf]);
            }
        }
    }

    // --- epilogue
    int gid = lane >> 2, tig = lane & 3;
    if constexpr (MODE == 4) {
        #pragma unroll
        for (int mf = 0; mf < 2; mf++) {
            #pragma unroll
            for (int half_i = 0; half_i < 2; half_i++) {
                int r = bm + wm + mf * 16 + gid + half_i * 8;
                bool valid = (r < Nr);
                float p0 = 0.f, p1 = 0.f;
                #pragma unroll
                for (int nf = 0; nf < 4; nf++) {
                    int c = bn + wn + nf * 8 + tig * 2;
                    if (valid) {
                        long base = (long)r * H2P + c;
                        float ah0 = __half2float(addmh[base]);
                        float ah1 = __half2float(addmh[base + 1]);
                        float x10 = fmaxf(ah0 + addm2[base]     + bias3[c],     0.f);
                        float x11 = fmaxf(ah1 + addm2[base + 1] + bias3[c + 1], 0.f);
                        float xm0 = x10 + fmaxf(acc[mf][nf][half_i * 2 + 0] + bias1[c],     0.f);
                        float xm1 = x11 + fmaxf(acc[mf][nf][half_i * 2 + 1] + bias1[c + 1], 0.f);
                        p0 += xm0 * w30[c] + xm1 * w30[c + 1];
                        p1 += xm0 * w31[c] + xm1 * w31[c + 1];
                        if (c < ZSB) {  // cols [0,112): write fp8x2 (zeros past 99)
                            float z0 = 0.f, z1 = 0.f;
                            if (c < H2) {
                                z0 = x10 + fmaxf(acc2[mf][nf][half_i * 2 + 0] + bias2[c],     0.f);
                                z1 = x11 + fmaxf(acc2[mf][nf][half_i * 2 + 1] + bias2[c + 1], 0.f);
                            }
                            __nv_fp8x2_storage_t pk = __nv_cvt_float2_to_fp8x2(
                                make_float2(z0, z1), __NV_SATFINITE, __NV_E4M3);
                            *reinterpret_cast<unsigned short*>(Z8 + (long)r * ZSB + c) = pk;
                        }
                    }
                }
                p0 += __shfl_down_sync(0xFFFFFFFFu, p0, 1);
                p0 += __shfl_down_sync(0xFFFFFFFFu, p0, 2);
                p1 += __shfl_down_sync(0xFFFFFFFFu, p1, 1);
                p1 += __shfl_down_sync(0xFFFFFFFFu, p1, 2);
                if (tig == 0 && valid) {
                    atomicAdd(&S0[r], p0);
                    atomicAdd(&S1[r], p1);
                }
            }
        }
    } else {
        #pragma unroll
        for (int mf = 0; mf < 2; mf++) {
            #pragma unroll
            for (int nf = 0; nf < 4; nf++) {
                int c = bn + wn + nf * 8 + tig * 2;
                float bv0 = 0.f, bv1 = 0.f;
                if constexpr (MODE == 1) { bv0 = bias1[c]; bv1 = bias1[c + 1]; }
                #pragma unroll
                for (int half_i = 0; half_i < 2; half_i++) {
                    int r = bm + wm + mf * 16 + gid + half_i * 8;
                    if (r >= Nr) continue;
                    float v0 = acc[mf][nf][half_i * 2 + 0];
                    float v1 = acc[mf][nf][half_i * 2 + 1];
                    if constexpr (MODE == 5) {
                        if (c < H2P) {
                            long base = (long)r * H2P + c;
                            Cb[base]     = __float2half(v0);
                            Cb[base + 1] = __float2half(v1);
                        } else {
                            long base = (long)r * H2P + (c - H2P);
                            Cb2[base]     = __float2half(v0);
                            Cb2[base + 1] = __float2half(v1);
                        }
                    } else {
                        long base = (long)r * M + c;
                        v0 = fmaxf(v0 + bv0, 0.f);
                        v1 = fmaxf(v1 + bv1, 0.f);
                        Cb[base]     = __float2half(v0);
                        Cb[base + 1] = __float2half(v1);
                    }
                }
            }
        }
    }
}

// ---------------------------------------------------------------------------
// Merged score + agg1. Score over fp8 z: 8 lanes/edge, 4 edges/warp,
// one uint4 (16 fp8) per lane, lanes 0..6 live (112 bytes).
// Blocks [SB,..): out[i] = s0[i] + Agg(s1)[i] + b3.
// ---------------------------------------------------------------------------
#define SB 2048
__global__ void score_agg1_kernel(const uint8_t* __restrict__ z8, const int* __restrict__ ei,
                                  const int* __restrict__ nei, int E_, float* __restrict__ accum,
                                  const float* __restrict__ s0, const float* __restrict__ s1,
                                  const int2* __restrict__ csr_sn,
                                  const int* __restrict__ rowptr, const float* __restrict__ b3,
                                  float* __restrict__ out, int n) {
    if (blockIdx.x >= SB) {
        int i = (blockIdx.x - SB) * 256 + threadIdx.x;
        if (i < n) {
            float a = 0.f;
            int end = rowptr[i + 1];
            for (int j = rowptr[i]; j < end; j++) {
                int2 sn = csr_sn[j];
                a += s1[sn.x] * __int_as_float(sn.y);
            }
            out[i] = s0[i] + a + b3[0];
        }
        return;
    }
    int lane = threadIdx.x & 31;
    int grp = lane >> 3;           // 0..3: edge within quad
    int l = lane & 7;              // lane within edge group
    int warp_global = (blockIdx.x * blockDim.x + threadIdx.x) >> 5;
    int nwarps = (SB * 256) >> 5;
    int total = 2 * E_;
    float psum = 0.f, nsum = 0.f;
    for (int t0 = warp_global * 4; t0 < total; t0 += nwarps * 4) {
        int t = t0 + grp;
        float dot = 0.f;
        int which = 0;
        if (t < total) {
            which = (t >= E_);
            const int* p = which ? nei : ei;
            int e = which ? t - E_ : t;
            int a = p[e], b = p[e + E_];
            if (l < 7) {
                uint4 ua = *reinterpret_cast<const uint4*>(z8 + (long)a * ZSB + l * 16);
                uint4 ub = *reinterpret_cast<const uint4*>(z8 + (long)b * ZSB + l * 16);
                const __nv_fp8x2_storage_t* pa =
                    reinterpret_cast<const __nv_fp8x2_storage_t*>(&ua);
                const __nv_fp8x2_storage_t* pb =
                    reinterpret_cast<const __nv_fp8x2_storage_t*>(&ub);
                #pragma unroll
                for (int q = 0; q < 8; q++) {
                    __half2_raw ra = __nv_cvt_fp8x2_to_halfraw2(pa[q], __NV_E4M3);
                    __half2_raw rb = __nv_cvt_fp8x2_to_halfraw2(pb[q], __NV_E4M3);
                    float2 fa = __half22float2(*reinterpret_cast<__half2*>(&ra));
                    float2 fb = __half22float2(*reinterpret_cast<__half2*>(&rb));
                    dot += fa.x * fb.x + fa.y * fb.y;
                }
            }
        }
        dot += __shfl_down_sync(0xFFFFFFFFu, dot, 4);
        dot += __shfl_down_sync(0xFFFFFFFFu, dot, 2);
        dot += __shfl_down_sync(0xFFFFFFFFu, dot, 1);
        if (l == 0 && t < total) {
            float sig = 1.f / (1.f + expf(-dot));
            if (which) nsum += logf(1.f - sig + 1e-15f);
            else       psum += logf(sig + 1e-15f);
        }
    }
    // group leaders at lanes 0,8,16,24
    psum += __shfl_down_sync(0xFFFFFFFFu, psum, 16);
    psum += __shfl_down_sync(0xFFFFFFFFu, psum, 8);
    nsum += __shfl_down_sync(0xFFFFFFFFu, nsum, 16);
    nsum += __shfl_down_sync(0xFFFFFFFFu, nsum, 8);
    __shared__ float redp[32], redn[32];
    if (lane == 0) { redp[threadIdx.x >> 5] = psum; redn[threadIdx.x >> 5] = nsum; }
    __syncthreads();
    if (threadIdx.x < 32) {
        int nw = blockDim.x >> 5;
        float vp = (threadIdx.x < nw) ? redp[threadIdx.x] : 0.f;
        float vn = (threadIdx.x < nw) ? redn[threadIdx.x] : 0.f;
        #pragma unroll
        for (int dd = 16; dd; dd >>= 1) {
            vp += __shfl_down_sync(0xFFFFFFFFu, vp, dd);
            vn += __shfl_down_sync(0xFFFFFFFFu, vn, dd);
        }
        if (threadIdx.x == 0) {
            atomicAdd(&accum[0], vp);
            atomicAdd(&accum[1], vn);
        }
    }
}

// Tiny tail: out[n]=loss, out[n+1]=c1, out[n+2]=c2.
__global__ void final_kernel(const float* __restrict__ accum, const float* __restrict__ c1,
                             const float* __restrict__ c2, float* __restrict__ out,
                             int n, float invE) {
    if (threadIdx.x == 0) {
        out[n] = -(accum[0] + accum[1]) * invE;
        out[n + 1] = c1[0];
        out[n + 2] = c2[0];
    }
}

// ---------------------------------------------------------------------------
// Launch
// ---------------------------------------------------------------------------
extern "C" void kernel_launch(void* const* d_in, const int* in_sizes, int n_in,
                              void* d_out, int out_size) {
    const float* x      = (const float*)d_in[0];
    const int*   ei     = (const int*)d_in[1];
    const int*   nei    = (const int*)d_in[2];
    const float* W1_0   = (const float*)d_in[3];
    const float* W1_1   = (const float*)d_in[4];
    const float* b1     = (const float*)d_in[5];
    const float* W2_0   = (const float*)d_in[6];
    const float* W2_1   = (const float*)d_in[7];
    const float* b2     = (const float*)d_in[8];
    const float* W3_0   = (const float*)d_in[9];
    const float* W3_1   = (const float*)d_in[10];
    const float* b3     = (const float*)d_in[11];
    const float* lin1_W = (const float*)d_in[12];
    const float* lin1_b = (const float*)d_in[13];
    const float* lin2_W = (const float*)d_in[14];
    const float* lin2_b = (const float*)d_in[15];
    const float* c1     = (const float*)d_in[16];
    const float* c2     = (const float*)d_in[17];
    float* out = (float*)d_out;

    int n = in_sizes[0] / F_IN;   // 50000
    int e = in_sizes[1] / 2;      // 800000

    Scratch* sp = nullptr;
    cudaGetSymbolAddress((void**)&sp, g_s);

    const int* src = ei;
    const int* dst = ei + e;

    int nb_n = (n + 255) / 256;
    int nb_e = (e + 255) / 256;
    int agg_blocks = (n * 32 + 255) / 256;
    int nb_scan = (n + 1023) / 1024;
    int gy = (n + 127) / 128;
    int nbA = (n * FP + 255) / 256;
    int nbC = (CTOT + 255) / 256;

    // Setup (zero + pad-x + weight conversions)
    setup_kernel<<<nbA + nbC, 256>>>(x, W1_0, W1_1, W2_0, W2_1,
                                     lin1_W, lin2_W, b1, b2, lin1_b, lin2_b,
                                     W3_0, W3_1, n, nbA);

    // Histogram (strictly after zeroing)
    hist_kernel<<<nb_e, 256>>>(src, dst, sp->deg, sp->cnt, e);

    // CSR build
    scan1dis_kernel<<<nb_scan, 1024>>>(sp->cnt, sp->deg, sp->rowptr, sp->bsum, sp->dis, n);
    scan23_kernel<<<nb_scan, 1024>>>(sp->rowptr, sp->cursor, sp->bsum, nb_scan, n);
    fill_kernel<<<nb_e, 256>>>(src, dst, sp->dis, sp->cursor, sp->csr_sn, e);

    // Stage 1 aggregation (fp16 source) -> xpA cols [64,128)
    aggx_kernel<<<agg_blocks, 256>>>(sp->csr_sn, sp->rowptr, sp->xpA, n);

    // G1 (MODE 1): h(fp16) = relu([xp|tx1] @ W1cat + b1)   K=128, M=320
    hgemm_kernel<1, false><<<dim3(H1P / 64, gy), 256>>>(
        sp->xpA, KA1, KA1, sp->W1c, nullptr, nullptr, nullptr,
        sp->b1p, nullptr, nullptr, nullptr, nullptr,
        nullptr, nullptr, sp->h_fp, nullptr, nullptr, n, H1P);

    // G2 (MODE 5): hW21f(fp16) | hW20h(fp16) = h @ [W2_1 | W2_0]   K=320, M=256
    hgemm_kernel<5, false><<<dim3(M2B / 64, gy), 256>>>(
        sp->h_fp, KH, KH, sp->W2c, nullptr, nullptr, nullptr,
        nullptr, nullptr, nullptr, nullptr, nullptr,
        nullptr, nullptr, sp->hW21f, sp->hW20h, nullptr, n, M2B);

    // agg2 = Agg(hW21f) over fp16 rows (live cols 0..99)
    agg2h_kernel<<<agg_blocks, 256>>>(sp->hW21f, sp->csr_sn, sp->rowptr, sp->agg2, n);

    // G4 (MODE 4): s0/s1 += xm . W3_{0,1}; z8 = fp8(z) compact;
    //              x1 = relu(hW20h + agg2 + b2) in epilogue
    hgemm_kernel<4, true><<<dim3(H2P / 64, gy), 256>>>(
        sp->xpA, KA1, FP, sp->L1, sp->L2, sp->hW20h, sp->agg2,
        sp->l1bp, sp->l2bp, sp->b2p, sp->w30p, sp->w31p,
        sp->s0, sp->s1, nullptr, nullptr, sp->z8, n, H2P);

    // Losses + node outputs (overlapped in one grid)
    score_agg1_kernel<<<SB + nb_n, 256>>>(sp->z8, ei, nei, e, sp->accum,
                                          sp->s0, sp->s1, sp->csr_sn,
                                          sp->rowptr, b3, out, n);
    final_kernel<<<1, 32>>>(sp->accum, c1, c2, out, n, 1.0f / (float)e);
}